// round 1
// baseline (speedup 1.0000x reference)
#include <cuda_runtime.h>
#include <cuda_bf16.h>
#include <math_constants.h>

// Problem constants
#define BATCH 2
#define SEQ   2048
#define EMB   1024
#define E3    3072
#define NH    16
#define HD    64
#define MTOT  (BATCH*SEQ)   // 4096

// Scratch (static device globals — no cudaMalloc allowed)
__device__ float g_qkv[(size_t)MTOT * E3];    // [4096, 3072]
__device__ float g_attn[(size_t)MTOT * EMB];  // [4096, 1024]

// ---------------------------------------------------------------------------
// SGEMM with bias: C[M,N] = A[M,K] @ B[K,N] + bias[N]
// 128x128 block tile, BK=16, 8x8 per-thread tile, 256 threads.
// ---------------------------------------------------------------------------
__global__ void __launch_bounds__(256) sgemm_bias(
    int M, int N, int K,
    const float* __restrict__ A,
    const float* __restrict__ B,
    const float* __restrict__ bias,
    float* __restrict__ C)
{
    constexpr int BM = 128, BN = 128, BK = 16;
    __shared__ __align__(16) float As[BK * BM];  // As[k][m] (transposed)
    __shared__ __align__(16) float Bs[BK * BN];  // Bs[k][n]

    const int tid  = threadIdx.x;
    const int tRow = (tid >> 4) << 3;   // 0..120 step 8
    const int tCol = (tid & 15) << 3;   // 0..120 step 8

    const int aRow = tid >> 2;          // 0..63
    const int aCol = (tid & 3) << 2;    // 0,4,8,12
    const int bRow = tid >> 5;          // 0..7
    const int bCol = (tid & 31) << 2;   // 0..124 step 4

    const float* Ab = A + (size_t)blockIdx.y * BM * K;
    const float* Bb = B + (size_t)blockIdx.x * BN;
    float* Cb = C + (size_t)blockIdx.y * BM * N + (size_t)blockIdx.x * BN;

    float acc[8][8] = {};

    for (int k0 = 0; k0 < K; k0 += BK) {
        // Load A tile (transpose into As[k][m])
        #pragma unroll
        for (int p = 0; p < 2; p++) {
            const float4 a = *(const float4*)(Ab + (size_t)(aRow + p * 64) * K + k0 + aCol);
            As[(aCol + 0) * BM + aRow + p * 64] = a.x;
            As[(aCol + 1) * BM + aRow + p * 64] = a.y;
            As[(aCol + 2) * BM + aRow + p * 64] = a.z;
            As[(aCol + 3) * BM + aRow + p * 64] = a.w;
        }
        // Load B tile (natural)
        #pragma unroll
        for (int p = 0; p < 2; p++) {
            *(float4*)&Bs[(bRow + p * 8) * BN + bCol] =
                *(const float4*)(Bb + (size_t)(k0 + bRow + p * 8) * N + bCol);
        }
        __syncthreads();

        #pragma unroll
        for (int k = 0; k < BK; k++) {
            float rm[8], rn[8];
            *(float4*)&rm[0] = *(const float4*)&As[k * BM + tRow];
            *(float4*)&rm[4] = *(const float4*)&As[k * BM + tRow + 4];
            *(float4*)&rn[0] = *(const float4*)&Bs[k * BN + tCol];
            *(float4*)&rn[4] = *(const float4*)&Bs[k * BN + tCol + 4];
            #pragma unroll
            for (int i = 0; i < 8; i++)
                #pragma unroll
                for (int j = 0; j < 8; j++)
                    acc[i][j] = fmaf(rm[i], rn[j], acc[i][j]);
        }
        __syncthreads();
    }

    float bb[8];
    *(float4*)&bb[0] = *(const float4*)(bias + (size_t)blockIdx.x * BN + tCol);
    *(float4*)&bb[4] = *(const float4*)(bias + (size_t)blockIdx.x * BN + tCol + 4);

    #pragma unroll
    for (int i = 0; i < 8; i++) {
        float4 o0 = make_float4(acc[i][0] + bb[0], acc[i][1] + bb[1],
                                acc[i][2] + bb[2], acc[i][3] + bb[3]);
        float4 o1 = make_float4(acc[i][4] + bb[4], acc[i][5] + bb[5],
                                acc[i][6] + bb[6], acc[i][7] + bb[7]);
        *(float4*)(Cb + (size_t)(tRow + i) * N + tCol)     = o0;
        *(float4*)(Cb + (size_t)(tRow + i) * N + tCol + 4) = o1;
    }
}

// ---------------------------------------------------------------------------
// Flash attention, fp32. Grid: (SEQ/64, NH, BATCH), 256 threads.
// 64 queries x 64 keys per tile, D=64. Thread (tr,tc) owns 4x4 tiles.
// SMEM: sQ = Q^T [d][r] swizzled, sK = K^T [d][c] swizzled (reused as P^T-ish
// [c][r] swizzled after scores), sV = V [c][d] natural. 48KB total.
// ---------------------------------------------------------------------------
__global__ void __launch_bounds__(256) flash_kernel()
{
    const int qt = blockIdx.x;   // query tile 0..31
    const int h  = blockIdx.y;   // head
    const int b  = blockIdx.z;   // batch

    __shared__ __align__(16) float sQ[64 * 64];
    __shared__ __align__(16) float sK[64 * 64];   // Kts, then P
    __shared__ __align__(16) float sV[64 * 64];

    const int tid = threadIdx.x;
    const int tr  = tid >> 4;    // 0..15 : row group (4 rows)
    const int tc  = tid & 15;    // 0..15 : col group (4 cols)

    const float* qbase = g_qkv + (size_t)(b * SEQ + qt * 64) * E3 + h * HD;
    const float* kbase = g_qkv + (size_t)(b * SEQ) * E3 + EMB     + h * HD;
    const float* vbase = g_qkv + (size_t)(b * SEQ) * E3 + 2 * EMB + h * HD;

    // ---- load Q transposed + swizzled, pre-scaled by 1/sqrt(D) ----
    {
        const int d4 = tid & 15;      // float4 group along d
        const int r0 = tid >> 4;      // 0..15
        #pragma unroll
        for (int p = 0; p < 4; p++) {
            const int r = r0 + p * 16;
            float4 v = *(const float4*)(qbase + (size_t)r * E3 + d4 * 4);
            v.x *= 0.125f; v.y *= 0.125f; v.z *= 0.125f; v.w *= 0.125f;
            const int gs = (r >> 2) ^ d4;
            const int rm = r & 3;
            sQ[(4 * d4 + 0) * 64 + gs * 4 + rm] = v.x;
            sQ[(4 * d4 + 1) * 64 + gs * 4 + rm] = v.y;
            sQ[(4 * d4 + 2) * 64 + gs * 4 + rm] = v.z;
            sQ[(4 * d4 + 3) * 64 + gs * 4 + rm] = v.w;
        }
    }

    float m_i[4], l_i[4], acc[4][4];
    #pragma unroll
    for (int i = 0; i < 4; i++) {
        m_i[i] = -CUDART_INF_F;
        l_i[i] = 0.0f;
        #pragma unroll
        for (int j = 0; j < 4; j++) acc[i][j] = 0.0f;
    }

    for (int kt = 0; kt < SEQ / 64; kt++) {
        __syncthreads();   // prior PV done with sK(P) and sV

        // ---- load K (transposed+swizzled) and V (natural) tiles ----
        {
            const int d4 = tid & 15;
            const int r0 = tid >> 4;
            #pragma unroll
            for (int p = 0; p < 4; p++) {
                const int c = r0 + p * 16;
                const size_t roff = (size_t)(kt * 64 + c) * E3 + d4 * 4;
                float4 kv = *(const float4*)(kbase + roff);
                const int gs = (c >> 2) ^ d4;
                const int cm = c & 3;
                sK[(4 * d4 + 0) * 64 + gs * 4 + cm] = kv.x;
                sK[(4 * d4 + 1) * 64 + gs * 4 + cm] = kv.y;
                sK[(4 * d4 + 2) * 64 + gs * 4 + cm] = kv.z;
                sK[(4 * d4 + 3) * 64 + gs * 4 + cm] = kv.w;
                float4 vv = *(const float4*)(vbase + roff);
                *(float4*)&sV[c * 64 + d4 * 4] = vv;
            }
        }
        __syncthreads();

        // ---- scores: s[i][j] = sum_k Q[tr*4+i][k] * K[tc*4+j][k] ----
        float s[4][4] = {};
        #pragma unroll 8
        for (int k = 0; k < 64; k++) {
            const int f = k >> 2;
            float q[4], kk[4];
            *(float4*)q  = *(const float4*)&sQ[k * 64 + ((tr ^ f) << 2)];
            *(float4*)kk = *(const float4*)&sK[k * 64 + ((tc ^ f) << 2)];
            #pragma unroll
            for (int i = 0; i < 4; i++)
                #pragma unroll
                for (int j = 0; j < 4; j++)
                    s[i][j] = fmaf(q[i], kk[j], s[i][j]);
        }

        // ---- online softmax (row stats across the 16 tc lanes) ----
        #pragma unroll
        for (int i = 0; i < 4; i++) {
            float tm = fmaxf(fmaxf(s[i][0], s[i][1]), fmaxf(s[i][2], s[i][3]));
            tm = fmaxf(tm, __shfl_xor_sync(0xffffffffu, tm, 1));
            tm = fmaxf(tm, __shfl_xor_sync(0xffffffffu, tm, 2));
            tm = fmaxf(tm, __shfl_xor_sync(0xffffffffu, tm, 4));
            tm = fmaxf(tm, __shfl_xor_sync(0xffffffffu, tm, 8));
            const float mnew  = fmaxf(m_i[i], tm);
            const float alpha = __expf(m_i[i] - mnew);
            float ps = 0.0f;
            #pragma unroll
            for (int j = 0; j < 4; j++) {
                s[i][j] = __expf(s[i][j] - mnew);
                ps += s[i][j];
            }
            ps += __shfl_xor_sync(0xffffffffu, ps, 1);
            ps += __shfl_xor_sync(0xffffffffu, ps, 2);
            ps += __shfl_xor_sync(0xffffffffu, ps, 4);
            ps += __shfl_xor_sync(0xffffffffu, ps, 8);
            l_i[i] = l_i[i] * alpha + ps;
            m_i[i] = mnew;
            #pragma unroll
            for (int j = 0; j < 4; j++) acc[i][j] *= alpha;
        }

        __syncthreads();   // all warps done reading sK as K^T

        // ---- write P into sK: layout P[c][r] swizzled by granule ----
        #pragma unroll
        for (int j = 0; j < 4; j++) {
            const int c  = tc * 4 + j;
            const int gs = tr ^ tc;   // tr ^ (c>>2)
            *(float4*)&sK[c * 64 + gs * 4] =
                make_float4(s[0][j], s[1][j], s[2][j], s[3][j]);
        }
        __syncthreads();

        // ---- PV: acc[i][j] += sum_c P[r][c] * V[c][d] ----
        #pragma unroll 8
        for (int c = 0; c < 64; c++) {
            float p[4], v[4];
            *(float4*)p = *(const float4*)&sK[c * 64 + ((tr ^ (c >> 2)) << 2)];
            *(float4*)v = *(const float4*)&sV[c * 64 + (tc << 2)];
            #pragma unroll
            for (int i = 0; i < 4; i++)
                #pragma unroll
                for (int j = 0; j < 4; j++)
                    acc[i][j] = fmaf(p[i], v[j], acc[i][j]);
        }
    }

    // ---- epilogue: normalize and write [B,S,E] ----
    #pragma unroll
    for (int i = 0; i < 4; i++) {
        const float rl = 1.0f / l_i[i];
        const int r = qt * 64 + tr * 4 + i;
        float4 o = make_float4(acc[i][0] * rl, acc[i][1] * rl,
                               acc[i][2] * rl, acc[i][3] * rl);
        *(float4*)(g_attn + (size_t)(b * SEQ + r) * EMB + h * HD + tc * 4) = o;
    }
}

// ---------------------------------------------------------------------------
extern "C" void kernel_launch(void* const* d_in, const int* in_sizes, int n_in,
                              void* d_out, int out_size)
{
    (void)in_sizes; (void)n_in; (void)out_size;
    const float* x     = (const float*)d_in[0];
    const float* w_in  = (const float*)d_in[1];
    const float* b_in  = (const float*)d_in[2];
    const float* w_out = (const float*)d_in[3];
    const float* b_out = (const float*)d_in[4];
    float* out = (float*)d_out;

    void* qkv_ptr  = nullptr;
    void* attn_ptr = nullptr;
    cudaGetSymbolAddress(&qkv_ptr,  g_qkv);
    cudaGetSymbolAddress(&attn_ptr, g_attn);

    // 1) QKV projection: [4096,1024] @ [1024,3072] + b_in
    sgemm_bias<<<dim3(E3 / 128, MTOT / 128), 256>>>(
        MTOT, E3, EMB, x, w_in, b_in, (float*)qkv_ptr);

    // 2) Attention per (b, h, q-tile)
    flash_kernel<<<dim3(SEQ / 64, NH, BATCH), 256>>>();

    // 3) Output projection: [4096,1024] @ [1024,1024] + b_out
    sgemm_bias<<<dim3(EMB / 128, MTOT / 128), 256>>>(
        MTOT, EMB, EMB, (float*)attn_ptr, w_out, b_out, out);
}

// round 3
// speedup vs baseline: 1.2919x; 1.2919x over previous
#include <cuda_runtime.h>
#include <cuda_bf16.h>
#include <math_constants.h>
#include <cstdint>

// Problem constants
#define BATCH 2
#define SEQ   2048
#define EMB   1024
#define E3    3072
#define NH    16
#define HD    64
#define MTOT  (BATCH*SEQ)   // 4096

// Scratch (static device globals — no cudaMalloc allowed)
__device__ float g_qkv [(size_t)MTOT * E3];   // [4096, 3072]
__device__ float g_attn[(size_t)MTOT * EMB];  // [4096, 1024]
__device__ float g_wti [(size_t)E3 * EMB];    // w_in^T  [3072, 1024]
__device__ float g_wto [(size_t)EMB * EMB];   // w_out^T [1024, 1024]

// ---------------------------------------------------------------------------
__device__ __forceinline__ float cvt_tf32(float x) {
    uint32_t u;
    asm("cvt.rna.tf32.f32 %0, %1;" : "=r"(u) : "f"(x));
    return __uint_as_float(u);
}

__device__ __forceinline__ void mma_tf32(float c[4], uint32_t a0, uint32_t a1,
                                         uint32_t a2, uint32_t a3,
                                         uint32_t b0, uint32_t b1) {
    asm volatile(
        "mma.sync.aligned.m16n8k8.row.col.f32.tf32.tf32.f32 "
        "{%0,%1,%2,%3}, {%4,%5,%6,%7}, {%8,%9}, {%0,%1,%2,%3};"
        : "+f"(c[0]), "+f"(c[1]), "+f"(c[2]), "+f"(c[3])
        : "r"(a0), "r"(a1), "r"(a2), "r"(a3), "r"(b0), "r"(b1));
}

// ---------------------------------------------------------------------------
// Transpose: out[C,R] = in[R,C]^T  (R, C multiples of 32). block (32,8).
// ---------------------------------------------------------------------------
__global__ void __launch_bounds__(256) transpose_k(
    const float* __restrict__ in, float* __restrict__ out, int R, int C)
{
    __shared__ float t[32][33];
    const int bx = blockIdx.x * 32;
    const int by = blockIdx.y * 32;
    const int x = bx + threadIdx.x;
    #pragma unroll
    for (int j = 0; j < 4; j++) {
        const int y = by + threadIdx.y + j * 8;
        t[threadIdx.y + j * 8][threadIdx.x] = in[(size_t)y * C + x];
    }
    __syncthreads();
    const int x2 = by + threadIdx.x;
    #pragma unroll
    for (int j = 0; j < 4; j++) {
        const int y2 = bx + threadIdx.y + j * 8;
        out[(size_t)y2 * R + x2] = t[threadIdx.x][threadIdx.y + j * 8];
    }
}

// ---------------------------------------------------------------------------
// tf32 mma.sync GEMM + bias: C[M,N] = A[M,K] @ Bt[N,K]^T + bias[N]
// CTA 128x128, 4 warps (2x2), warp tile 64x64, BK=16, double-buffered SMEM.
//
// SMEM layout per 128-row tile, row stride 24 floats:
//   pos(row, k) = row*24 + ((row>>2)&1)*4 + (k>>3)*8 + slot(k&7)
//   slot(k) = (k%4)*2 + (k>=4)   -> order [k0,k4,k1,k5,k2,k6,k3,k7]
// This makes mma fragment pairs (a0,a2),(a1,a3),(b0,b1) contiguous LDS.64,
// conflict-free in both 16-lane phases; STS.128 of staged rows is also
// conflict-free (verified per-phase bank maps).
// ---------------------------------------------------------------------------
__global__ void __launch_bounds__(128) gemm_tf32mma(
    int N, int K,
    const float* __restrict__ A,
    const float* __restrict__ Bt,
    const float* __restrict__ bias,
    float* __restrict__ C)
{
    __shared__ __align__(16) float sA[2][128 * 24];
    __shared__ __align__(16) float sB[2][128 * 24];

    const int tid  = threadIdx.x;
    const int wid  = tid >> 5;
    const int lane = tid & 31;
    const int wm   = wid >> 1;       // 0..1 : m half (64 rows)
    const int wn   = wid & 1;        // 0..1 : n half (64 cols)
    const int qr   = lane >> 2;      // 0..7
    const int qc   = lane & 3;       // 0..3

    const float* Arow = A  + (size_t)(blockIdx.y * 128 + tid) * K;
    const float* Brow = Bt + (size_t)(blockIdx.x * 128 + tid) * K;

    // staging row base in smem (each thread owns row `tid`)
    const int stBase = tid * 24 + ((tid >> 2) & 1) * 4;
    // fragment lane base (row qr within a 16-row fragment block)
    const int ldBase = qr * 24 + ((qr >> 2) & 1) * 4 + qc * 2;

    float acc[4][8][4];
    #pragma unroll
    for (int i = 0; i < 4; i++)
        #pragma unroll
        for (int j = 0; j < 8; j++)
            #pragma unroll
            for (int c = 0; c < 4; c++) acc[i][j][c] = 0.0f;

    const int KT = K / 16;
    float4 ra[4], rb[4];

    // prefetch tile 0
    #pragma unroll
    for (int q = 0; q < 4; q++) {
        ra[q] = *(const float4*)(Arow + q * 4);
        rb[q] = *(const float4*)(Brow + q * 4);
    }
    // stage tile 0 into buffer 0
    #pragma unroll
    for (int g = 0; g < 2; g++) {
        const float4 a0 = ra[g * 2], a1 = ra[g * 2 + 1];
        const float4 b0 = rb[g * 2], b1 = rb[g * 2 + 1];
        float* dA = &sA[0][stBase + g * 8];
        float* dB = &sB[0][stBase + g * 8];
        *(float4*)(dA)     = make_float4(cvt_tf32(a0.x), cvt_tf32(a1.x), cvt_tf32(a0.y), cvt_tf32(a1.y));
        *(float4*)(dA + 4) = make_float4(cvt_tf32(a0.z), cvt_tf32(a1.z), cvt_tf32(a0.w), cvt_tf32(a1.w));
        *(float4*)(dB)     = make_float4(cvt_tf32(b0.x), cvt_tf32(b1.x), cvt_tf32(b0.y), cvt_tf32(b1.y));
        *(float4*)(dB + 4) = make_float4(cvt_tf32(b0.z), cvt_tf32(b1.z), cvt_tf32(b0.w), cvt_tf32(b1.w));
    }
    __syncthreads();

    for (int t = 0; t < KT; t++) {
        const int buf = t & 1;
        if (t + 1 < KT) {
            const int k0 = (t + 1) * 16;
            #pragma unroll
            for (int q = 0; q < 4; q++) {
                ra[q] = *(const float4*)(Arow + k0 + q * 4);
                rb[q] = *(const float4*)(Brow + k0 + q * 4);
            }
        }

        // compute on current buffer: 2 k-steps of 8
        #pragma unroll
        for (int g = 0; g < 2; g++) {
            const float* pA = &sA[buf][wm * 1536 + g * 8 + ldBase];
            const float* pB = &sB[buf][wn * 1536 + g * 8 + ldBase];

            uint32_t afr[4][4];
            #pragma unroll
            for (int mi = 0; mi < 4; mi++) {
                const float2 lo = *(const float2*)(pA + mi * 384);        // rows +0
                const float2 hi = *(const float2*)(pA + mi * 384 + 192);  // rows +8
                afr[mi][0] = __float_as_uint(lo.x);   // a0
                afr[mi][2] = __float_as_uint(lo.y);   // a2
                afr[mi][1] = __float_as_uint(hi.x);   // a1
                afr[mi][3] = __float_as_uint(hi.y);   // a3
            }
            uint32_t bfr[8][2];
            #pragma unroll
            for (int nj = 0; nj < 8; nj++) {
                const float2 bb = *(const float2*)(pB + nj * 192);
                bfr[nj][0] = __float_as_uint(bb.x);   // b0
                bfr[nj][1] = __float_as_uint(bb.y);   // b1
            }
            #pragma unroll
            for (int mi = 0; mi < 4; mi++)
                #pragma unroll
                for (int nj = 0; nj < 8; nj++)
                    mma_tf32(acc[mi][nj], afr[mi][0], afr[mi][1], afr[mi][2],
                             afr[mi][3], bfr[nj][0], bfr[nj][1]);
        }

        if (t + 1 < KT) {
            const int nb = buf ^ 1;
            #pragma unroll
            for (int g = 0; g < 2; g++) {
                const float4 a0 = ra[g * 2], a1 = ra[g * 2 + 1];
                const float4 b0 = rb[g * 2], b1 = rb[g * 2 + 1];
                float* dA = &sA[nb][stBase + g * 8];
                float* dB = &sB[nb][stBase + g * 8];
                *(float4*)(dA)     = make_float4(cvt_tf32(a0.x), cvt_tf32(a1.x), cvt_tf32(a0.y), cvt_tf32(a1.y));
                *(float4*)(dA + 4) = make_float4(cvt_tf32(a0.z), cvt_tf32(a1.z), cvt_tf32(a0.w), cvt_tf32(a1.w));
                *(float4*)(dB)     = make_float4(cvt_tf32(b0.x), cvt_tf32(b1.x), cvt_tf32(b0.y), cvt_tf32(b1.y));
                *(float4*)(dB + 4) = make_float4(cvt_tf32(b0.z), cvt_tf32(b1.z), cvt_tf32(b0.w), cvt_tf32(b1.w));
            }
        }
        __syncthreads();
    }

    // epilogue: direct global stores with bias
    const int mBase = blockIdx.y * 128 + wm * 64;
    const int nBase = blockIdx.x * 128 + wn * 64;
    #pragma unroll
    for (int mi = 0; mi < 4; mi++) {
        #pragma unroll
        for (int nj = 0; nj < 8; nj++) {
            const int col = nBase + nj * 8 + qc * 2;
            const float bx0 = bias[col], bx1 = bias[col + 1];
            const int r0 = mBase + mi * 16 + qr;
            float2 o0 = make_float2(acc[mi][nj][0] + bx0, acc[mi][nj][1] + bx1);
            float2 o1 = make_float2(acc[mi][nj][2] + bx0, acc[mi][nj][3] + bx1);
            *(float2*)(C + (size_t)r0 * N + col)       = o0;
            *(float2*)(C + (size_t)(r0 + 8) * N + col) = o1;
        }
    }
}

// ---------------------------------------------------------------------------
// Flash attention, fp32 (unchanged from passing R1 kernel).
// ---------------------------------------------------------------------------
__global__ void __launch_bounds__(256) flash_kernel()
{
    const int qt = blockIdx.x;
    const int h  = blockIdx.y;
    const int b  = blockIdx.z;

    __shared__ __align__(16) float sQ[64 * 64];
    __shared__ __align__(16) float sK[64 * 64];
    __shared__ __align__(16) float sV[64 * 64];

    const int tid = threadIdx.x;
    const int tr  = tid >> 4;
    const int tc  = tid & 15;

    const float* qbase = g_qkv + (size_t)(b * SEQ + qt * 64) * E3 + h * HD;
    const float* kbase = g_qkv + (size_t)(b * SEQ) * E3 + EMB     + h * HD;
    const float* vbase = g_qkv + (size_t)(b * SEQ) * E3 + 2 * EMB + h * HD;

    {
        const int d4 = tid & 15;
        const int r0 = tid >> 4;
        #pragma unroll
        for (int p = 0; p < 4; p++) {
            const int r = r0 + p * 16;
            float4 v = *(const float4*)(qbase + (size_t)r * E3 + d4 * 4);
            v.x *= 0.125f; v.y *= 0.125f; v.z *= 0.125f; v.w *= 0.125f;
            const int gs = (r >> 2) ^ d4;
            const int rm = r & 3;
            sQ[(4 * d4 + 0) * 64 + gs * 4 + rm] = v.x;
            sQ[(4 * d4 + 1) * 64 + gs * 4 + rm] = v.y;
            sQ[(4 * d4 + 2) * 64 + gs * 4 + rm] = v.z;
            sQ[(4 * d4 + 3) * 64 + gs * 4 + rm] = v.w;
        }
    }

    float m_i[4], l_i[4], acc[4][4];
    #pragma unroll
    for (int i = 0; i < 4; i++) {
        m_i[i] = -CUDART_INF_F;
        l_i[i] = 0.0f;
        #pragma unroll
        for (int j = 0; j < 4; j++) acc[i][j] = 0.0f;
    }

    for (int kt = 0; kt < SEQ / 64; kt++) {
        __syncthreads();
        {
            const int d4 = tid & 15;
            const int r0 = tid >> 4;
            #pragma unroll
            for (int p = 0; p < 4; p++) {
                const int c = r0 + p * 16;
                const size_t roff = (size_t)(kt * 64 + c) * E3 + d4 * 4;
                float4 kv = *(const float4*)(kbase + roff);
                const int gs = (c >> 2) ^ d4;
                const int cm = c & 3;
                sK[(4 * d4 + 0) * 64 + gs * 4 + cm] = kv.x;
                sK[(4 * d4 + 1) * 64 + gs * 4 + cm] = kv.y;
                sK[(4 * d4 + 2) * 64 + gs * 4 + cm] = kv.z;
                sK[(4 * d4 + 3) * 64 + gs * 4 + cm] = kv.w;
                float4 vv = *(const float4*)(vbase + roff);
                *(float4*)&sV[c * 64 + d4 * 4] = vv;
            }
        }
        __syncthreads();

        float s[4][4] = {};
        #pragma unroll 8
        for (int k = 0; k < 64; k++) {
            const int f = k >> 2;
            float q[4], kk[4];
            *(float4*)q  = *(const float4*)&sQ[k * 64 + ((tr ^ f) << 2)];
            *(float4*)kk = *(const float4*)&sK[k * 64 + ((tc ^ f) << 2)];
            #pragma unroll
            for (int i = 0; i < 4; i++)
                #pragma unroll
                for (int j = 0; j < 4; j++)
                    s[i][j] = fmaf(q[i], kk[j], s[i][j]);
        }

        #pragma unroll
        for (int i = 0; i < 4; i++) {
            float tm = fmaxf(fmaxf(s[i][0], s[i][1]), fmaxf(s[i][2], s[i][3]));
            tm = fmaxf(tm, __shfl_xor_sync(0xffffffffu, tm, 1));
            tm = fmaxf(tm, __shfl_xor_sync(0xffffffffu, tm, 2));
            tm = fmaxf(tm, __shfl_xor_sync(0xffffffffu, tm, 4));
            tm = fmaxf(tm, __shfl_xor_sync(0xffffffffu, tm, 8));
            const float mnew  = fmaxf(m_i[i], tm);
            const float alpha = __expf(m_i[i] - mnew);
            float ps = 0.0f;
            #pragma unroll
            for (int j = 0; j < 4; j++) {
                s[i][j] = __expf(s[i][j] - mnew);
                ps += s[i][j];
            }
            ps += __shfl_xor_sync(0xffffffffu, ps, 1);
            ps += __shfl_xor_sync(0xffffffffu, ps, 2);
            ps += __shfl_xor_sync(0xffffffffu, ps, 4);
            ps += __shfl_xor_sync(0xffffffffu, ps, 8);
            l_i[i] = l_i[i] * alpha + ps;
            m_i[i] = mnew;
            #pragma unroll
            for (int j = 0; j < 4; j++) acc[i][j] *= alpha;
        }

        __syncthreads();

        #pragma unroll
        for (int j = 0; j < 4; j++) {
            const int c  = tc * 4 + j;
            const int gs = tr ^ tc;
            *(float4*)&sK[c * 64 + gs * 4] =
                make_float4(s[0][j], s[1][j], s[2][j], s[3][j]);
        }
        __syncthreads();

        #pragma unroll 8
        for (int c = 0; c < 64; c++) {
            float p[4], v[4];
            *(float4*)p = *(const float4*)&sK[c * 64 + ((tr ^ (c >> 2)) << 2)];
            *(float4*)v = *(const float4*)&sV[c * 64 + (tc << 2)];
            #pragma unroll
            for (int i = 0; i < 4; i++)
                #pragma unroll
                for (int j = 0; j < 4; j++)
                    acc[i][j] = fmaf(p[i], v[j], acc[i][j]);
        }
    }

    #pragma unroll
    for (int i = 0; i < 4; i++) {
        const float rl = 1.0f / l_i[i];
        const int r = qt * 64 + tr * 4 + i;
        float4 o = make_float4(acc[i][0] * rl, acc[i][1] * rl,
                               acc[i][2] * rl, acc[i][3] * rl);
        *(float4*)(g_attn + (size_t)(b * SEQ + r) * EMB + h * HD + tc * 4) = o;
    }
}

// ---------------------------------------------------------------------------
extern "C" void kernel_launch(void* const* d_in, const int* in_sizes, int n_in,
                              void* d_out, int out_size)
{
    (void)in_sizes; (void)n_in; (void)out_size;
    const float* x     = (const float*)d_in[0];
    const float* w_in  = (const float*)d_in[1];
    const float* b_in  = (const float*)d_in[2];
    const float* w_out = (const float*)d_in[3];
    const float* b_out = (const float*)d_in[4];
    float* out = (float*)d_out;

    void *qkv_p, *attn_p, *wti_p, *wto_p;
    cudaGetSymbolAddress(&qkv_p,  g_qkv);
    cudaGetSymbolAddress(&attn_p, g_attn);
    cudaGetSymbolAddress(&wti_p,  g_wti);
    cudaGetSymbolAddress(&wto_p,  g_wto);

    // 0) transpose weights to K-major [N, K]
    transpose_k<<<dim3(E3 / 32, EMB / 32), dim3(32, 8)>>>(w_in,  (float*)wti_p, EMB, E3);
    transpose_k<<<dim3(EMB / 32, EMB / 32), dim3(32, 8)>>>(w_out, (float*)wto_p, EMB, EMB);

    // 1) QKV projection (tf32 mma): [4096,1024] @ [1024,3072] + b_in
    gemm_tf32mma<<<dim3(E3 / 128, MTOT / 128), 128>>>(
        E3, EMB, x, (const float*)wti_p, b_in, (float*)qkv_p);

    // 2) Attention
    flash_kernel<<<dim3(SEQ / 64, NH, BATCH), 256>>>();

    // 3) Output projection (tf32 mma): [4096,1024] @ [1024,1024] + b_out
    gemm_tf32mma<<<dim3(EMB / 128, MTOT / 128), 128>>>(
        EMB, EMB, (const float*)attn_p, (const float*)wto_p, b_out, out);
}

// round 4
// speedup vs baseline: 1.9168x; 1.4838x over previous
#include <cuda_runtime.h>
#include <cuda_bf16.h>
#include <math_constants.h>
#include <cstdint>

// Problem constants
#define BATCH 2
#define SEQ   2048
#define EMB   1024
#define E3    3072
#define NH    16
#define HD    64
#define MTOT  (BATCH*SEQ)   // 4096

// Scratch (static device globals — no cudaMalloc allowed)
__device__ float g_qkv [(size_t)MTOT * E3];   // [4096, 3072]
__device__ float g_attn[(size_t)MTOT * EMB];  // [4096, 1024]
__device__ float g_wti [(size_t)E3 * EMB];    // w_in^T  [3072, 1024]
__device__ float g_wto [(size_t)EMB * EMB];   // w_out^T [1024, 1024]

// ---------------------------------------------------------------------------
__device__ __forceinline__ float cvt_tf32(float x) {
    uint32_t u;
    asm("cvt.rna.tf32.f32 %0, %1;" : "=r"(u) : "f"(x));
    return __uint_as_float(u);
}

__device__ __forceinline__ void mma_tf32(float c[4], uint32_t a0, uint32_t a1,
                                         uint32_t a2, uint32_t a3,
                                         uint32_t b0, uint32_t b1) {
    asm volatile(
        "mma.sync.aligned.m16n8k8.row.col.f32.tf32.tf32.f32 "
        "{%0,%1,%2,%3}, {%4,%5,%6,%7}, {%8,%9}, {%0,%1,%2,%3};"
        : "+f"(c[0]), "+f"(c[1]), "+f"(c[2]), "+f"(c[3])
        : "r"(a0), "r"(a1), "r"(a2), "r"(a3), "r"(b0), "r"(b1));
}

// ---------------------------------------------------------------------------
// Transpose: out[C,R] = in[R,C]^T  (R, C multiples of 32). block (32,8).
// ---------------------------------------------------------------------------
__global__ void __launch_bounds__(256) transpose_k(
    const float* __restrict__ in, float* __restrict__ out, int R, int C)
{
    __shared__ float t[32][33];
    const int bx = blockIdx.x * 32;
    const int by = blockIdx.y * 32;
    const int x = bx + threadIdx.x;
    #pragma unroll
    for (int j = 0; j < 4; j++) {
        const int y = by + threadIdx.y + j * 8;
        t[threadIdx.y + j * 8][threadIdx.x] = in[(size_t)y * C + x];
    }
    __syncthreads();
    const int x2 = by + threadIdx.x;
    #pragma unroll
    for (int j = 0; j < 4; j++) {
        const int y2 = bx + threadIdx.y + j * 8;
        out[(size_t)y2 * R + x2] = t[threadIdx.x][threadIdx.y + j * 8];
    }
}

// ---------------------------------------------------------------------------
// tf32 mma.sync GEMM + bias (unchanged from R3, passing)
// ---------------------------------------------------------------------------
__global__ void __launch_bounds__(128) gemm_tf32mma(
    int N, int K,
    const float* __restrict__ A,
    const float* __restrict__ Bt,
    const float* __restrict__ bias,
    float* __restrict__ C)
{
    __shared__ __align__(16) float sA[2][128 * 24];
    __shared__ __align__(16) float sB[2][128 * 24];

    const int tid  = threadIdx.x;
    const int wid  = tid >> 5;
    const int lane = tid & 31;
    const int wm   = wid >> 1;
    const int wn   = wid & 1;
    const int qr   = lane >> 2;
    const int qc   = lane & 3;

    const float* Arow = A  + (size_t)(blockIdx.y * 128 + tid) * K;
    const float* Brow = Bt + (size_t)(blockIdx.x * 128 + tid) * K;

    const int stBase = tid * 24 + ((tid >> 2) & 1) * 4;
    const int ldBase = qr * 24 + ((qr >> 2) & 1) * 4 + qc * 2;

    float acc[4][8][4];
    #pragma unroll
    for (int i = 0; i < 4; i++)
        #pragma unroll
        for (int j = 0; j < 8; j++)
            #pragma unroll
            for (int c = 0; c < 4; c++) acc[i][j][c] = 0.0f;

    const int KT = K / 16;
    float4 ra[4], rb[4];

    #pragma unroll
    for (int q = 0; q < 4; q++) {
        ra[q] = *(const float4*)(Arow + q * 4);
        rb[q] = *(const float4*)(Brow + q * 4);
    }
    #pragma unroll
    for (int g = 0; g < 2; g++) {
        const float4 a0 = ra[g * 2], a1 = ra[g * 2 + 1];
        const float4 b0 = rb[g * 2], b1 = rb[g * 2 + 1];
        float* dA = &sA[0][stBase + g * 8];
        float* dB = &sB[0][stBase + g * 8];
        *(float4*)(dA)     = make_float4(cvt_tf32(a0.x), cvt_tf32(a1.x), cvt_tf32(a0.y), cvt_tf32(a1.y));
        *(float4*)(dA + 4) = make_float4(cvt_tf32(a0.z), cvt_tf32(a1.z), cvt_tf32(a0.w), cvt_tf32(a1.w));
        *(float4*)(dB)     = make_float4(cvt_tf32(b0.x), cvt_tf32(b1.x), cvt_tf32(b0.y), cvt_tf32(b1.y));
        *(float4*)(dB + 4) = make_float4(cvt_tf32(b0.z), cvt_tf32(b1.z), cvt_tf32(b0.w), cvt_tf32(b1.w));
    }
    __syncthreads();

    for (int t = 0; t < KT; t++) {
        const int buf = t & 1;
        if (t + 1 < KT) {
            const int k0 = (t + 1) * 16;
            #pragma unroll
            for (int q = 0; q < 4; q++) {
                ra[q] = *(const float4*)(Arow + k0 + q * 4);
                rb[q] = *(const float4*)(Brow + k0 + q * 4);
            }
        }

        #pragma unroll
        for (int g = 0; g < 2; g++) {
            const float* pA = &sA[buf][wm * 1536 + g * 8 + ldBase];
            const float* pB = &sB[buf][wn * 1536 + g * 8 + ldBase];

            uint32_t afr[4][4];
            #pragma unroll
            for (int mi = 0; mi < 4; mi++) {
                const float2 lo = *(const float2*)(pA + mi * 384);
                const float2 hi = *(const float2*)(pA + mi * 384 + 192);
                afr[mi][0] = __float_as_uint(lo.x);
                afr[mi][2] = __float_as_uint(lo.y);
                afr[mi][1] = __float_as_uint(hi.x);
                afr[mi][3] = __float_as_uint(hi.y);
            }
            uint32_t bfr[8][2];
            #pragma unroll
            for (int nj = 0; nj < 8; nj++) {
                const float2 bb = *(const float2*)(pB + nj * 192);
                bfr[nj][0] = __float_as_uint(bb.x);
                bfr[nj][1] = __float_as_uint(bb.y);
            }
            #pragma unroll
            for (int mi = 0; mi < 4; mi++)
                #pragma unroll
                for (int nj = 0; nj < 8; nj++)
                    mma_tf32(acc[mi][nj], afr[mi][0], afr[mi][1], afr[mi][2],
                             afr[mi][3], bfr[nj][0], bfr[nj][1]);
        }

        if (t + 1 < KT) {
            const int nb = buf ^ 1;
            #pragma unroll
            for (int g = 0; g < 2; g++) {
                const float4 a0 = ra[g * 2], a1 = ra[g * 2 + 1];
                const float4 b0 = rb[g * 2], b1 = rb[g * 2 + 1];
                float* dA = &sA[nb][stBase + g * 8];
                float* dB = &sB[nb][stBase + g * 8];
                *(float4*)(dA)     = make_float4(cvt_tf32(a0.x), cvt_tf32(a1.x), cvt_tf32(a0.y), cvt_tf32(a1.y));
                *(float4*)(dA + 4) = make_float4(cvt_tf32(a0.z), cvt_tf32(a1.z), cvt_tf32(a0.w), cvt_tf32(a1.w));
                *(float4*)(dB)     = make_float4(cvt_tf32(b0.x), cvt_tf32(b1.x), cvt_tf32(b0.y), cvt_tf32(b1.y));
                *(float4*)(dB + 4) = make_float4(cvt_tf32(b0.z), cvt_tf32(b1.z), cvt_tf32(b0.w), cvt_tf32(b1.w));
            }
        }
        __syncthreads();
    }

    const int mBase = blockIdx.y * 128 + wm * 64;
    const int nBase = blockIdx.x * 128 + wn * 64;
    #pragma unroll
    for (int mi = 0; mi < 4; mi++) {
        #pragma unroll
        for (int nj = 0; nj < 8; nj++) {
            const int col = nBase + nj * 8 + qc * 2;
            const float bx0 = bias[col], bx1 = bias[col + 1];
            const int r0 = mBase + mi * 16 + qr;
            float2 o0 = make_float2(acc[mi][nj][0] + bx0, acc[mi][nj][1] + bx1);
            float2 o1 = make_float2(acc[mi][nj][2] + bx0, acc[mi][nj][3] + bx1);
            *(float2*)(C + (size_t)r0 * N + col)       = o0;
            *(float2*)(C + (size_t)(r0 + 8) * N + col) = o1;
        }
    }
}

// ---------------------------------------------------------------------------
// Tensor-core flash attention, tf32 mma.sync.
// Grid (SEQ/128, NH, BATCH), 128 threads (4 warps, 32 query rows each).
// SMEM tiles, all row-stride 68 floats:
//   sQ[128][64] (d cols), sK[64][64] (d cols), sVt[64 d][64 keys],
//   sP[128][64] (key cols). Fragment LDS.32 bank pattern = qr*4+qc (free).
// ---------------------------------------------------------------------------
#define FB_M 128
#define FB_N 64
#define F_STR 68
#define FLASH_SMEM ((FB_M*F_STR + 64*F_STR + 64*F_STR + FB_M*F_STR) * 4)

__global__ void __launch_bounds__(128) flash_tc()
{
    extern __shared__ float fsm[];
    float* sQ  = fsm;                       // 128*68
    float* sK  = sQ  + FB_M * F_STR;        // 64*68
    float* sVt = sK  + 64 * F_STR;          // 64*68
    float* sP  = sVt + 64 * F_STR;          // 128*68

    const int qt = blockIdx.x, h = blockIdx.y, b = blockIdx.z;
    const int tid  = threadIdx.x;
    const int wid  = tid >> 5;
    const int lane = tid & 31;
    const int qr   = lane >> 2;
    const int qc   = lane & 3;
    const int rb   = wid * 32;              // warp's query-row base in tile

    const float* qg = g_qkv + (size_t)(b * SEQ + qt * FB_M) * E3 + h * HD;
    const float* kg = g_qkv + (size_t)(b * SEQ) * E3 + EMB     + h * HD;
    const float* vg = g_qkv + (size_t)(b * SEQ) * E3 + 2 * EMB + h * HD;

    // ---- load Q (row = tid), pre-scaled by 1/8, tf32-rounded ----
    {
        const float* src = qg + (size_t)tid * E3;
        float* dst = sQ + tid * F_STR;
        #pragma unroll
        for (int p = 0; p < 16; p++) {
            float4 v = *(const float4*)(src + p * 4);
            *(float4*)(dst + p * 4) = make_float4(
                cvt_tf32(v.x * 0.125f), cvt_tf32(v.y * 0.125f),
                cvt_tf32(v.z * 0.125f), cvt_tf32(v.w * 0.125f));
        }
    }

    float o[2][8][4];
    float m_i[4], l_i[4];
    #pragma unroll
    for (int mt = 0; mt < 2; mt++)
        #pragma unroll
        for (int j = 0; j < 8; j++)
            #pragma unroll
            for (int c = 0; c < 4; c++) o[mt][j][c] = 0.0f;
    #pragma unroll
    for (int i = 0; i < 4; i++) { m_i[i] = -CUDART_INF_F; l_i[i] = 0.0f; }

    const int krow = tid & 63;
    const int c4b  = (tid >> 6) * 8;

    for (int kt = 0; kt < SEQ / FB_N; kt++) {
        __syncthreads();   // prev iter's QK/PV done with sK/sVt/sP

        // ---- load K tile [64 keys][64 d] and V^T tile [64 d][64 keys] ----
        {
            const float* ksrc = kg + (size_t)(kt * 64 + krow) * E3;
            const float* vsrc = vg + (size_t)(kt * 64 + krow) * E3;
            float* kdst = sK + krow * F_STR;
            #pragma unroll
            for (int p = 0; p < 8; p++) {
                const int c4 = c4b + p;
                float4 v = *(const float4*)(ksrc + c4 * 4);
                *(float4*)(kdst + c4 * 4) = make_float4(
                    cvt_tf32(v.x), cvt_tf32(v.y), cvt_tf32(v.z), cvt_tf32(v.w));
                float4 w = *(const float4*)(vsrc + c4 * 4);
                sVt[(c4 * 4 + 0) * F_STR + krow] = cvt_tf32(w.x);
                sVt[(c4 * 4 + 1) * F_STR + krow] = cvt_tf32(w.y);
                sVt[(c4 * 4 + 2) * F_STR + krow] = cvt_tf32(w.z);
                sVt[(c4 * 4 + 3) * F_STR + krow] = cvt_tf32(w.w);
            }
        }
        __syncthreads();

        // ---- S = Q K^T (tf32 mma), per warp: m32 x n64 x k64 ----
        float s[2][8][4];
        #pragma unroll
        for (int mt = 0; mt < 2; mt++)
            #pragma unroll
            for (int j = 0; j < 8; j++)
                #pragma unroll
                for (int c = 0; c < 4; c++) s[mt][j][c] = 0.0f;

        #pragma unroll
        for (int g = 0; g < 8; g++) {
            uint32_t a[2][4];
            #pragma unroll
            for (int mt = 0; mt < 2; mt++) {
                const float* q0 = sQ + (rb + mt * 16 + qr) * F_STR + g * 8 + qc;
                a[mt][0] = __float_as_uint(q0[0]);
                a[mt][2] = __float_as_uint(q0[4]);
                a[mt][1] = __float_as_uint(q0[8 * F_STR]);
                a[mt][3] = __float_as_uint(q0[8 * F_STR + 4]);
            }
            #pragma unroll
            for (int j = 0; j < 8; j++) {
                const float* kp = sK + (j * 8 + qr) * F_STR + g * 8 + qc;
                const uint32_t b0 = __float_as_uint(kp[0]);
                const uint32_t b1 = __float_as_uint(kp[4]);
                mma_tf32(s[0][j], a[0][0], a[0][1], a[0][2], a[0][3], b0, b1);
                mma_tf32(s[1][j], a[1][0], a[1][1], a[1][2], a[1][3], b0, b1);
            }
        }

        // ---- online softmax (rows qr / qr+8 per m-tile) ----
        #pragma unroll
        for (int mt = 0; mt < 2; mt++) {
            #pragma unroll
            for (int hf = 0; hf < 2; hf++) {
                const int mi = mt * 2 + hf;
                float tm = -CUDART_INF_F;
                #pragma unroll
                for (int j = 0; j < 8; j++)
                    tm = fmaxf(tm, fmaxf(s[mt][j][hf * 2], s[mt][j][hf * 2 + 1]));
                tm = fmaxf(tm, __shfl_xor_sync(0xffffffffu, tm, 1));
                tm = fmaxf(tm, __shfl_xor_sync(0xffffffffu, tm, 2));
                const float mnew  = fmaxf(m_i[mi], tm);
                const float alpha = __expf(m_i[mi] - mnew);
                float ps = 0.0f;
                #pragma unroll
                for (int j = 0; j < 8; j++) {
                    float p0 = cvt_tf32(__expf(s[mt][j][hf * 2]     - mnew));
                    float p1 = cvt_tf32(__expf(s[mt][j][hf * 2 + 1] - mnew));
                    s[mt][j][hf * 2]     = p0;
                    s[mt][j][hf * 2 + 1] = p1;
                    ps += p0 + p1;
                }
                ps += __shfl_xor_sync(0xffffffffu, ps, 1);
                ps += __shfl_xor_sync(0xffffffffu, ps, 2);
                l_i[mi] = l_i[mi] * alpha + ps;
                m_i[mi] = mnew;
                #pragma unroll
                for (int j = 0; j < 8; j++) {
                    o[mt][j][hf * 2]     *= alpha;
                    o[mt][j][hf * 2 + 1] *= alpha;
                }
            }
        }

        // ---- store P to SMEM (own rows only) ----
        #pragma unroll
        for (int mt = 0; mt < 2; mt++) {
            #pragma unroll
            for (int j = 0; j < 8; j++) {
                float* pp = sP + (rb + mt * 16 + qr) * F_STR + j * 8 + 2 * qc;
                *(float2*)pp = make_float2(s[mt][j][0], s[mt][j][1]);
                *(float2*)(pp + 8 * F_STR) = make_float2(s[mt][j][2], s[mt][j][3]);
            }
        }
        __syncwarp();

        // ---- O += P V (tf32 mma), contraction over keys ----
        #pragma unroll
        for (int g = 0; g < 8; g++) {
            uint32_t a[2][4];
            #pragma unroll
            for (int mt = 0; mt < 2; mt++) {
                const float* p0 = sP + (rb + mt * 16 + qr) * F_STR + g * 8 + qc;
                a[mt][0] = __float_as_uint(p0[0]);
                a[mt][2] = __float_as_uint(p0[4]);
                a[mt][1] = __float_as_uint(p0[8 * F_STR]);
                a[mt][3] = __float_as_uint(p0[8 * F_STR + 4]);
            }
            #pragma unroll
            for (int j = 0; j < 8; j++) {
                const float* vp = sVt + (j * 8 + qr) * F_STR + g * 8 + qc;
                const uint32_t b0 = __float_as_uint(vp[0]);
                const uint32_t b1 = __float_as_uint(vp[4]);
                mma_tf32(o[0][j], a[0][0], a[0][1], a[0][2], a[0][3], b0, b1);
                mma_tf32(o[1][j], a[1][0], a[1][1], a[1][2], a[1][3], b0, b1);
            }
        }
    }

    // ---- epilogue: normalize, write [B,S,E] ----
    #pragma unroll
    for (int mt = 0; mt < 2; mt++) {
        const float inv0 = 1.0f / l_i[mt * 2];
        const float inv1 = 1.0f / l_i[mt * 2 + 1];
        const size_t row0 = (size_t)(b * SEQ + qt * FB_M + rb + mt * 16 + qr);
        #pragma unroll
        for (int j = 0; j < 8; j++) {
            const int col = h * HD + j * 8 + 2 * qc;
            *(float2*)(g_attn + row0 * EMB + col) =
                make_float2(o[mt][j][0] * inv0, o[mt][j][1] * inv0);
            *(float2*)(g_attn + (row0 + 8) * EMB + col) =
                make_float2(o[mt][j][2] * inv1, o[mt][j][3] * inv1);
        }
    }
}

// ---------------------------------------------------------------------------
extern "C" void kernel_launch(void* const* d_in, const int* in_sizes, int n_in,
                              void* d_out, int out_size)
{
    (void)in_sizes; (void)n_in; (void)out_size;
    const float* x     = (const float*)d_in[0];
    const float* w_in  = (const float*)d_in[1];
    const float* b_in  = (const float*)d_in[2];
    const float* w_out = (const float*)d_in[3];
    const float* b_out = (const float*)d_in[4];
    float* out = (float*)d_out;

    void *qkv_p, *attn_p, *wti_p, *wto_p;
    cudaGetSymbolAddress(&qkv_p,  g_qkv);
    cudaGetSymbolAddress(&attn_p, g_attn);
    cudaGetSymbolAddress(&wti_p,  g_wti);
    cudaGetSymbolAddress(&wto_p,  g_wto);

    cudaFuncSetAttribute(flash_tc, cudaFuncAttributeMaxDynamicSharedMemorySize,
                         FLASH_SMEM);

    // 0) transpose weights to K-major [N, K]
    transpose_k<<<dim3(E3 / 32, EMB / 32), dim3(32, 8)>>>(w_in,  (float*)wti_p, EMB, E3);
    transpose_k<<<dim3(EMB / 32, EMB / 32), dim3(32, 8)>>>(w_out, (float*)wto_p, EMB, EMB);

    // 1) QKV projection (tf32 mma): [4096,1024] @ [1024,3072] + b_in
    gemm_tf32mma<<<dim3(E3 / 128, MTOT / 128), 128>>>(
        E3, EMB, x, (const float*)wti_p, b_in, (float*)qkv_p);

    // 2) Attention (tensor-core flash)
    flash_tc<<<dim3(SEQ / FB_M, NH, BATCH), 128, FLASH_SMEM>>>();

    // 3) Output projection (tf32 mma): [4096,1024] @ [1024,1024] + b_out
    gemm_tf32mma<<<dim3(EMB / 128, MTOT / 128), 128>>>(
        EMB, EMB, (const float*)attn_p, (const float*)wto_p, b_out, out);
}

// round 5
// speedup vs baseline: 1.9345x; 1.0092x over previous
#include <cuda_runtime.h>
#include <cuda_bf16.h>
#include <math_constants.h>
#include <cstdint>

// Problem constants
#define BATCH 2
#define SEQ   2048
#define EMB   1024
#define E3    3072
#define NH    16
#define HD    64
#define MTOT  (BATCH*SEQ)   // 4096

// Scratch (static device globals — no cudaMalloc allowed)
__device__ float g_qkv [(size_t)MTOT * E3];   // [4096, 3072]
__device__ float g_attn[(size_t)MTOT * EMB];  // [4096, 1024]
__device__ float g_wti [(size_t)E3 * EMB];    // w_in^T  [3072, 1024]
__device__ float g_wto [(size_t)EMB * EMB];   // w_out^T [1024, 1024]

// ---------------------------------------------------------------------------
__device__ __forceinline__ float cvt_tf32(float x) {
    uint32_t u;
    asm("cvt.rna.tf32.f32 %0, %1;" : "=r"(u) : "f"(x));
    return __uint_as_float(u);
}

__device__ __forceinline__ void mma_tf32(float c[4], uint32_t a0, uint32_t a1,
                                         uint32_t a2, uint32_t a3,
                                         uint32_t b0, uint32_t b1) {
    asm volatile(
        "mma.sync.aligned.m16n8k8.row.col.f32.tf32.tf32.f32 "
        "{%0,%1,%2,%3}, {%4,%5,%6,%7}, {%8,%9}, {%0,%1,%2,%3};"
        : "+f"(c[0]), "+f"(c[1]), "+f"(c[2]), "+f"(c[3])
        : "r"(a0), "r"(a1), "r"(a2), "r"(a3), "r"(b0), "r"(b1));
}

// ---------------------------------------------------------------------------
// Transpose: out[C,R] = in[R,C]^T  (R, C multiples of 32). block (32,8).
// ---------------------------------------------------------------------------
__global__ void __launch_bounds__(256) transpose_k(
    const float* __restrict__ in, float* __restrict__ out, int R, int C)
{
    __shared__ float t[32][33];
    const int bx = blockIdx.x * 32;
    const int by = blockIdx.y * 32;
    const int x = bx + threadIdx.x;
    #pragma unroll
    for (int j = 0; j < 4; j++) {
        const int y = by + threadIdx.y + j * 8;
        t[threadIdx.y + j * 8][threadIdx.x] = in[(size_t)y * C + x];
    }
    __syncthreads();
    const int x2 = by + threadIdx.x;
    #pragma unroll
    for (int j = 0; j < 4; j++) {
        const int y2 = bx + threadIdx.y + j * 8;
        out[(size_t)y2 * R + x2] = t[threadIdx.x][threadIdx.y + j * 8];
    }
}

// ---------------------------------------------------------------------------
// tf32 mma.sync GEMM + bias: C[M,N] = A[M,K] @ Bt[N,K]^T + bias[N]
// CTA 128x128, 8 warps (4x2), warp tile 32x64, BK=16, double-buffered SMEM.
// SMEM layout (row stride 24, k-permuted) identical to R3 — verified
// conflict-free STS.128 staging and LDS.64 fragment loads.
// ---------------------------------------------------------------------------
__global__ void __launch_bounds__(256, 2) gemm_tf32mma(
    int N, int K,
    const float* __restrict__ A,
    const float* __restrict__ Bt,
    const float* __restrict__ bias,
    float* __restrict__ C)
{
    __shared__ __align__(16) float sA[2][128 * 24];
    __shared__ __align__(16) float sB[2][128 * 24];

    const int tid  = threadIdx.x;
    const int wid  = tid >> 5;
    const int lane = tid & 31;
    const int wm   = wid >> 1;       // 0..3 : 32-row slice
    const int wn   = wid & 1;        // 0..1 : 64-col slice
    const int qr   = lane >> 2;
    const int qc   = lane & 3;

    const int row = tid & 127;       // staging row owned by this thread
    const int kg  = tid >> 7;        // k-group 0/1 (8 k each)

    const float* Arow = A  + (size_t)(blockIdx.y * 128 + row) * K + kg * 8;
    const float* Brow = Bt + (size_t)(blockIdx.x * 128 + row) * K + kg * 8;

    const int stBase = row * 24 + ((row >> 2) & 1) * 4 + kg * 8;
    const int ldBase = qr * 24 + ((qr >> 2) & 1) * 4 + qc * 2;

    float acc[2][8][4];
    #pragma unroll
    for (int i = 0; i < 2; i++)
        #pragma unroll
        for (int j = 0; j < 8; j++)
            #pragma unroll
            for (int c = 0; c < 4; c++) acc[i][j][c] = 0.0f;

    const int KT = K / 16;
    float4 ra0, ra1, rb0, rb1;

    // prefetch + stage tile 0
    ra0 = *(const float4*)(Arow);     ra1 = *(const float4*)(Arow + 4);
    rb0 = *(const float4*)(Brow);     rb1 = *(const float4*)(Brow + 4);
    {
        float* dA = &sA[0][stBase];
        float* dB = &sB[0][stBase];
        *(float4*)(dA)     = make_float4(cvt_tf32(ra0.x), cvt_tf32(ra1.x), cvt_tf32(ra0.y), cvt_tf32(ra1.y));
        *(float4*)(dA + 4) = make_float4(cvt_tf32(ra0.z), cvt_tf32(ra1.z), cvt_tf32(ra0.w), cvt_tf32(ra1.w));
        *(float4*)(dB)     = make_float4(cvt_tf32(rb0.x), cvt_tf32(rb1.x), cvt_tf32(rb0.y), cvt_tf32(rb1.y));
        *(float4*)(dB + 4) = make_float4(cvt_tf32(rb0.z), cvt_tf32(rb1.z), cvt_tf32(rb0.w), cvt_tf32(rb1.w));
    }
    __syncthreads();

    for (int t = 0; t < KT; t++) {
        const int buf = t & 1;
        if (t + 1 < KT) {
            const int k0 = (t + 1) * 16;
            ra0 = *(const float4*)(Arow + k0);     ra1 = *(const float4*)(Arow + k0 + 4);
            rb0 = *(const float4*)(Brow + k0);     rb1 = *(const float4*)(Brow + k0 + 4);
        }

        #pragma unroll
        for (int g = 0; g < 2; g++) {
            const float* pA = &sA[buf][wm * 768 + g * 8 + ldBase];
            const float* pB = &sB[buf][wn * 1536 + g * 8 + ldBase];

            uint32_t afr[2][4];
            #pragma unroll
            for (int mi = 0; mi < 2; mi++) {
                const float2 lo = *(const float2*)(pA + mi * 384);
                const float2 hi = *(const float2*)(pA + mi * 384 + 192);
                afr[mi][0] = __float_as_uint(lo.x);
                afr[mi][2] = __float_as_uint(lo.y);
                afr[mi][1] = __float_as_uint(hi.x);
                afr[mi][3] = __float_as_uint(hi.y);
            }
            uint32_t bfr[8][2];
            #pragma unroll
            for (int nj = 0; nj < 8; nj++) {
                const float2 bb = *(const float2*)(pB + nj * 192);
                bfr[nj][0] = __float_as_uint(bb.x);
                bfr[nj][1] = __float_as_uint(bb.y);
            }
            #pragma unroll
            for (int mi = 0; mi < 2; mi++)
                #pragma unroll
                for (int nj = 0; nj < 8; nj++)
                    mma_tf32(acc[mi][nj], afr[mi][0], afr[mi][1], afr[mi][2],
                             afr[mi][3], bfr[nj][0], bfr[nj][1]);
        }

        if (t + 1 < KT) {
            const int nb = buf ^ 1;
            float* dA = &sA[nb][stBase];
            float* dB = &sB[nb][stBase];
            *(float4*)(dA)     = make_float4(cvt_tf32(ra0.x), cvt_tf32(ra1.x), cvt_tf32(ra0.y), cvt_tf32(ra1.y));
            *(float4*)(dA + 4) = make_float4(cvt_tf32(ra0.z), cvt_tf32(ra1.z), cvt_tf32(ra0.w), cvt_tf32(ra1.w));
            *(float4*)(dB)     = make_float4(cvt_tf32(rb0.x), cvt_tf32(rb1.x), cvt_tf32(rb0.y), cvt_tf32(rb1.y));
            *(float4*)(dB + 4) = make_float4(cvt_tf32(rb0.z), cvt_tf32(rb1.z), cvt_tf32(rb0.w), cvt_tf32(rb1.w));
        }
        __syncthreads();
    }

    const int mBase = blockIdx.y * 128 + wm * 32;
    const int nBase = blockIdx.x * 128 + wn * 64;
    #pragma unroll
    for (int mi = 0; mi < 2; mi++) {
        #pragma unroll
        for (int nj = 0; nj < 8; nj++) {
            const int col = nBase + nj * 8 + qc * 2;
            const float bx0 = bias[col], bx1 = bias[col + 1];
            const int r0 = mBase + mi * 16 + qr;
            float2 o0 = make_float2(acc[mi][nj][0] + bx0, acc[mi][nj][1] + bx1);
            float2 o1 = make_float2(acc[mi][nj][2] + bx0, acc[mi][nj][3] + bx1);
            *(float2*)(C + (size_t)r0 * N + col)       = o0;
            *(float2*)(C + (size_t)(r0 + 8) * N + col) = o1;
        }
    }
}

// ---------------------------------------------------------------------------
// Tensor-core flash attention, tf32 mma.sync.
// Grid (SEQ/128, NH, BATCH), 256 threads (8 warps, 16 query rows each).
// SMEM tiles, row stride 68 floats. Fragment LDS bank = qr*4+qc (free).
// ---------------------------------------------------------------------------
#define FB_M 128
#define FB_N 64
#define F_STR 68
#define FLASH_SMEM ((FB_M*F_STR + 64*F_STR + 64*F_STR + FB_M*F_STR) * 4)

__global__ void __launch_bounds__(256, 2) flash_tc()
{
    extern __shared__ float fsm[];
    float* sQ  = fsm;                       // 128*68
    float* sK  = sQ  + FB_M * F_STR;        // 64*68
    float* sVt = sK  + 64 * F_STR;          // 64*68
    float* sP  = sVt + 64 * F_STR;          // 128*68

    const int qt = blockIdx.x, h = blockIdx.y, b = blockIdx.z;
    const int tid  = threadIdx.x;
    const int wid  = tid >> 5;
    const int lane = tid & 31;
    const int qr   = lane >> 2;
    const int qc   = lane & 3;
    const int rb   = wid * 16;              // warp's query-row base (16 rows)

    const float* qg = g_qkv + (size_t)(b * SEQ + qt * FB_M) * E3 + h * HD;
    const float* kg = g_qkv + (size_t)(b * SEQ) * E3 + EMB     + h * HD;
    const float* vg = g_qkv + (size_t)(b * SEQ) * E3 + 2 * EMB + h * HD;

    // ---- load Q (row = tid&127, half = tid>>7), scaled by 1/8, tf32 ----
    {
        const int qrow = tid & 127;
        const int qh   = tid >> 7;          // 32-col half
        const float* src = qg + (size_t)qrow * E3 + qh * 32;
        float* dst = sQ + qrow * F_STR + qh * 32;
        #pragma unroll
        for (int p = 0; p < 8; p++) {
            float4 v = *(const float4*)(src + p * 4);
            *(float4*)(dst + p * 4) = make_float4(
                cvt_tf32(v.x * 0.125f), cvt_tf32(v.y * 0.125f),
                cvt_tf32(v.z * 0.125f), cvt_tf32(v.w * 0.125f));
        }
    }

    float o[8][4];
    float m_i[2], l_i[2];
    #pragma unroll
    for (int j = 0; j < 8; j++)
        #pragma unroll
        for (int c = 0; c < 4; c++) o[j][c] = 0.0f;
    m_i[0] = m_i[1] = -CUDART_INF_F;
    l_i[0] = l_i[1] = 0.0f;

    const int krow = tid & 63;
    const int c4b  = (tid >> 6) * 4;        // 4 float4 groups per thread

    for (int kt = 0; kt < SEQ / FB_N; kt++) {
        __syncthreads();   // prev iter's QK/PV done with sK/sVt/sP

        // ---- load K tile [64 keys][64 d] and V^T tile [64 d][64 keys] ----
        {
            const float* ksrc = kg + (size_t)(kt * 64 + krow) * E3;
            const float* vsrc = vg + (size_t)(kt * 64 + krow) * E3;
            float* kdst = sK + krow * F_STR;
            #pragma unroll
            for (int p = 0; p < 4; p++) {
                const int c4 = c4b + p;
                float4 v = *(const float4*)(ksrc + c4 * 4);
                *(float4*)(kdst + c4 * 4) = make_float4(
                    cvt_tf32(v.x), cvt_tf32(v.y), cvt_tf32(v.z), cvt_tf32(v.w));
                float4 w = *(const float4*)(vsrc + c4 * 4);
                sVt[(c4 * 4 + 0) * F_STR + krow] = cvt_tf32(w.x);
                sVt[(c4 * 4 + 1) * F_STR + krow] = cvt_tf32(w.y);
                sVt[(c4 * 4 + 2) * F_STR + krow] = cvt_tf32(w.z);
                sVt[(c4 * 4 + 3) * F_STR + krow] = cvt_tf32(w.w);
            }
        }
        __syncthreads();

        // ---- S = Q K^T (tf32 mma), per warp: m16 x n64 x k64 ----
        float s[8][4];
        #pragma unroll
        for (int j = 0; j < 8; j++)
            #pragma unroll
            for (int c = 0; c < 4; c++) s[j][c] = 0.0f;

        #pragma unroll
        for (int g = 0; g < 8; g++) {
            const float* q0 = sQ + (rb + qr) * F_STR + g * 8 + qc;
            uint32_t a0 = __float_as_uint(q0[0]);
            uint32_t a2 = __float_as_uint(q0[4]);
            uint32_t a1 = __float_as_uint(q0[8 * F_STR]);
            uint32_t a3 = __float_as_uint(q0[8 * F_STR + 4]);
            #pragma unroll
            for (int j = 0; j < 8; j++) {
                const float* kp = sK + (j * 8 + qr) * F_STR + g * 8 + qc;
                const uint32_t b0 = __float_as_uint(kp[0]);
                const uint32_t b1 = __float_as_uint(kp[4]);
                mma_tf32(s[j], a0, a1, a2, a3, b0, b1);
            }
        }

        // ---- online softmax (rows qr / qr+8) ----
        #pragma unroll
        for (int hf = 0; hf < 2; hf++) {
            float tm = -CUDART_INF_F;
            #pragma unroll
            for (int j = 0; j < 8; j++)
                tm = fmaxf(tm, fmaxf(s[j][hf * 2], s[j][hf * 2 + 1]));
            tm = fmaxf(tm, __shfl_xor_sync(0xffffffffu, tm, 1));
            tm = fmaxf(tm, __shfl_xor_sync(0xffffffffu, tm, 2));
            const float mnew  = fmaxf(m_i[hf], tm);
            const float alpha = __expf(m_i[hf] - mnew);
            float ps = 0.0f;
            #pragma unroll
            for (int j = 0; j < 8; j++) {
                float p0 = cvt_tf32(__expf(s[j][hf * 2]     - mnew));
                float p1 = cvt_tf32(__expf(s[j][hf * 2 + 1] - mnew));
                s[j][hf * 2]     = p0;
                s[j][hf * 2 + 1] = p1;
                ps += p0 + p1;
            }
            ps += __shfl_xor_sync(0xffffffffu, ps, 1);
            ps += __shfl_xor_sync(0xffffffffu, ps, 2);
            l_i[hf] = l_i[hf] * alpha + ps;
            m_i[hf] = mnew;
            #pragma unroll
            for (int j = 0; j < 8; j++) {
                o[j][hf * 2]     *= alpha;
                o[j][hf * 2 + 1] *= alpha;
            }
        }

        // ---- store P to SMEM (own 16 rows only) ----
        #pragma unroll
        for (int j = 0; j < 8; j++) {
            float* pp = sP + (rb + qr) * F_STR + j * 8 + 2 * qc;
            *(float2*)pp = make_float2(s[j][0], s[j][1]);
            *(float2*)(pp + 8 * F_STR) = make_float2(s[j][2], s[j][3]);
        }
        __syncwarp();

        // ---- O += P V (tf32 mma), contraction over keys ----
        #pragma unroll
        for (int g = 0; g < 8; g++) {
            const float* p0 = sP + (rb + qr) * F_STR + g * 8 + qc;
            uint32_t a0 = __float_as_uint(p0[0]);
            uint32_t a2 = __float_as_uint(p0[4]);
            uint32_t a1 = __float_as_uint(p0[8 * F_STR]);
            uint32_t a3 = __float_as_uint(p0[8 * F_STR + 4]);
            #pragma unroll
            for (int j = 0; j < 8; j++) {
                const float* vp = sVt + (j * 8 + qr) * F_STR + g * 8 + qc;
                const uint32_t b0 = __float_as_uint(vp[0]);
                const uint32_t b1 = __float_as_uint(vp[4]);
                mma_tf32(o[j], a0, a1, a2, a3, b0, b1);
            }
        }
    }

    // ---- epilogue: normalize, write [B,S,E] ----
    const float inv0 = 1.0f / l_i[0];
    const float inv1 = 1.0f / l_i[1];
    const size_t row0 = (size_t)(b * SEQ + qt * FB_M + rb + qr);
    #pragma unroll
    for (int j = 0; j < 8; j++) {
        const int col = h * HD + j * 8 + 2 * qc;
        *(float2*)(g_attn + row0 * EMB + col) =
            make_float2(o[j][0] * inv0, o[j][1] * inv0);
        *(float2*)(g_attn + (row0 + 8) * EMB + col) =
            make_float2(o[j][2] * inv1, o[j][3] * inv1);
    }
}

// ---------------------------------------------------------------------------
extern "C" void kernel_launch(void* const* d_in, const int* in_sizes, int n_in,
                              void* d_out, int out_size)
{
    (void)in_sizes; (void)n_in; (void)out_size;
    const float* x     = (const float*)d_in[0];
    const float* w_in  = (const float*)d_in[1];
    const float* b_in  = (const float*)d_in[2];
    const float* w_out = (const float*)d_in[3];
    const float* b_out = (const float*)d_in[4];
    float* out = (float*)d_out;

    void *qkv_p, *attn_p, *wti_p, *wto_p;
    cudaGetSymbolAddress(&qkv_p,  g_qkv);
    cudaGetSymbolAddress(&attn_p, g_attn);
    cudaGetSymbolAddress(&wti_p,  g_wti);
    cudaGetSymbolAddress(&wto_p,  g_wto);

    cudaFuncSetAttribute(flash_tc, cudaFuncAttributeMaxDynamicSharedMemorySize,
                         FLASH_SMEM);

    // 0) transpose weights to K-major [N, K]
    transpose_k<<<dim3(E3 / 32, EMB / 32), dim3(32, 8)>>>(w_in,  (float*)wti_p, EMB, E3);
    transpose_k<<<dim3(EMB / 32, EMB / 32), dim3(32, 8)>>>(w_out, (float*)wto_p, EMB, EMB);

    // 1) QKV projection (tf32 mma): [4096,1024] @ [1024,3072] + b_in
    gemm_tf32mma<<<dim3(E3 / 128, MTOT / 128), 256>>>(
        E3, EMB, x, (const float*)wti_p, b_in, (float*)qkv_p);

    // 2) Attention (tensor-core flash)
    flash_tc<<<dim3(SEQ / FB_M, NH, BATCH), 256, FLASH_SMEM>>>();

    // 3) Output projection (tf32 mma): [4096,1024] @ [1024,1024] + b_out
    gemm_tf32mma<<<dim3(EMB / 128, MTOT / 128), 256>>>(
        EMB, EMB, (const float*)attn_p, (const float*)wto_p, b_out, out);
}

// round 6
// speedup vs baseline: 2.3641x; 1.2221x over previous
#include <cuda_runtime.h>
#include <cuda_bf16.h>
#include <math_constants.h>
#include <cstdint>

// Problem constants
#define BATCH 2
#define SEQ   2048
#define EMB   1024
#define E3    3072
#define NH    16
#define HD    64
#define MTOT  (BATCH*SEQ)   // 4096

// Scratch (static device globals — no cudaMalloc allowed)
__device__ float g_qkv [(size_t)MTOT * E3];   // [4096, 3072]
__device__ float g_attn[(size_t)MTOT * EMB];  // [4096, 1024]
__device__ float g_wti [(size_t)E3 * EMB];    // w_in^T  [3072, 1024]
__device__ float g_wto [(size_t)EMB * EMB];   // w_out^T [1024, 1024]

// ---------------------------------------------------------------------------
__device__ __forceinline__ float cvt_tf32(float x) {
    uint32_t u;
    asm("cvt.rna.tf32.f32 %0, %1;" : "=r"(u) : "f"(x));
    return __uint_as_float(u);
}

__device__ __forceinline__ void mma_tf32(float c[4], uint32_t a0, uint32_t a1,
                                         uint32_t a2, uint32_t a3,
                                         uint32_t b0, uint32_t b1) {
    asm volatile(
        "mma.sync.aligned.m16n8k8.row.col.f32.tf32.tf32.f32 "
        "{%0,%1,%2,%3}, {%4,%5,%6,%7}, {%8,%9}, {%0,%1,%2,%3};"
        : "+f"(c[0]), "+f"(c[1]), "+f"(c[2]), "+f"(c[3])
        : "r"(a0), "r"(a1), "r"(a2), "r"(a3), "r"(b0), "r"(b1));
}

__device__ __forceinline__ uint32_t smem_u32(const void* p) {
    uint32_t a;
    asm("{ .reg .u64 t; cvta.to.shared.u64 t, %1; cvt.u32.u64 %0, t; }" : "=r"(a) : "l"(p));
    return a;
}
__device__ __forceinline__ void cp16(uint32_t saddr, const void* gaddr) {
    asm volatile("cp.async.cg.shared.global [%0], [%1], 16;" :: "r"(saddr), "l"(gaddr));
}
#define CP_COMMIT() asm volatile("cp.async.commit_group;" ::: "memory")
#define CP_WAIT(n)  asm volatile("cp.async.wait_group %0;" :: "n"(n) : "memory")

// mean truncation-bias compensation for raw-fp32 tf32 operands (RZ truncate)
#define TF32_COMP 1.00034f

// ---------------------------------------------------------------------------
// Transpose: out[C,R] = in[R,C]^T  (R, C multiples of 32). block (32,8).
// ---------------------------------------------------------------------------
__global__ void __launch_bounds__(256) transpose_k(
    const float* __restrict__ in, float* __restrict__ out, int R, int C)
{
    __shared__ float t[32][33];
    const int bx = blockIdx.x * 32;
    const int by = blockIdx.y * 32;
    const int x = bx + threadIdx.x;
    #pragma unroll
    for (int j = 0; j < 4; j++) {
        const int y = by + threadIdx.y + j * 8;
        t[threadIdx.y + j * 8][threadIdx.x] = in[(size_t)y * C + x];
    }
    __syncthreads();
    const int x2 = by + threadIdx.x;
    #pragma unroll
    for (int j = 0; j < 4; j++) {
        const int y2 = bx + threadIdx.y + j * 8;
        out[(size_t)y2 * R + x2] = t[threadIdx.x][threadIdx.y + j * 8];
    }
}

// ---------------------------------------------------------------------------
// tf32 mma.sync GEMM + bias (unchanged from R5, passing)
// ---------------------------------------------------------------------------
__global__ void __launch_bounds__(256, 2) gemm_tf32mma(
    int N, int K,
    const float* __restrict__ A,
    const float* __restrict__ Bt,
    const float* __restrict__ bias,
    float* __restrict__ C)
{
    __shared__ __align__(16) float sA[2][128 * 24];
    __shared__ __align__(16) float sB[2][128 * 24];

    const int tid  = threadIdx.x;
    const int wid  = tid >> 5;
    const int lane = tid & 31;
    const int wm   = wid >> 1;
    const int wn   = wid & 1;
    const int qr   = lane >> 2;
    const int qc   = lane & 3;

    const int row = tid & 127;
    const int kg  = tid >> 7;

    const float* Arow = A  + (size_t)(blockIdx.y * 128 + row) * K + kg * 8;
    const float* Brow = Bt + (size_t)(blockIdx.x * 128 + row) * K + kg * 8;

    const int stBase = row * 24 + ((row >> 2) & 1) * 4 + kg * 8;
    const int ldBase = qr * 24 + ((qr >> 2) & 1) * 4 + qc * 2;

    float acc[2][8][4];
    #pragma unroll
    for (int i = 0; i < 2; i++)
        #pragma unroll
        for (int j = 0; j < 8; j++)
            #pragma unroll
            for (int c = 0; c < 4; c++) acc[i][j][c] = 0.0f;

    const int KT = K / 16;
    float4 ra0, ra1, rb0, rb1;

    ra0 = *(const float4*)(Arow);     ra1 = *(const float4*)(Arow + 4);
    rb0 = *(const float4*)(Brow);     rb1 = *(const float4*)(Brow + 4);
    {
        float* dA = &sA[0][stBase];
        float* dB = &sB[0][stBase];
        *(float4*)(dA)     = make_float4(cvt_tf32(ra0.x), cvt_tf32(ra1.x), cvt_tf32(ra0.y), cvt_tf32(ra1.y));
        *(float4*)(dA + 4) = make_float4(cvt_tf32(ra0.z), cvt_tf32(ra1.z), cvt_tf32(ra0.w), cvt_tf32(ra1.w));
        *(float4*)(dB)     = make_float4(cvt_tf32(rb0.x), cvt_tf32(rb1.x), cvt_tf32(rb0.y), cvt_tf32(rb1.y));
        *(float4*)(dB + 4) = make_float4(cvt_tf32(rb0.z), cvt_tf32(rb1.z), cvt_tf32(rb0.w), cvt_tf32(rb1.w));
    }
    __syncthreads();

    for (int t = 0; t < KT; t++) {
        const int buf = t & 1;
        if (t + 1 < KT) {
            const int k0 = (t + 1) * 16;
            ra0 = *(const float4*)(Arow + k0);     ra1 = *(const float4*)(Arow + k0 + 4);
            rb0 = *(const float4*)(Brow + k0);     rb1 = *(const float4*)(Brow + k0 + 4);
        }

        #pragma unroll
        for (int g = 0; g < 2; g++) {
            const float* pA = &sA[buf][wm * 768 + g * 8 + ldBase];
            const float* pB = &sB[buf][wn * 1536 + g * 8 + ldBase];

            uint32_t afr[2][4];
            #pragma unroll
            for (int mi = 0; mi < 2; mi++) {
                const float2 lo = *(const float2*)(pA + mi * 384);
                const float2 hi = *(const float2*)(pA + mi * 384 + 192);
                afr[mi][0] = __float_as_uint(lo.x);
                afr[mi][2] = __float_as_uint(lo.y);
                afr[mi][1] = __float_as_uint(hi.x);
                afr[mi][3] = __float_as_uint(hi.y);
            }
            uint32_t bfr[8][2];
            #pragma unroll
            for (int nj = 0; nj < 8; nj++) {
                const float2 bb = *(const float2*)(pB + nj * 192);
                bfr[nj][0] = __float_as_uint(bb.x);
                bfr[nj][1] = __float_as_uint(bb.y);
            }
            #pragma unroll
            for (int mi = 0; mi < 2; mi++)
                #pragma unroll
                for (int nj = 0; nj < 8; nj++)
                    mma_tf32(acc[mi][nj], afr[mi][0], afr[mi][1], afr[mi][2],
                             afr[mi][3], bfr[nj][0], bfr[nj][1]);
        }

        if (t + 1 < KT) {
            const int nb = buf ^ 1;
            float* dA = &sA[nb][stBase];
            float* dB = &sB[nb][stBase];
            *(float4*)(dA)     = make_float4(cvt_tf32(ra0.x), cvt_tf32(ra1.x), cvt_tf32(ra0.y), cvt_tf32(ra1.y));
            *(float4*)(dA + 4) = make_float4(cvt_tf32(ra0.z), cvt_tf32(ra1.z), cvt_tf32(ra0.w), cvt_tf32(ra1.w));
            *(float4*)(dB)     = make_float4(cvt_tf32(rb0.x), cvt_tf32(rb1.x), cvt_tf32(rb0.y), cvt_tf32(rb1.y));
            *(float4*)(dB + 4) = make_float4(cvt_tf32(rb0.z), cvt_tf32(rb1.z), cvt_tf32(rb0.w), cvt_tf32(rb1.w));
        }
        __syncthreads();
    }

    const int mBase = blockIdx.y * 128 + wm * 32;
    const int nBase = blockIdx.x * 128 + wn * 64;
    #pragma unroll
    for (int mi = 0; mi < 2; mi++) {
        #pragma unroll
        for (int nj = 0; nj < 8; nj++) {
            const int col = nBase + nj * 8 + qc * 2;
            const float bx0 = bias[col], bx1 = bias[col + 1];
            const int r0 = mBase + mi * 16 + qr;
            float2 o0 = make_float2(acc[mi][nj][0] + bx0, acc[mi][nj][1] + bx1);
            float2 o1 = make_float2(acc[mi][nj][2] + bx0, acc[mi][nj][3] + bx1);
            *(float2*)(C + (size_t)r0 * N + col)       = o0;
            *(float2*)(C + (size_t)(r0 + 8) * N + col) = o1;
        }
    }
}

// ---------------------------------------------------------------------------
// Flash attention v3: tf32 mma, FB_M=256, 8 warps x m32, cp.async K/V
// double-buffer (natural layout, raw fp32 -> HW tf32 truncation, bias
// compensated), P via register shuffles (no sP smem).
// SMEM (floats): sQ 256*72 | sK0 | sK1 | sV0 | sV1 (each 64*72) = 144KB.
// ---------------------------------------------------------------------------
#define FB_M   256
#define F_STR  72
#define QSZ    (FB_M * F_STR)        // 18432 floats
#define KVSZ   (64 * F_STR)          // 4608 floats
#define FLASH_SMEM ((QSZ + 4 * KVSZ) * 4)
#define NT     (SEQ / 64)            // 32

__global__ void __launch_bounds__(256, 1) flash_tc3()
{
    extern __shared__ float fsm[];
    const uint32_t sb = smem_u32(fsm);

    const int qt = blockIdx.x, h = blockIdx.y, bz = blockIdx.z;
    const int tid  = threadIdx.x;
    const int wid  = tid >> 5;
    const int lane = tid & 31;
    const int qr   = lane >> 2;
    const int qc   = lane & 3;
    const int rb   = wid * 32;               // warp's 32 query rows
    const int rotq = ((qr >> 2) & 1) * 4;    // row-rotation for qr in [0,8)
    const bool odd = qc & 1;
    const int srcA = (lane & ~3) | (qc >> 1);
    const int srcB = srcA + 2;

    const float* qg = g_qkv + (size_t)(bz * SEQ + qt * FB_M) * E3 + h * HD;
    const float* kg = g_qkv + (size_t)(bz * SEQ) * E3 + EMB     + h * HD;
    const float* vg = g_qkv + (size_t)(bz * SEQ) * E3 + 2 * EMB + h * HD;

    // cp.async coordinates: thread covers 16 floats of one K row + one V row
    const int krow = tid & 63;
    const int kq   = tid >> 6;                // quarter-row 0..3
    const uint32_t soffKV = (uint32_t)(krow * F_STR + ((krow >> 2) & 1) * 4 + kq * 16) * 4;
    const uint32_t sK0 = sb + QSZ * 4;
    const uint32_t sV0 = sb + (QSZ + 2 * KVSZ) * 4;

    // ---- issue group 0 (K/V tile 0) ----
    {
        const float* ks = kg + (size_t)krow * E3 + kq * 16;
        const float* vs = vg + (size_t)krow * E3 + kq * 16;
        #pragma unroll
        for (int c = 0; c < 4; c++) {
            cp16(sK0 + soffKV + c * 16, ks + c * 4);
            cp16(sV0 + soffKV + c * 16, vs + c * 4);
        }
        CP_COMMIT();
    }

    // ---- load Q (row = tid): scale, cvt.rna, k-permuted + rotated store ----
    {
        const float qscale = 0.125f * TF32_COMP;   // K-side truncation comp
        const float* src = qg + (size_t)tid * E3;
        float* dst = fsm + tid * F_STR + ((tid >> 2) & 1) * 4;
        #pragma unroll
        for (int gq = 0; gq < 8; gq++) {
            float4 f0 = *(const float4*)(src + gq * 8);
            float4 f1 = *(const float4*)(src + gq * 8 + 4);
            *(float4*)(dst + gq * 8) = make_float4(
                cvt_tf32(f0.x * qscale), cvt_tf32(f1.x * qscale),
                cvt_tf32(f0.y * qscale), cvt_tf32(f1.y * qscale));
            *(float4*)(dst + gq * 8 + 4) = make_float4(
                cvt_tf32(f0.z * qscale), cvt_tf32(f1.z * qscale),
                cvt_tf32(f0.w * qscale), cvt_tf32(f1.w * qscale));
        }
    }

    float o[2][8][4];
    float m_i[4], l_i[4];
    #pragma unroll
    for (int mt = 0; mt < 2; mt++)
        #pragma unroll
        for (int j = 0; j < 8; j++)
            #pragma unroll
            for (int c = 0; c < 4; c++) o[mt][j][c] = 0.0f;
    #pragma unroll
    for (int i = 0; i < 4; i++) { m_i[i] = -CUDART_INF_F; l_i[i] = 0.0f; }

    // per-warp fragment base offsets (floats)
    const int qb0 = (rb + qr) * F_STR + rotq + 2 * qc;        // mt=0
    const int qb1 = (rb + 16 + qr) * F_STR + rotq + 2 * qc;   // mt=1

    for (int t = 0; t < NT; t++) {
        const int buf = t & 1;
        // issue next K/V group into the other buffer (free since iter t-1)
        if (t + 1 < NT) {
            const int nb = (t + 1) & 1;
            const float* ks = kg + (size_t)((t + 1) * 64 + krow) * E3 + kq * 16;
            const float* vs = vg + (size_t)((t + 1) * 64 + krow) * E3 + kq * 16;
            const uint32_t dK = sK0 + nb * (KVSZ * 4) + soffKV;
            const uint32_t dV = sV0 + nb * (KVSZ * 4) + soffKV;
            #pragma unroll
            for (int c = 0; c < 4; c++) {
                cp16(dK + c * 16, ks + c * 4);
                cp16(dV + c * 16, vs + c * 4);
            }
            CP_COMMIT();
            CP_WAIT(1);
        } else {
            CP_WAIT(0);
        }
        __syncthreads();   // tile t visible to all; prev buffers free

        const float* kb = fsm + QSZ + buf * KVSZ;
        const float* vb = fsm + QSZ + 2 * KVSZ + buf * KVSZ;

        // ---- S = Q K^T : per warp m32 x n64 x k64 ----
        float s[2][8][4];
        #pragma unroll
        for (int mt = 0; mt < 2; mt++)
            #pragma unroll
            for (int j = 0; j < 8; j++)
                #pragma unroll
                for (int c = 0; c < 4; c++) s[mt][j][c] = 0.0f;

        #pragma unroll
        for (int g = 0; g < 8; g++) {
            uint32_t a[2][4];
            {
                const float2 lo0 = *(const float2*)(fsm + qb0 + g * 8);
                const float2 hi0 = *(const float2*)(fsm + qb0 + 8 * F_STR + g * 8);
                a[0][0] = __float_as_uint(lo0.x); a[0][2] = __float_as_uint(lo0.y);
                a[0][1] = __float_as_uint(hi0.x); a[0][3] = __float_as_uint(hi0.y);
                const float2 lo1 = *(const float2*)(fsm + qb1 + g * 8);
                const float2 hi1 = *(const float2*)(fsm + qb1 + 8 * F_STR + g * 8);
                a[1][0] = __float_as_uint(lo1.x); a[1][2] = __float_as_uint(lo1.y);
                a[1][1] = __float_as_uint(hi1.x); a[1][3] = __float_as_uint(hi1.y);
            }
            #pragma unroll
            for (int j = 0; j < 8; j++) {
                const float* kp = kb + (j * 8 + qr) * F_STR + rotq + g * 8 + qc;
                const uint32_t b0 = __float_as_uint(kp[0]);
                const uint32_t b1 = __float_as_uint(kp[4]);
                mma_tf32(s[0][j], a[0][0], a[0][1], a[0][2], a[0][3], b0, b1);
                mma_tf32(s[1][j], a[1][0], a[1][1], a[1][2], a[1][3], b0, b1);
            }
        }

        // ---- online softmax (4 row groups: mt x hf) ----
        #pragma unroll
        for (int mt = 0; mt < 2; mt++) {
            #pragma unroll
            for (int hf = 0; hf < 2; hf++) {
                const int mi = mt * 2 + hf;
                float tm = -CUDART_INF_F;
                #pragma unroll
                for (int j = 0; j < 8; j++)
                    tm = fmaxf(tm, fmaxf(s[mt][j][hf * 2], s[mt][j][hf * 2 + 1]));
                tm = fmaxf(tm, __shfl_xor_sync(0xffffffffu, tm, 1));
                tm = fmaxf(tm, __shfl_xor_sync(0xffffffffu, tm, 2));
                const float mnew  = fmaxf(m_i[mi], tm);
                const float alpha = __expf(m_i[mi] - mnew);
                float ps = 0.0f;
                #pragma unroll
                for (int j = 0; j < 8; j++) {
                    float p0 = cvt_tf32(__expf(s[mt][j][hf * 2]     - mnew));
                    float p1 = cvt_tf32(__expf(s[mt][j][hf * 2 + 1] - mnew));
                    s[mt][j][hf * 2]     = p0;
                    s[mt][j][hf * 2 + 1] = p1;
                    ps += p0 + p1;
                }
                ps += __shfl_xor_sync(0xffffffffu, ps, 1);
                ps += __shfl_xor_sync(0xffffffffu, ps, 2);
                l_i[mi] = l_i[mi] * alpha + ps;
                m_i[mi] = mnew;
                #pragma unroll
                for (int j = 0; j < 8; j++) {
                    o[mt][j][hf * 2]     *= alpha;
                    o[mt][j][hf * 2 + 1] *= alpha;
                }
            }
        }

        // ---- O += P V : A fragments from accumulators via shuffles ----
        #pragma unroll
        for (int g = 0; g < 8; g++) {
            uint32_t a[2][4];
            #pragma unroll
            for (int mt = 0; mt < 2; mt++) {
                const float x0 = __shfl_sync(0xffffffffu, s[mt][g][0], srcA);
                const float x1 = __shfl_sync(0xffffffffu, s[mt][g][1], srcA);
                const float y0 = __shfl_sync(0xffffffffu, s[mt][g][2], srcA);
                const float y1 = __shfl_sync(0xffffffffu, s[mt][g][3], srcA);
                const float w0 = __shfl_sync(0xffffffffu, s[mt][g][0], srcB);
                const float w1 = __shfl_sync(0xffffffffu, s[mt][g][1], srcB);
                const float u0 = __shfl_sync(0xffffffffu, s[mt][g][2], srcB);
                const float u1 = __shfl_sync(0xffffffffu, s[mt][g][3], srcB);
                a[mt][0] = __float_as_uint(odd ? x1 : x0);
                a[mt][1] = __float_as_uint(odd ? y1 : y0);
                a[mt][2] = __float_as_uint(odd ? w1 : w0);
                a[mt][3] = __float_as_uint(odd ? u1 : u0);
            }
            const float* v0 = vb + (g * 8 + qc) * F_STR;          // rot = 0
            const float* v1 = vb + (g * 8 + qc + 4) * F_STR + 4;  // rot = 4
            #pragma unroll
            for (int j = 0; j < 8; j++) {
                const uint32_t b0 = __float_as_uint(v0[j * 8 + qr]);
                const uint32_t b1 = __float_as_uint(v1[j * 8 + qr]);
                mma_tf32(o[0][j], a[0][0], a[0][1], a[0][2], a[0][3], b0, b1);
                mma_tf32(o[1][j], a[1][0], a[1][1], a[1][2], a[1][3], b0, b1);
            }
        }
        __syncthreads();   // done reading buf before it is refilled
    }

    // ---- epilogue: normalize (with V truncation comp), write [B,S,E] ----
    #pragma unroll
    for (int mt = 0; mt < 2; mt++) {
        const float inv0 = TF32_COMP / l_i[mt * 2];
        const float inv1 = TF32_COMP / l_i[mt * 2 + 1];
        const size_t row0 = (size_t)(bz * SEQ + qt * FB_M + rb + mt * 16 + qr);
        #pragma unroll
        for (int j = 0; j < 8; j++) {
            const int col = h * HD + j * 8 + 2 * qc;
            *(float2*)(g_attn + row0 * EMB + col) =
                make_float2(o[mt][j][0] * inv0, o[mt][j][1] * inv0);
            *(float2*)(g_attn + (row0 + 8) * EMB + col) =
                make_float2(o[mt][j][2] * inv1, o[mt][j][3] * inv1);
        }
    }
}

// ---------------------------------------------------------------------------
extern "C" void kernel_launch(void* const* d_in, const int* in_sizes, int n_in,
                              void* d_out, int out_size)
{
    (void)in_sizes; (void)n_in; (void)out_size;
    const float* x     = (const float*)d_in[0];
    const float* w_in  = (const float*)d_in[1];
    const float* b_in  = (const float*)d_in[2];
    const float* w_out = (const float*)d_in[3];
    const float* b_out = (const float*)d_in[4];
    float* out = (float*)d_out;

    void *qkv_p, *attn_p, *wti_p, *wto_p;
    cudaGetSymbolAddress(&qkv_p,  g_qkv);
    cudaGetSymbolAddress(&attn_p, g_attn);
    cudaGetSymbolAddress(&wti_p,  g_wti);
    cudaGetSymbolAddress(&wto_p,  g_wto);

    cudaFuncSetAttribute(flash_tc3, cudaFuncAttributeMaxDynamicSharedMemorySize,
                         FLASH_SMEM);

    // 0) transpose weights to K-major [N, K]
    transpose_k<<<dim3(E3 / 32, EMB / 32), dim3(32, 8)>>>(w_in,  (float*)wti_p, EMB, E3);
    transpose_k<<<dim3(EMB / 32, EMB / 32), dim3(32, 8)>>>(w_out, (float*)wto_p, EMB, EMB);

    // 1) QKV projection (tf32 mma): [4096,1024] @ [1024,3072] + b_in
    gemm_tf32mma<<<dim3(E3 / 128, MTOT / 128), 256>>>(
        E3, EMB, x, (const float*)wti_p, b_in, (float*)qkv_p);

    // 2) Attention (tensor-core flash v3)
    flash_tc3<<<dim3(SEQ / FB_M, NH, BATCH), 256, FLASH_SMEM>>>();

    // 3) Output projection (tf32 mma): [4096,1024] @ [1024,1024] + b_out
    gemm_tf32mma<<<dim3(EMB / 128, MTOT / 128), 256>>>(
        EMB, EMB, (const float*)attn_p, (const float*)wto_p, b_out, out);
}

// round 7
// speedup vs baseline: 2.3945x; 1.0129x over previous
#include <cuda_runtime.h>
#include <cuda_bf16.h>
#include <math_constants.h>
#include <cstdint>

// Problem constants
#define BATCH 2
#define SEQ   2048
#define EMB   1024
#define E3    3072
#define NH    16
#define HD    64
#define MTOT  (BATCH*SEQ)   // 4096

// Scratch (static device globals — no cudaMalloc allowed)
__device__ float g_qkv [(size_t)MTOT * E3];   // [4096, 3072]
__device__ float g_attn[(size_t)MTOT * EMB];  // [4096, 1024]
__device__ float g_wti [(size_t)E3 * EMB];    // w_in^T  [3072, 1024]
__device__ float g_wto [(size_t)EMB * EMB];   // w_out^T [1024, 1024]

// ---------------------------------------------------------------------------
__device__ __forceinline__ float cvt_tf32(float x) {
    uint32_t u;
    asm("cvt.rna.tf32.f32 %0, %1;" : "=r"(u) : "f"(x));
    return __uint_as_float(u);
}

__device__ __forceinline__ void mma_tf32(float c[4], uint32_t a0, uint32_t a1,
                                         uint32_t a2, uint32_t a3,
                                         uint32_t b0, uint32_t b1) {
    asm volatile(
        "mma.sync.aligned.m16n8k8.row.col.f32.tf32.tf32.f32 "
        "{%0,%1,%2,%3}, {%4,%5,%6,%7}, {%8,%9}, {%0,%1,%2,%3};"
        : "+f"(c[0]), "+f"(c[1]), "+f"(c[2]), "+f"(c[3])
        : "r"(a0), "r"(a1), "r"(a2), "r"(a3), "r"(b0), "r"(b1));
}

__device__ __forceinline__ uint32_t smem_u32(const void* p) {
    uint32_t a;
    asm("{ .reg .u64 t; cvta.to.shared.u64 t, %1; cvt.u32.u64 %0, t; }" : "=r"(a) : "l"(p));
    return a;
}
__device__ __forceinline__ void cp16(uint32_t saddr, const void* gaddr) {
    asm volatile("cp.async.cg.shared.global [%0], [%1], 16;" :: "r"(saddr), "l"(gaddr));
}
#define CP_COMMIT() asm volatile("cp.async.commit_group;" ::: "memory")
#define CP_WAIT(n)  asm volatile("cp.async.wait_group %0;" :: "n"(n) : "memory")

// mean truncation-bias compensation for raw-fp32 tf32 operands (RZ truncate)
#define TF32_COMP  1.00034f
#define TF32_COMP2 1.00068f

// ---------------------------------------------------------------------------
// Transpose: out[C,R] = in[R,C]^T  (R, C multiples of 32). block (32,8).
// ---------------------------------------------------------------------------
__global__ void __launch_bounds__(256) transpose_k(
    const float* __restrict__ in, float* __restrict__ out, int R, int C)
{
    __shared__ float t[32][33];
    const int bx = blockIdx.x * 32;
    const int by = blockIdx.y * 32;
    const int x = bx + threadIdx.x;
    #pragma unroll
    for (int j = 0; j < 4; j++) {
        const int y = by + threadIdx.y + j * 8;
        t[threadIdx.y + j * 8][threadIdx.x] = in[(size_t)y * C + x];
    }
    __syncthreads();
    const int x2 = by + threadIdx.x;
    #pragma unroll
    for (int j = 0; j < 4; j++) {
        const int y2 = bx + threadIdx.y + j * 8;
        out[(size_t)y2 * R + x2] = t[threadIdx.x][threadIdx.y + j * 8];
    }
}

// ---------------------------------------------------------------------------
// tf32 mma GEMM v2: C[M,N] = A[M,K] @ Bt[N,K]^T + bias[N]
// CTA 128x128, 8 warps (4x2), warp tile 32x64, BK=32, cp.async double buffer,
// raw-fp32 operands (HW tf32 truncation; compensated in epilogue).
// SMEM: natural k layout, row stride 40 floats + bit2-row rotation —
// cp.async stores and all fragment LDS.32 phases verified conflict-free.
// ---------------------------------------------------------------------------
#define GS     40
#define GTILE  (128 * GS)                 // 5120 floats per tile buffer
#define GEMM_SMEM (4 * GTILE * 4)         // sA[2] + sB[2] = 81920 bytes

__global__ void __launch_bounds__(256, 2) gemm_tf32cp(
    int N, int K,
    const float* __restrict__ A,
    const float* __restrict__ Bt,
    const float* __restrict__ bias,
    float* __restrict__ C)
{
    extern __shared__ float gsm[];
    float* sA = gsm;                       // [2][GTILE]
    float* sB = gsm + 2 * GTILE;           // [2][GTILE]
    const uint32_t sbA = smem_u32(sA);
    const uint32_t sbB = smem_u32(sB);

    const int tid  = threadIdx.x;
    const int wid  = tid >> 5;
    const int lane = tid & 31;
    const int wm   = wid >> 1;             // 0..3 : 32-row slice
    const int wn   = wid & 1;              // 0..1 : 64-col slice
    const int qr   = lane >> 2;
    const int qc   = lane & 3;
    const int rot  = ((qr >> 2) & 1) * 4;

    // cp.async mapping: thread owns 16 floats of one A row + one B row
    const int row  = tid & 127;
    const int half = tid >> 7;
    const uint32_t soff =
        (uint32_t)(row * GS + ((row >> 2) & 1) * 4 + half * 16) * 4;
    const float* Ag = A  + (size_t)(blockIdx.y * 128 + row) * K + half * 16;
    const float* Bg = Bt + (size_t)(blockIdx.x * 128 + row) * K + half * 16;

    float acc[2][8][4];
    #pragma unroll
    for (int i = 0; i < 2; i++)
        #pragma unroll
        for (int j = 0; j < 8; j++)
            #pragma unroll
            for (int c = 0; c < 4; c++) acc[i][j][c] = 0.0f;

    // prologue: issue tile 0
    #pragma unroll
    for (int c = 0; c < 4; c++) {
        cp16(sbA + soff + c * 16, Ag + c * 4);
        cp16(sbB + soff + c * 16, Bg + c * 4);
    }
    CP_COMMIT();

    const int KT = K / 32;
    // per-warp fragment bases (float offsets inside a tile buffer)
    const int aBase = (wm * 32 + qr) * GS + rot + qc;
    const int bBase = (wn * 64 + qr) * GS + rot + qc;

    for (int t = 0; t < KT; t++) {
        const int buf = t & 1;
        if (t + 1 < KT) {
            const int nb = (t + 1) & 1;
            const uint32_t dA = sbA + (uint32_t)nb * GTILE * 4 + soff;
            const uint32_t dB = sbB + (uint32_t)nb * GTILE * 4 + soff;
            const float* ap = Ag + (t + 1) * 32;
            const float* bp = Bg + (t + 1) * 32;
            #pragma unroll
            for (int c = 0; c < 4; c++) {
                cp16(dA + c * 16, ap + c * 4);
                cp16(dB + c * 16, bp + c * 4);
            }
            CP_COMMIT();
            CP_WAIT(1);
        } else {
            CP_WAIT(0);
        }
        __syncthreads();

        const float* pa = sA + buf * GTILE + aBase;
        const float* pb = sB + buf * GTILE + bBase;

        #pragma unroll
        for (int g = 0; g < 4; g++) {
            uint32_t af[2][4];
            #pragma unroll
            for (int mt = 0; mt < 2; mt++) {
                const float* p = pa + mt * 16 * GS + g * 8;
                af[mt][0] = __float_as_uint(p[0]);
                af[mt][2] = __float_as_uint(p[4]);
                af[mt][1] = __float_as_uint(p[8 * GS]);
                af[mt][3] = __float_as_uint(p[8 * GS + 4]);
            }
            #pragma unroll
            for (int j = 0; j < 8; j++) {
                const float* p = pb + j * 8 * GS + g * 8;
                const uint32_t b0 = __float_as_uint(p[0]);
                const uint32_t b1 = __float_as_uint(p[4]);
                mma_tf32(acc[0][j], af[0][0], af[0][1], af[0][2], af[0][3], b0, b1);
                mma_tf32(acc[1][j], af[1][0], af[1][1], af[1][2], af[1][3], b0, b1);
            }
        }
        __syncthreads();
    }

    // epilogue: compensate truncation bias, add bias, store
    const int mBase = blockIdx.y * 128 + wm * 32;
    const int nBase = blockIdx.x * 128 + wn * 64;
    #pragma unroll
    for (int mi = 0; mi < 2; mi++) {
        #pragma unroll
        for (int nj = 0; nj < 8; nj++) {
            const int col = nBase + nj * 8 + qc * 2;
            const float bx0 = bias[col], bx1 = bias[col + 1];
            const int r0 = mBase + mi * 16 + qr;
            float2 o0 = make_float2(fmaf(acc[mi][nj][0], TF32_COMP2, bx0),
                                    fmaf(acc[mi][nj][1], TF32_COMP2, bx1));
            float2 o1 = make_float2(fmaf(acc[mi][nj][2], TF32_COMP2, bx0),
                                    fmaf(acc[mi][nj][3], TF32_COMP2, bx1));
            *(float2*)(C + (size_t)r0 * N + col)       = o0;
            *(float2*)(C + (size_t)(r0 + 8) * N + col) = o1;
        }
    }
}

// ---------------------------------------------------------------------------
// Flash attention v3 (unchanged from R6, passing at 308us)
// ---------------------------------------------------------------------------
#define FB_M   256
#define F_STR  72
#define QSZ    (FB_M * F_STR)
#define KVSZ   (64 * F_STR)
#define FLASH_SMEM ((QSZ + 4 * KVSZ) * 4)
#define NT     (SEQ / 64)

__global__ void __launch_bounds__(256, 1) flash_tc3()
{
    extern __shared__ float fsm[];
    const uint32_t sb = smem_u32(fsm);

    const int qt = blockIdx.x, h = blockIdx.y, bz = blockIdx.z;
    const int tid  = threadIdx.x;
    const int wid  = tid >> 5;
    const int lane = tid & 31;
    const int qr   = lane >> 2;
    const int qc   = lane & 3;
    const int rb   = wid * 32;
    const int rotq = ((qr >> 2) & 1) * 4;
    const bool odd = qc & 1;
    const int srcA = (lane & ~3) | (qc >> 1);
    const int srcB = srcA + 2;

    const float* qg = g_qkv + (size_t)(bz * SEQ + qt * FB_M) * E3 + h * HD;
    const float* kg = g_qkv + (size_t)(bz * SEQ) * E3 + EMB     + h * HD;
    const float* vg = g_qkv + (size_t)(bz * SEQ) * E3 + 2 * EMB + h * HD;

    const int krow = tid & 63;
    const int kq   = tid >> 6;
    const uint32_t soffKV = (uint32_t)(krow * F_STR + ((krow >> 2) & 1) * 4 + kq * 16) * 4;
    const uint32_t sK0 = sb + QSZ * 4;
    const uint32_t sV0 = sb + (QSZ + 2 * KVSZ) * 4;

    {
        const float* ks = kg + (size_t)krow * E3 + kq * 16;
        const float* vs = vg + (size_t)krow * E3 + kq * 16;
        #pragma unroll
        for (int c = 0; c < 4; c++) {
            cp16(sK0 + soffKV + c * 16, ks + c * 4);
            cp16(sV0 + soffKV + c * 16, vs + c * 4);
        }
        CP_COMMIT();
    }

    {
        const float qscale = 0.125f * TF32_COMP;
        const float* src = qg + (size_t)tid * E3;
        float* dst = fsm + tid * F_STR + ((tid >> 2) & 1) * 4;
        #pragma unroll
        for (int gq = 0; gq < 8; gq++) {
            float4 f0 = *(const float4*)(src + gq * 8);
            float4 f1 = *(const float4*)(src + gq * 8 + 4);
            *(float4*)(dst + gq * 8) = make_float4(
                cvt_tf32(f0.x * qscale), cvt_tf32(f1.x * qscale),
                cvt_tf32(f0.y * qscale), cvt_tf32(f1.y * qscale));
            *(float4*)(dst + gq * 8 + 4) = make_float4(
                cvt_tf32(f0.z * qscale), cvt_tf32(f1.z * qscale),
                cvt_tf32(f0.w * qscale), cvt_tf32(f1.w * qscale));
        }
    }

    float o[2][8][4];
    float m_i[4], l_i[4];
    #pragma unroll
    for (int mt = 0; mt < 2; mt++)
        #pragma unroll
        for (int j = 0; j < 8; j++)
            #pragma unroll
            for (int c = 0; c < 4; c++) o[mt][j][c] = 0.0f;
    #pragma unroll
    for (int i = 0; i < 4; i++) { m_i[i] = -CUDART_INF_F; l_i[i] = 0.0f; }

    const int qb0 = (rb + qr) * F_STR + rotq + 2 * qc;
    const int qb1 = (rb + 16 + qr) * F_STR + rotq + 2 * qc;

    for (int t = 0; t < NT; t++) {
        const int buf = t & 1;
        if (t + 1 < NT) {
            const int nb = (t + 1) & 1;
            const float* ks = kg + (size_t)((t + 1) * 64 + krow) * E3 + kq * 16;
            const float* vs = vg + (size_t)((t + 1) * 64 + krow) * E3 + kq * 16;
            const uint32_t dK = sK0 + nb * (KVSZ * 4) + soffKV;
            const uint32_t dV = sV0 + nb * (KVSZ * 4) + soffKV;
            #pragma unroll
            for (int c = 0; c < 4; c++) {
                cp16(dK + c * 16, ks + c * 4);
                cp16(dV + c * 16, vs + c * 4);
            }
            CP_COMMIT();
            CP_WAIT(1);
        } else {
            CP_WAIT(0);
        }
        __syncthreads();

        const float* kb = fsm + QSZ + buf * KVSZ;
        const float* vb = fsm + QSZ + 2 * KVSZ + buf * KVSZ;

        float s[2][8][4];
        #pragma unroll
        for (int mt = 0; mt < 2; mt++)
            #pragma unroll
            for (int j = 0; j < 8; j++)
                #pragma unroll
                for (int c = 0; c < 4; c++) s[mt][j][c] = 0.0f;

        #pragma unroll
        for (int g = 0; g < 8; g++) {
            uint32_t a[2][4];
            {
                const float2 lo0 = *(const float2*)(fsm + qb0 + g * 8);
                const float2 hi0 = *(const float2*)(fsm + qb0 + 8 * F_STR + g * 8);
                a[0][0] = __float_as_uint(lo0.x); a[0][2] = __float_as_uint(lo0.y);
                a[0][1] = __float_as_uint(hi0.x); a[0][3] = __float_as_uint(hi0.y);
                const float2 lo1 = *(const float2*)(fsm + qb1 + g * 8);
                const float2 hi1 = *(const float2*)(fsm + qb1 + 8 * F_STR + g * 8);
                a[1][0] = __float_as_uint(lo1.x); a[1][2] = __float_as_uint(lo1.y);
                a[1][1] = __float_as_uint(hi1.x); a[1][3] = __float_as_uint(hi1.y);
            }
            #pragma unroll
            for (int j = 0; j < 8; j++) {
                const float* kp = kb + (j * 8 + qr) * F_STR + rotq + g * 8 + qc;
                const uint32_t b0 = __float_as_uint(kp[0]);
                const uint32_t b1 = __float_as_uint(kp[4]);
                mma_tf32(s[0][j], a[0][0], a[0][1], a[0][2], a[0][3], b0, b1);
                mma_tf32(s[1][j], a[1][0], a[1][1], a[1][2], a[1][3], b0, b1);
            }
        }

        #pragma unroll
        for (int mt = 0; mt < 2; mt++) {
            #pragma unroll
            for (int hf = 0; hf < 2; hf++) {
                const int mi = mt * 2 + hf;
                float tm = -CUDART_INF_F;
                #pragma unroll
                for (int j = 0; j < 8; j++)
                    tm = fmaxf(tm, fmaxf(s[mt][j][hf * 2], s[mt][j][hf * 2 + 1]));
                tm = fmaxf(tm, __shfl_xor_sync(0xffffffffu, tm, 1));
                tm = fmaxf(tm, __shfl_xor_sync(0xffffffffu, tm, 2));
                const float mnew  = fmaxf(m_i[mi], tm);
                const float alpha = __expf(m_i[mi] - mnew);
                float ps = 0.0f;
                #pragma unroll
                for (int j = 0; j < 8; j++) {
                    float p0 = cvt_tf32(__expf(s[mt][j][hf * 2]     - mnew));
                    float p1 = cvt_tf32(__expf(s[mt][j][hf * 2 + 1] - mnew));
                    s[mt][j][hf * 2]     = p0;
                    s[mt][j][hf * 2 + 1] = p1;
                    ps += p0 + p1;
                }
                ps += __shfl_xor_sync(0xffffffffu, ps, 1);
                ps += __shfl_xor_sync(0xffffffffu, ps, 2);
                l_i[mi] = l_i[mi] * alpha + ps;
                m_i[mi] = mnew;
                #pragma unroll
                for (int j = 0; j < 8; j++) {
                    o[mt][j][hf * 2]     *= alpha;
                    o[mt][j][hf * 2 + 1] *= alpha;
                }
            }
        }

        #pragma unroll
        for (int g = 0; g < 8; g++) {
            uint32_t a[2][4];
            #pragma unroll
            for (int mt = 0; mt < 2; mt++) {
                const float x0 = __shfl_sync(0xffffffffu, s[mt][g][0], srcA);
                const float x1 = __shfl_sync(0xffffffffu, s[mt][g][1], srcA);
                const float y0 = __shfl_sync(0xffffffffu, s[mt][g][2], srcA);
                const float y1 = __shfl_sync(0xffffffffu, s[mt][g][3], srcA);
                const float w0 = __shfl_sync(0xffffffffu, s[mt][g][0], srcB);
                const float w1 = __shfl_sync(0xffffffffu, s[mt][g][1], srcB);
                const float u0 = __shfl_sync(0xffffffffu, s[mt][g][2], srcB);
                const float u1 = __shfl_sync(0xffffffffu, s[mt][g][3], srcB);
                a[mt][0] = __float_as_uint(odd ? x1 : x0);
                a[mt][1] = __float_as_uint(odd ? y1 : y0);
                a[mt][2] = __float_as_uint(odd ? w1 : w0);
                a[mt][3] = __float_as_uint(odd ? u1 : u0);
            }
            const float* v0 = vb + (g * 8 + qc) * F_STR;
            const float* v1 = vb + (g * 8 + qc + 4) * F_STR + 4;
            #pragma unroll
            for (int j = 0; j < 8; j++) {
                const uint32_t b0 = __float_as_uint(v0[j * 8 + qr]);
                const uint32_t b1 = __float_as_uint(v1[j * 8 + qr]);
                mma_tf32(o[0][j], a[0][0], a[0][1], a[0][2], a[0][3], b0, b1);
                mma_tf32(o[1][j], a[1][0], a[1][1], a[1][2], a[1][3], b0, b1);
            }
        }
        __syncthreads();
    }

    #pragma unroll
    for (int mt = 0; mt < 2; mt++) {
        const float inv0 = TF32_COMP / l_i[mt * 2];
        const float inv1 = TF32_COMP / l_i[mt * 2 + 1];
        const size_t row0 = (size_t)(bz * SEQ + qt * FB_M + rb + mt * 16 + qr);
        #pragma unroll
        for (int j = 0; j < 8; j++) {
            const int col = h * HD + j * 8 + 2 * qc;
            *(float2*)(g_attn + row0 * EMB + col) =
                make_float2(o[mt][j][0] * inv0, o[mt][j][1] * inv0);
            *(float2*)(g_attn + (row0 + 8) * EMB + col) =
                make_float2(o[mt][j][2] * inv1, o[mt][j][3] * inv1);
        }
    }
}

// ---------------------------------------------------------------------------
extern "C" void kernel_launch(void* const* d_in, const int* in_sizes, int n_in,
                              void* d_out, int out_size)
{
    (void)in_sizes; (void)n_in; (void)out_size;
    const float* x     = (const float*)d_in[0];
    const float* w_in  = (const float*)d_in[1];
    const float* b_in  = (const float*)d_in[2];
    const float* w_out = (const float*)d_in[3];
    const float* b_out = (const float*)d_in[4];
    float* out = (float*)d_out;

    void *qkv_p, *attn_p, *wti_p, *wto_p;
    cudaGetSymbolAddress(&qkv_p,  g_qkv);
    cudaGetSymbolAddress(&attn_p, g_attn);
    cudaGetSymbolAddress(&wti_p,  g_wti);
    cudaGetSymbolAddress(&wto_p,  g_wto);

    cudaFuncSetAttribute(flash_tc3, cudaFuncAttributeMaxDynamicSharedMemorySize,
                         FLASH_SMEM);
    cudaFuncSetAttribute(gemm_tf32cp, cudaFuncAttributeMaxDynamicSharedMemorySize,
                         GEMM_SMEM);

    // 0) transpose weights to K-major [N, K]
    transpose_k<<<dim3(E3 / 32, EMB / 32), dim3(32, 8)>>>(w_in,  (float*)wti_p, EMB, E3);
    transpose_k<<<dim3(EMB / 32, EMB / 32), dim3(32, 8)>>>(w_out, (float*)wto_p, EMB, EMB);

    // 1) QKV projection: [4096,1024] @ [1024,3072] + b_in
    gemm_tf32cp<<<dim3(E3 / 128, MTOT / 128), 256, GEMM_SMEM>>>(
        E3, EMB, x, (const float*)wti_p, b_in, (float*)qkv_p);

    // 2) Attention (tensor-core flash v3)
    flash_tc3<<<dim3(SEQ / FB_M, NH, BATCH), 256, FLASH_SMEM>>>();

    // 3) Output projection: [4096,1024] @ [1024,1024] + b_out
    gemm_tf32cp<<<dim3(EMB / 128, MTOT / 128), 256, GEMM_SMEM>>>(
        EMB, EMB, (const float*)attn_p, (const float*)wto_p, b_out, out);
}

// round 8
// speedup vs baseline: 2.4372x; 1.0178x over previous
#include <cuda_runtime.h>
#include <cuda_bf16.h>
#include <math_constants.h>
#include <cstdint>

// Problem constants
#define BATCH 2
#define SEQ   2048
#define EMB   1024
#define E3    3072
#define NH    16
#define HD    64
#define MTOT  (BATCH*SEQ)   // 4096

// Scratch (static device globals — no cudaMalloc allowed)
__device__ float g_qkv [(size_t)MTOT * E3];   // [4096, 3072]
__device__ float g_attn[(size_t)MTOT * EMB];  // [4096, 1024]
__device__ float g_wti [(size_t)E3 * EMB];    // w_in^T  [3072, 1024], k-permuted
__device__ float g_wto [(size_t)EMB * EMB];   // w_out^T [1024, 1024], k-permuted

// ---------------------------------------------------------------------------
__device__ __forceinline__ float cvt_tf32(float x) {
    uint32_t u;
    asm("cvt.rna.tf32.f32 %0, %1;" : "=r"(u) : "f"(x));
    return __uint_as_float(u);
}

__device__ __forceinline__ void mma_tf32(float c[4], uint32_t a0, uint32_t a1,
                                         uint32_t a2, uint32_t a3,
                                         uint32_t b0, uint32_t b1) {
    asm volatile(
        "mma.sync.aligned.m16n8k8.row.col.f32.tf32.tf32.f32 "
        "{%0,%1,%2,%3}, {%4,%5,%6,%7}, {%8,%9}, {%0,%1,%2,%3};"
        : "+f"(c[0]), "+f"(c[1]), "+f"(c[2]), "+f"(c[3])
        : "r"(a0), "r"(a1), "r"(a2), "r"(a3), "r"(b0), "r"(b1));
}

__device__ __forceinline__ uint32_t smem_u32(const void* p) {
    uint32_t a;
    asm("{ .reg .u64 t; cvta.to.shared.u64 t, %1; cvt.u32.u64 %0, t; }" : "=r"(a) : "l"(p));
    return a;
}
__device__ __forceinline__ void cp16(uint32_t saddr, const void* gaddr) {
    asm volatile("cp.async.cg.shared.global [%0], [%1], 16;" :: "r"(saddr), "l"(gaddr));
}
#define CP_COMMIT() asm volatile("cp.async.commit_group;" ::: "memory")
#define CP_WAIT(n)  asm volatile("cp.async.wait_group %0;" :: "n"(n) : "memory")

// mean truncation-bias compensation for raw-fp32 tf32 operands (RZ truncate)
#define TF32_COMP  1.00034f
#define TF32_COMP2 1.00068f
#define LOG2E      1.4426950408889634f

// ---------------------------------------------------------------------------
// Transpose + k-permute: out[n, perm(k)] = in[k, n].
// perm within 8-groups: k -> (k%4)*2 + (k>=4)  => b0/b1 fragment pairs adjacent
// ---------------------------------------------------------------------------
__global__ void __launch_bounds__(256) transpose_k(
    const float* __restrict__ in, float* __restrict__ out, int R, int C)
{
    __shared__ float t[32][33];
    const int bx = blockIdx.x * 32;
    const int by = blockIdx.y * 32;
    const int x = bx + threadIdx.x;
    #pragma unroll
    for (int j = 0; j < 4; j++) {
        const int y = by + threadIdx.y + j * 8;
        t[threadIdx.y + j * 8][threadIdx.x] = in[(size_t)y * C + x];
    }
    __syncthreads();
    const int x2 = by + threadIdx.x;                 // k index
    const int px = (x2 & ~7) | (((x2 & 3) << 1) | ((x2 >> 2) & 1));
    #pragma unroll
    for (int j = 0; j < 4; j++) {
        const int y2 = bx + threadIdx.y + j * 8;     // n index
        out[(size_t)y2 * R + px] = t[threadIdx.x][threadIdx.y + j * 8];
    }
}

// ---------------------------------------------------------------------------
// tf32 mma GEMM v3: C[M,N] = A[M,K] @ Bt[N,K]^T + bias[N]
// CTA 128x128, 8 warps (4x2), warp tile 32x64, BK=32, cp.async double buffer.
// A natural layout (LDS.32 frags); Bt is k-permuted -> B frags are LDS.64.
// ---------------------------------------------------------------------------
#define GS     40
#define GTILE  (128 * GS)
#define GEMM_SMEM (4 * GTILE * 4)

__global__ void __launch_bounds__(256, 2) gemm_tf32cp(
    int N, int K,
    const float* __restrict__ A,
    const float* __restrict__ Bt,
    const float* __restrict__ bias,
    float* __restrict__ C)
{
    extern __shared__ float gsm[];
    float* sA = gsm;
    float* sB = gsm + 2 * GTILE;
    const uint32_t sbA = smem_u32(sA);
    const uint32_t sbB = smem_u32(sB);

    const int tid  = threadIdx.x;
    const int wid  = tid >> 5;
    const int lane = tid & 31;
    const int wm   = wid >> 1;
    const int wn   = wid & 1;
    const int qr   = lane >> 2;
    const int qc   = lane & 3;
    const int rot  = ((qr >> 2) & 1) * 4;

    const int row  = tid & 127;
    const int half = tid >> 7;
    const uint32_t soff =
        (uint32_t)(row * GS + ((row >> 2) & 1) * 4 + half * 16) * 4;
    const float* Ag = A  + (size_t)(blockIdx.y * 128 + row) * K + half * 16;
    const float* Bg = Bt + (size_t)(blockIdx.x * 128 + row) * K + half * 16;

    float acc[2][8][4];
    #pragma unroll
    for (int i = 0; i < 2; i++)
        #pragma unroll
        for (int j = 0; j < 8; j++)
            #pragma unroll
            for (int c = 0; c < 4; c++) acc[i][j][c] = 0.0f;

    #pragma unroll
    for (int c = 0; c < 4; c++) {
        cp16(sbA + soff + c * 16, Ag + c * 4);
        cp16(sbB + soff + c * 16, Bg + c * 4);
    }
    CP_COMMIT();

    const int KT = K / 32;
    const int aBase = (wm * 32 + qr) * GS + rot + qc;       // natural k
    const int bBase = (wn * 64 + qr) * GS + rot + 2 * qc;   // permuted k

    for (int t = 0; t < KT; t++) {
        const int buf = t & 1;
        if (t + 1 < KT) {
            const int nb = (t + 1) & 1;
            const uint32_t dA = sbA + (uint32_t)nb * GTILE * 4 + soff;
            const uint32_t dB = sbB + (uint32_t)nb * GTILE * 4 + soff;
            const float* ap = Ag + (t + 1) * 32;
            const float* bp = Bg + (t + 1) * 32;
            #pragma unroll
            for (int c = 0; c < 4; c++) {
                cp16(dA + c * 16, ap + c * 4);
                cp16(dB + c * 16, bp + c * 4);
            }
            CP_COMMIT();
            CP_WAIT(1);
        } else {
            CP_WAIT(0);
        }
        __syncthreads();

        const float* pa = sA + buf * GTILE + aBase;
        const float* pb = sB + buf * GTILE + bBase;

        #pragma unroll
        for (int g = 0; g < 4; g++) {
            uint32_t af[2][4];
            #pragma unroll
            for (int mt = 0; mt < 2; mt++) {
                const float* p = pa + mt * 16 * GS + g * 8;
                af[mt][0] = __float_as_uint(p[0]);
                af[mt][2] = __float_as_uint(p[4]);
                af[mt][1] = __float_as_uint(p[8 * GS]);
                af[mt][3] = __float_as_uint(p[8 * GS + 4]);
            }
            #pragma unroll
            for (int j = 0; j < 8; j++) {
                const float2 bb = *(const float2*)(pb + j * 8 * GS + g * 8);
                const uint32_t b0 = __float_as_uint(bb.x);
                const uint32_t b1 = __float_as_uint(bb.y);
                mma_tf32(acc[0][j], af[0][0], af[0][1], af[0][2], af[0][3], b0, b1);
                mma_tf32(acc[1][j], af[1][0], af[1][1], af[1][2], af[1][3], b0, b1);
            }
        }
        __syncthreads();
    }

    const int mBase = blockIdx.y * 128 + wm * 32;
    const int nBase = blockIdx.x * 128 + wn * 64;
    #pragma unroll
    for (int mi = 0; mi < 2; mi++) {
        #pragma unroll
        for (int nj = 0; nj < 8; nj++) {
            const int col = nBase + nj * 8 + qc * 2;
            const float bx0 = bias[col], bx1 = bias[col + 1];
            const int r0 = mBase + mi * 16 + qr;
            float2 o0 = make_float2(fmaf(acc[mi][nj][0], TF32_COMP2, bx0),
                                    fmaf(acc[mi][nj][1], TF32_COMP2, bx1));
            float2 o1 = make_float2(fmaf(acc[mi][nj][2], TF32_COMP2, bx0),
                                    fmaf(acc[mi][nj][3], TF32_COMP2, bx1));
            *(float2*)(C + (size_t)r0 * N + col)       = o0;
            *(float2*)(C + (size_t)(r0 + 8) * N + col) = o1;
        }
    }
}

// ---------------------------------------------------------------------------
// Flash attention v4: 512 threads (16 warps x m16), FB_M=256, tf32 mma,
// cp.async K/V double buffer, exp2 softmax, P raw (compensated).
// SMEM: Q 256*72 | K0 | K1 | V0 | V1 (64*72 each) = 144KB, 1 CTA/SM.
// ---------------------------------------------------------------------------
#define FB_M   256
#define F_STR  72
#define QSZ    (FB_M * F_STR)
#define KVSZ   (64 * F_STR)
#define FLASH_SMEM ((QSZ + 4 * KVSZ) * 4)
#define NT     (SEQ / 64)

__global__ void __launch_bounds__(512, 1) flash_tc4()
{
    extern __shared__ float fsm[];
    const uint32_t sb = smem_u32(fsm);

    const int qt = blockIdx.x, h = blockIdx.y, bz = blockIdx.z;
    const int tid  = threadIdx.x;
    const int wid  = tid >> 5;
    const int lane = tid & 31;
    const int qr   = lane >> 2;
    const int qc   = lane & 3;
    const int rb   = wid * 16;               // warp's 16 query rows
    const int rotq = ((qr >> 2) & 1) * 4;
    const bool odd = qc & 1;
    const int srcA = (lane & ~3) | (qc >> 1);
    const int srcB = srcA + 2;

    const float* qg = g_qkv + (size_t)(bz * SEQ + qt * FB_M) * E3 + h * HD;
    const float* kg = g_qkv + (size_t)(bz * SEQ) * E3 + EMB     + h * HD;
    const float* vg = g_qkv + (size_t)(bz * SEQ) * E3 + 2 * EMB + h * HD;

    // cp.async: threads 0-255 load K (16 floats each), 256-511 load V
    const int isV  = tid >> 8;
    const int krow = tid & 63;
    const int kq   = (tid >> 6) & 3;
    const uint32_t soffKV =
        (uint32_t)(krow * F_STR + ((krow >> 2) & 1) * 4 + kq * 16) * 4;
    const uint32_t sK0 = sb + QSZ * 4;
    const uint32_t sV0 = sb + (QSZ + 2 * KVSZ) * 4;
    const float* kvg = isV ? vg : kg;
    const uint32_t kvs0 = isV ? sV0 : sK0;

    // ---- issue group 0 (K/V tile 0) ----
    {
        const float* s = kvg + (size_t)krow * E3 + kq * 16;
        #pragma unroll
        for (int c = 0; c < 4; c++) cp16(kvs0 + soffKV + c * 16, s + c * 4);
        CP_COMMIT();
    }

    // ---- load Q (row = tid>>1, half = tid&1): scale*log2e, cvt.rna ----
    {
        const float qscale = 0.125f * LOG2E * TF32_COMP;
        const int qrow = tid >> 1;
        const int qh   = tid & 1;
        const float* src = qg + (size_t)qrow * E3 + qh * 32;
        float* dst = fsm + qrow * F_STR + ((qrow >> 2) & 1) * 4 + qh * 32;
        #pragma unroll
        for (int gq = 0; gq < 4; gq++) {
            float4 f0 = *(const float4*)(src + gq * 8);
            float4 f1 = *(const float4*)(src + gq * 8 + 4);
            *(float4*)(dst + gq * 8) = make_float4(
                cvt_tf32(f0.x * qscale), cvt_tf32(f1.x * qscale),
                cvt_tf32(f0.y * qscale), cvt_tf32(f1.y * qscale));
            *(float4*)(dst + gq * 8 + 4) = make_float4(
                cvt_tf32(f0.z * qscale), cvt_tf32(f1.z * qscale),
                cvt_tf32(f0.w * qscale), cvt_tf32(f1.w * qscale));
        }
    }

    float o[8][4];
    float m_i[2], l_i[2];
    #pragma unroll
    for (int j = 0; j < 8; j++)
        #pragma unroll
        for (int c = 0; c < 4; c++) o[j][c] = 0.0f;
    m_i[0] = m_i[1] = -CUDART_INF_F;
    l_i[0] = l_i[1] = 0.0f;

    const int qb = (rb + qr) * F_STR + rotq + 2 * qc;

    for (int t = 0; t < NT; t++) {
        const int buf = t & 1;
        if (t + 1 < NT) {
            const int nb = (t + 1) & 1;
            const float* s = kvg + (size_t)((t + 1) * 64 + krow) * E3 + kq * 16;
            const uint32_t d = kvs0 + nb * (KVSZ * 4) + soffKV;
            #pragma unroll
            for (int c = 0; c < 4; c++) cp16(d + c * 16, s + c * 4);
            CP_COMMIT();
            CP_WAIT(1);
        } else {
            CP_WAIT(0);
        }
        __syncthreads();

        const float* kb = fsm + QSZ + buf * KVSZ;
        const float* vb = fsm + QSZ + 2 * KVSZ + buf * KVSZ;

        // ---- S = Q K^T : per warp m16 x n64 x k64 (scores in log2 units) ----
        float s[8][4];
        #pragma unroll
        for (int j = 0; j < 8; j++)
            #pragma unroll
            for (int c = 0; c < 4; c++) s[j][c] = 0.0f;

        #pragma unroll
        for (int g = 0; g < 8; g++) {
            const float2 lo = *(const float2*)(fsm + qb + g * 8);
            const float2 hi = *(const float2*)(fsm + qb + 8 * F_STR + g * 8);
            const uint32_t a0 = __float_as_uint(lo.x);
            const uint32_t a2 = __float_as_uint(lo.y);
            const uint32_t a1 = __float_as_uint(hi.x);
            const uint32_t a3 = __float_as_uint(hi.y);
            #pragma unroll
            for (int j = 0; j < 8; j++) {
                const float* kp = kb + (j * 8 + qr) * F_STR + rotq + g * 8 + qc;
                mma_tf32(s[j], a0, a1, a2, a3,
                         __float_as_uint(kp[0]), __float_as_uint(kp[4]));
            }
        }

        // ---- online softmax (rows qr / qr+8), exp2 domain ----
        #pragma unroll
        for (int hf = 0; hf < 2; hf++) {
            float tm = -CUDART_INF_F;
            #pragma unroll
            for (int j = 0; j < 8; j++)
                tm = fmaxf(tm, fmaxf(s[j][hf * 2], s[j][hf * 2 + 1]));
            tm = fmaxf(tm, __shfl_xor_sync(0xffffffffu, tm, 1));
            tm = fmaxf(tm, __shfl_xor_sync(0xffffffffu, tm, 2));
            const float mnew  = fmaxf(m_i[hf], tm);
            const float alpha = exp2f(m_i[hf] - mnew);
            float ps = 0.0f;
            #pragma unroll
            for (int j = 0; j < 8; j++) {
                const float p0 = exp2f(s[j][hf * 2]     - mnew);
                const float p1 = exp2f(s[j][hf * 2 + 1] - mnew);
                s[j][hf * 2]     = p0;
                s[j][hf * 2 + 1] = p1;
                ps += p0 + p1;
            }
            ps += __shfl_xor_sync(0xffffffffu, ps, 1);
            ps += __shfl_xor_sync(0xffffffffu, ps, 2);
            l_i[hf] = l_i[hf] * alpha + ps;
            m_i[hf] = mnew;
            #pragma unroll
            for (int j = 0; j < 8; j++) {
                o[j][hf * 2]     *= alpha;
                o[j][hf * 2 + 1] *= alpha;
            }
        }

        // ---- O += P V : A fragments from accumulators via shuffles ----
        #pragma unroll
        for (int g = 0; g < 8; g++) {
            const float x0 = __shfl_sync(0xffffffffu, s[g][0], srcA);
            const float x1 = __shfl_sync(0xffffffffu, s[g][1], srcA);
            const float y0 = __shfl_sync(0xffffffffu, s[g][2], srcA);
            const float y1 = __shfl_sync(0xffffffffu, s[g][3], srcA);
            const float w0 = __shfl_sync(0xffffffffu, s[g][0], srcB);
            const float w1 = __shfl_sync(0xffffffffu, s[g][1], srcB);
            const float u0 = __shfl_sync(0xffffffffu, s[g][2], srcB);
            const float u1 = __shfl_sync(0xffffffffu, s[g][3], srcB);
            const uint32_t a0 = __float_as_uint(odd ? x1 : x0);
            const uint32_t a1 = __float_as_uint(odd ? y1 : y0);
            const uint32_t a2 = __float_as_uint(odd ? w1 : w0);
            const uint32_t a3 = __float_as_uint(odd ? u1 : u0);
            const float* v0 = vb + (g * 8 + qc) * F_STR;
            const float* v1 = vb + (g * 8 + qc + 4) * F_STR + 4;
            #pragma unroll
            for (int j = 0; j < 8; j++) {
                mma_tf32(o[j], a0, a1, a2, a3,
                         __float_as_uint(v0[j * 8 + qr]),
                         __float_as_uint(v1[j * 8 + qr]));
            }
        }
        __syncthreads();
    }

    // ---- epilogue: normalize with P+V truncation comp, write [B,S,E] ----
    const float inv0 = TF32_COMP2 / l_i[0];
    const float inv1 = TF32_COMP2 / l_i[1];
    const size_t row0 = (size_t)(bz * SEQ + qt * FB_M + rb + qr);
    #pragma unroll
    for (int j = 0; j < 8; j++) {
        const int col = h * HD + j * 8 + 2 * qc;
        *(float2*)(g_attn + row0 * EMB + col) =
            make_float2(o[j][0] * inv0, o[j][1] * inv0);
        *(float2*)(g_attn + (row0 + 8) * EMB + col) =
            make_float2(o[j][2] * inv1, o[j][3] * inv1);
    }
}

// ---------------------------------------------------------------------------
extern "C" void kernel_launch(void* const* d_in, const int* in_sizes, int n_in,
                              void* d_out, int out_size)
{
    (void)in_sizes; (void)n_in; (void)out_size;
    const float* x     = (const float*)d_in[0];
    const float* w_in  = (const float*)d_in[1];
    const float* b_in  = (const float*)d_in[2];
    const float* w_out = (const float*)d_in[3];
    const float* b_out = (const float*)d_in[4];
    float* out = (float*)d_out;

    void *qkv_p, *attn_p, *wti_p, *wto_p;
    cudaGetSymbolAddress(&qkv_p,  g_qkv);
    cudaGetSymbolAddress(&attn_p, g_attn);
    cudaGetSymbolAddress(&wti_p,  g_wti);
    cudaGetSymbolAddress(&wto_p,  g_wto);

    cudaFuncSetAttribute(flash_tc4, cudaFuncAttributeMaxDynamicSharedMemorySize,
                         FLASH_SMEM);
    cudaFuncSetAttribute(gemm_tf32cp, cudaFuncAttributeMaxDynamicSharedMemorySize,
                         GEMM_SMEM);

    // 0) transpose + k-permute weights to [N, perm(K)]
    transpose_k<<<dim3(E3 / 32, EMB / 32), dim3(32, 8)>>>(w_in,  (float*)wti_p, EMB, E3);
    transpose_k<<<dim3(EMB / 32, EMB / 32), dim3(32, 8)>>>(w_out, (float*)wto_p, EMB, EMB);

    // 1) QKV projection: [4096,1024] @ [1024,3072] + b_in
    gemm_tf32cp<<<dim3(E3 / 128, MTOT / 128), 256, GEMM_SMEM>>>(
        E3, EMB, x, (const float*)wti_p, b_in, (float*)qkv_p);

    // 2) Attention (tensor-core flash v4)
    flash_tc4<<<dim3(SEQ / FB_M, NH, BATCH), 512, FLASH_SMEM>>>();

    // 3) Output projection: [4096,1024] @ [1024,1024] + b_out
    gemm_tf32cp<<<dim3(EMB / 128, MTOT / 128), 256, GEMM_SMEM>>>(
        EMB, EMB, (const float*)attn_p, (const float*)wto_p, b_out, out);
}

// round 9
// speedup vs baseline: 4.3254x; 1.7747x over previous
#include <cuda_runtime.h>
#include <cuda_fp16.h>
#include <math_constants.h>
#include <cstdint>

// Problem constants
#define BATCH 2
#define SEQ   2048
#define EMB   1024
#define E3    3072
#define NH    16
#define HD    64
#define MTOT  (BATCH*SEQ)   // 4096

// Scratch (static device globals — no cudaMalloc allowed)
__device__ __half g_xh   [(size_t)MTOT * EMB];   // x as fp16
__device__ __half g_qkvh [(size_t)MTOT * E3];    // qkv fp16
__device__ __half g_attnh[(size_t)MTOT * EMB];   // attn fp16
__device__ __half g_wti  [(size_t)E3 * EMB];     // w_in^T  fp16 [3072][1024]
__device__ __half g_wto  [(size_t)EMB * EMB];    // w_out^T fp16 [1024][1024]

#define LOG2E 1.4426950408889634f

// ---------------------------------------------------------------------------
__device__ __forceinline__ void mma_f16(float c[4], uint32_t a0, uint32_t a1,
                                        uint32_t a2, uint32_t a3,
                                        uint32_t b0, uint32_t b1) {
    asm volatile(
        "mma.sync.aligned.m16n8k16.row.col.f32.f16.f16.f32 "
        "{%0,%1,%2,%3}, {%4,%5,%6,%7}, {%8,%9}, {%0,%1,%2,%3};"
        : "+f"(c[0]), "+f"(c[1]), "+f"(c[2]), "+f"(c[3])
        : "r"(a0), "r"(a1), "r"(a2), "r"(a3), "r"(b0), "r"(b1));
}

__device__ __forceinline__ uint32_t smem_u32(const void* p) {
    uint32_t a;
    asm("{ .reg .u64 t; cvta.to.shared.u64 t, %1; cvt.u32.u64 %0, t; }" : "=r"(a) : "l"(p));
    return a;
}
__device__ __forceinline__ void cp16(uint32_t saddr, const void* gaddr) {
    asm volatile("cp.async.cg.shared.global [%0], [%1], 16;" :: "r"(saddr), "l"(gaddr));
}
#define CP_COMMIT() asm volatile("cp.async.commit_group;" ::: "memory")
#define CP_WAIT(n)  asm volatile("cp.async.wait_group %0;" :: "n"(n) : "memory")

__device__ __forceinline__ void ldsm_x4_trans(uint32_t& r0, uint32_t& r1,
                                              uint32_t& r2, uint32_t& r3,
                                              uint32_t addr) {
    asm volatile("ldmatrix.sync.aligned.m8n8.x4.trans.shared.b16 "
                 "{%0,%1,%2,%3}, [%4];"
                 : "=r"(r0), "=r"(r1), "=r"(r2), "=r"(r3) : "r"(addr));
}

// ---------------------------------------------------------------------------
// x fp32 -> fp16 (8 elems/thread)
// ---------------------------------------------------------------------------
__global__ void __launch_bounds__(256) cvt_x_half(
    const float* __restrict__ in, __half* __restrict__ out)
{
    const size_t i = ((size_t)blockIdx.x * 256 + threadIdx.x) * 8;
    const float4 f0 = *(const float4*)(in + i);
    const float4 f1 = *(const float4*)(in + i + 4);
    __half2 h[4];
    h[0] = __floats2half2_rn(f0.x, f0.y);
    h[1] = __floats2half2_rn(f0.z, f0.w);
    h[2] = __floats2half2_rn(f1.x, f1.y);
    h[3] = __floats2half2_rn(f1.z, f1.w);
    *(uint4*)(out + i) = *(uint4*)h;
}

// ---------------------------------------------------------------------------
// Transpose fp32 -> fp16: out[C][R] = half(in[R][C]^T)
// ---------------------------------------------------------------------------
__global__ void __launch_bounds__(256) transpose_h(
    const float* __restrict__ in, __half* __restrict__ out, int R, int C)
{
    __shared__ float t[32][33];
    const int bx = blockIdx.x * 32;
    const int by = blockIdx.y * 32;
    const int x = bx + threadIdx.x;
    #pragma unroll
    for (int j = 0; j < 4; j++) {
        const int y = by + threadIdx.y + j * 8;
        t[threadIdx.y + j * 8][threadIdx.x] = in[(size_t)y * C + x];
    }
    __syncthreads();
    const int x2 = by + threadIdx.x;
    #pragma unroll
    for (int j = 0; j < 4; j++) {
        const int y2 = bx + threadIdx.y + j * 8;
        out[(size_t)y2 * R + x2] = __float2half_rn(t[threadIdx.x][threadIdx.y + j * 8]);
    }
}

// ---------------------------------------------------------------------------
// fp16 mma GEMM: C = A[M,K] @ Bt[N,K]^T + bias. CTA 128x128, 8 warps (4x2),
// warp tile 32x64, BK=32, cp.async double buffer.
// SMEM tiles fp16, row stride 40 (80B = 20 banks): all LDS.32 fragment
// phases and 16B cp.async stores conflict-free (verified bank maps).
// Output: fp16 (Ch) when Ch != nullptr, else fp32 (Cf).
// ---------------------------------------------------------------------------
#define GSH    40
#define GTILEH (128 * GSH)                 // fp16 units per tile buffer
#define GEMM_SMEM (4 * GTILEH * 2)         // 40960 bytes

__global__ void __launch_bounds__(256, 2) gemm_f16(
    int N, int K,
    const __half* __restrict__ A,
    const __half* __restrict__ Bt,
    const float* __restrict__ bias,
    __half* __restrict__ Ch,
    float* __restrict__ Cf)
{
    extern __shared__ __half gsm[];
    __half* sA = gsm;                      // [2][GTILEH]
    __half* sB = gsm + 2 * GTILEH;
    const uint32_t sbA = smem_u32(sA);
    const uint32_t sbB = smem_u32(sB);

    const int tid  = threadIdx.x;
    const int wid  = tid >> 5;
    const int lane = tid & 31;
    const int wm   = wid >> 1;             // 0..3 : 32-row slice
    const int wn   = wid & 1;              // 0..1 : 64-col slice
    const int qr   = lane >> 2;
    const int qc   = lane & 3;

    // cp.async: thread -> (row, 32B half-chunk): 2 cp16 per matrix per tile
    const int row = tid & 127;
    const int hc  = tid >> 7;
    const uint32_t soff = (uint32_t)(row * GSH + hc * 16) * 2;
    const __half* Ag = A  + (size_t)(blockIdx.y * 128 + row) * K + hc * 16;
    const __half* Bg = Bt + (size_t)(blockIdx.x * 128 + row) * K + hc * 16;

    float acc[2][8][4];
    #pragma unroll
    for (int i = 0; i < 2; i++)
        #pragma unroll
        for (int j = 0; j < 8; j++)
            #pragma unroll
            for (int c = 0; c < 4; c++) acc[i][j][c] = 0.0f;

    // prologue: tile 0
    cp16(sbA + soff, Ag);      cp16(sbA + soff + 16, Ag + 8);
    cp16(sbB + soff, Bg);      cp16(sbB + soff + 16, Bg + 8);
    CP_COMMIT();

    const int KT = K / 32;
    const int aBase = (wm * 32 + qr) * GSH + 2 * qc;
    const int bBase = (wn * 64 + qr) * GSH + 2 * qc;

    for (int t = 0; t < KT; t++) {
        const int buf = t & 1;
        if (t + 1 < KT) {
            const int nb = (t + 1) & 1;
            const uint32_t dA = sbA + (uint32_t)nb * GTILEH * 2 + soff;
            const uint32_t dB = sbB + (uint32_t)nb * GTILEH * 2 + soff;
            const __half* ap = Ag + (t + 1) * 32;
            const __half* bp = Bg + (t + 1) * 32;
            cp16(dA, ap);      cp16(dA + 16, ap + 8);
            cp16(dB, bp);      cp16(dB + 16, bp + 8);
            CP_COMMIT();
            CP_WAIT(1);
        } else {
            CP_WAIT(0);
        }
        __syncthreads();

        const __half* pa = sA + buf * GTILEH + aBase;
        const __half* pb = sB + buf * GTILEH + bBase;

        #pragma unroll
        for (int g = 0; g < 2; g++) {          // two k16 groups
            uint32_t af[2][4];
            #pragma unroll
            for (int mt = 0; mt < 2; mt++) {
                const __half* p = pa + mt * 16 * GSH + g * 16;
                af[mt][0] = *(const uint32_t*)(p);
                af[mt][1] = *(const uint32_t*)(p + 8 * GSH);
                af[mt][2] = *(const uint32_t*)(p + 8);
                af[mt][3] = *(const uint32_t*)(p + 8 * GSH + 8);
            }
            #pragma unroll
            for (int j = 0; j < 8; j++) {
                const __half* p = pb + j * 8 * GSH + g * 16;
                const uint32_t b0 = *(const uint32_t*)(p);
                const uint32_t b1 = *(const uint32_t*)(p + 8);
                mma_f16(acc[0][j], af[0][0], af[0][1], af[0][2], af[0][3], b0, b1);
                mma_f16(acc[1][j], af[1][0], af[1][1], af[1][2], af[1][3], b0, b1);
            }
        }
        __syncthreads();
    }

    const int mBase = blockIdx.y * 128 + wm * 32;
    const int nBase = blockIdx.x * 128 + wn * 64;
    #pragma unroll
    for (int mi = 0; mi < 2; mi++) {
        #pragma unroll
        for (int nj = 0; nj < 8; nj++) {
            const int col = nBase + nj * 8 + qc * 2;
            const float bx0 = bias[col], bx1 = bias[col + 1];
            const int r0 = mBase + mi * 16 + qr;
            if (Ch) {
                *(__half2*)(Ch + (size_t)r0 * N + col) =
                    __floats2half2_rn(acc[mi][nj][0] + bx0, acc[mi][nj][1] + bx1);
                *(__half2*)(Ch + (size_t)(r0 + 8) * N + col) =
                    __floats2half2_rn(acc[mi][nj][2] + bx0, acc[mi][nj][3] + bx1);
            } else {
                *(float2*)(Cf + (size_t)r0 * N + col) =
                    make_float2(acc[mi][nj][0] + bx0, acc[mi][nj][1] + bx1);
                *(float2*)(Cf + (size_t)(r0 + 8) * N + col) =
                    make_float2(acc[mi][nj][2] + bx0, acc[mi][nj][3] + bx1);
            }
        }
    }
}

// ---------------------------------------------------------------------------
// Flash attention v5: fp16 m16n8k16 mma, FB_M=128, 8 warps x m16, 256 thr,
// 2 CTA/SM. cp.async fp16 K/V double buffer; P->A frags by pure packs
// (C-frag layout == A-frag layout for fp16); V^T frags via ldmatrix.x4.trans.
// SMEM fp16, row stride 72 (144B = 36 banks): LDS.32 frags and ldmatrix rows
// conflict-free (verified).
// ---------------------------------------------------------------------------
#define FB_M   128
#define FSH    72
#define QSZH   (FB_M * FSH)                // 9216 fp16
#define KVSZH  (64 * FSH)                  // 4608 fp16
#define FLASH_SMEM ((QSZH + 4 * KVSZH) * 2)   // 55296 bytes
#define NT     (SEQ / 64)

__global__ void __launch_bounds__(256, 2) flash_f16()
{
    extern __shared__ __half fsm[];
    const uint32_t sb = smem_u32(fsm);

    const int qt = blockIdx.x, h = blockIdx.y, bz = blockIdx.z;
    const int tid  = threadIdx.x;
    const int wid  = tid >> 5;
    const int lane = tid & 31;
    const int qr   = lane >> 2;
    const int qc   = lane & 3;
    const int rb   = wid * 16;             // warp's 16 query rows

    const __half* qg = g_qkvh + (size_t)(bz * SEQ + qt * FB_M) * E3 + h * HD;
    const __half* kg = g_qkvh + (size_t)(bz * SEQ) * E3 + EMB     + h * HD;
    const __half* vg = g_qkvh + (size_t)(bz * SEQ) * E3 + 2 * EMB + h * HD;

    // cp.async: threads 0-127 -> K, 128-255 -> V; each thread 64B of one row
    const int isV  = tid >> 7;
    const int krow = tid & 63;
    const int khc  = (tid >> 6) & 1;
    const uint32_t soffKV = (uint32_t)(krow * FSH + khc * 32) * 2;
    const uint32_t sK0 = sb + QSZH * 2;
    const uint32_t sV0 = sb + (QSZH + 2 * KVSZH) * 2;
    const __half* kvg   = isV ? vg : kg;
    const uint32_t kvs0 = isV ? sV0 : sK0;

    // issue K/V tile 0
    {
        const __half* s = kvg + (size_t)krow * E3 + khc * 32;
        #pragma unroll
        for (int c = 0; c < 4; c++) cp16(kvs0 + soffKV + c * 16, s + c * 8);
        CP_COMMIT();
    }

    // load Q scaled by (1/8)*log2e, fp32 math, store fp16 natural
    {
        const float qscale = 0.125f * LOG2E;
        const int qrow = tid >> 1;
        const int qh   = tid & 1;
        const __half* src = qg + (size_t)qrow * E3 + qh * 32;
        __half* dst = fsm + qrow * FSH + qh * 32;
        #pragma unroll
        for (int p = 0; p < 4; p++) {
            uint4 raw = *(const uint4*)(src + p * 8);
            const __half2* hp = (const __half2*)&raw;
            __half2 o[4];
            #pragma unroll
            for (int e = 0; e < 4; e++) {
                float2 f = __half22float2(hp[e]);
                o[e] = __floats2half2_rn(f.x * qscale, f.y * qscale);
            }
            *(uint4*)(dst + p * 8) = *(uint4*)o;
        }
    }

    float o[8][4];
    float m_i[2], l_i[2];
    #pragma unroll
    for (int j = 0; j < 8; j++)
        #pragma unroll
        for (int c = 0; c < 4; c++) o[j][c] = 0.0f;
    m_i[0] = m_i[1] = -CUDART_INF_F;
    l_i[0] = l_i[1] = 0.0f;

    const int qb = (rb + qr) * FSH + 2 * qc;
    // ldmatrix lane offset: t = lane>>3 (matrix), rr = lane&7 (row)
    const uint32_t lmo = (uint32_t)(((lane >> 3) & 1) * 8 + (lane & 7)) * FSH * 2
                       + (uint32_t)((lane >> 4) * 8) * 2;

    for (int t = 0; t < NT; t++) {
        const int buf = t & 1;
        if (t + 1 < NT) {
            const int nb = (t + 1) & 1;
            const __half* s = kvg + (size_t)((t + 1) * 64 + krow) * E3 + khc * 32;
            const uint32_t d = kvs0 + nb * (KVSZH * 2) + soffKV;
            #pragma unroll
            for (int c = 0; c < 4; c++) cp16(d + c * 16, s + c * 8);
            CP_COMMIT();
            CP_WAIT(1);
        } else {
            CP_WAIT(0);
        }
        __syncthreads();

        const __half* kb = fsm + QSZH + buf * KVSZH;
        const uint32_t vbase = sV0 + buf * (KVSZH * 2) + lmo;

        // ---- S = Q K^T : m16 x n64 x k64 (4 k16-groups x 8 j) ----
        float s[8][4];
        #pragma unroll
        for (int j = 0; j < 8; j++)
            #pragma unroll
            for (int c = 0; c < 4; c++) s[j][c] = 0.0f;

        #pragma unroll
        for (int g = 0; g < 4; g++) {
            const __half* qp = fsm + qb + g * 16;
            const uint32_t a0 = *(const uint32_t*)(qp);
            const uint32_t a1 = *(const uint32_t*)(qp + 8 * FSH);
            const uint32_t a2 = *(const uint32_t*)(qp + 8);
            const uint32_t a3 = *(const uint32_t*)(qp + 8 * FSH + 8);
            #pragma unroll
            for (int j = 0; j < 8; j++) {
                const __half* kp = kb + (j * 8 + qr) * FSH + g * 16 + 2 * qc;
                mma_f16(s[j], a0, a1, a2, a3,
                        *(const uint32_t*)(kp), *(const uint32_t*)(kp + 8));
            }
        }

        // ---- online softmax (rows qr / qr+8), exp2 domain ----
        #pragma unroll
        for (int hf = 0; hf < 2; hf++) {
            float tm = -CUDART_INF_F;
            #pragma unroll
            for (int j = 0; j < 8; j++)
                tm = fmaxf(tm, fmaxf(s[j][hf * 2], s[j][hf * 2 + 1]));
            tm = fmaxf(tm, __shfl_xor_sync(0xffffffffu, tm, 1));
            tm = fmaxf(tm, __shfl_xor_sync(0xffffffffu, tm, 2));
            const float mnew  = fmaxf(m_i[hf], tm);
            const float alpha = exp2f(m_i[hf] - mnew);
            float ps = 0.0f;
            #pragma unroll
            for (int j = 0; j < 8; j++) {
                const float p0 = exp2f(s[j][hf * 2]     - mnew);
                const float p1 = exp2f(s[j][hf * 2 + 1] - mnew);
                s[j][hf * 2]     = p0;
                s[j][hf * 2 + 1] = p1;
                ps += p0 + p1;
            }
            ps += __shfl_xor_sync(0xffffffffu, ps, 1);
            ps += __shfl_xor_sync(0xffffffffu, ps, 2);
            l_i[hf] = l_i[hf] * alpha + ps;
            m_i[hf] = mnew;
            #pragma unroll
            for (int j = 0; j < 8; j++) {
                o[j][hf * 2]     *= alpha;
                o[j][hf * 2 + 1] *= alpha;
            }
        }

        // ---- O += P V : A frags = packed accumulators (no shuffles);
        //      B frags = ldmatrix.x4.trans of V ----
        #pragma unroll
        for (int g = 0; g < 4; g++) {
            uint32_t pa0, pa1, pa2, pa3;
            {
                __half2 t0 = __floats2half2_rn(s[2 * g][0],     s[2 * g][1]);
                __half2 t1 = __floats2half2_rn(s[2 * g][2],     s[2 * g][3]);
                __half2 t2 = __floats2half2_rn(s[2 * g + 1][0], s[2 * g + 1][1]);
                __half2 t3 = __floats2half2_rn(s[2 * g + 1][2], s[2 * g + 1][3]);
                pa0 = *(uint32_t*)&t0; pa1 = *(uint32_t*)&t1;
                pa2 = *(uint32_t*)&t2; pa3 = *(uint32_t*)&t3;
            }
            #pragma unroll
            for (int jp = 0; jp < 4; jp++) {
                uint32_t b0, b1, b2, b3;
                ldsm_x4_trans(b0, b1, b2, b3,
                              vbase + (uint32_t)(g * 16) * FSH * 2
                                    + (uint32_t)(jp * 16) * 2);
                mma_f16(o[2 * jp],     pa0, pa1, pa2, pa3, b0, b1);
                mma_f16(o[2 * jp + 1], pa0, pa1, pa2, pa3, b2, b3);
            }
        }
        __syncthreads();
    }

    // ---- epilogue: normalize, write fp16 attn ----
    const float inv0 = 1.0f / l_i[0];
    const float inv1 = 1.0f / l_i[1];
    const size_t row0 = (size_t)(bz * SEQ + qt * FB_M + rb + qr);
    #pragma unroll
    for (int j = 0; j < 8; j++) {
        const int col = h * HD + j * 8 + 2 * qc;
        *(__half2*)(g_attnh + row0 * EMB + col) =
            __floats2half2_rn(o[j][0] * inv0, o[j][1] * inv0);
        *(__half2*)(g_attnh + (row0 + 8) * EMB + col) =
            __floats2half2_rn(o[j][2] * inv1, o[j][3] * inv1);
    }
}

// ---------------------------------------------------------------------------
extern "C" void kernel_launch(void* const* d_in, const int* in_sizes, int n_in,
                              void* d_out, int out_size)
{
    (void)in_sizes; (void)n_in; (void)out_size;
    const float* x     = (const float*)d_in[0];
    const float* w_in  = (const float*)d_in[1];
    const float* b_in  = (const float*)d_in[2];
    const float* w_out = (const float*)d_in[3];
    const float* b_out = (const float*)d_in[4];
    float* out = (float*)d_out;

    void *xh_p, *qkv_p, *attn_p, *wti_p, *wto_p;
    cudaGetSymbolAddress(&xh_p,   g_xh);
    cudaGetSymbolAddress(&qkv_p,  g_qkvh);
    cudaGetSymbolAddress(&attn_p, g_attnh);
    cudaGetSymbolAddress(&wti_p,  g_wti);
    cudaGetSymbolAddress(&wto_p,  g_wto);

    cudaFuncSetAttribute(flash_f16, cudaFuncAttributeMaxDynamicSharedMemorySize,
                         FLASH_SMEM);
    cudaFuncSetAttribute(gemm_f16, cudaFuncAttributeMaxDynamicSharedMemorySize,
                         GEMM_SMEM);

    // 0) conversions: x -> fp16, weights -> fp16 transposed [N][K]
    cvt_x_half<<<(MTOT * EMB) / (256 * 8), 256>>>(x, (__half*)xh_p);
    transpose_h<<<dim3(E3 / 32, EMB / 32), dim3(32, 8)>>>(w_in,  (__half*)wti_p, EMB, E3);
    transpose_h<<<dim3(EMB / 32, EMB / 32), dim3(32, 8)>>>(w_out, (__half*)wto_p, EMB, EMB);

    // 1) QKV projection (fp16 mma, fp16 out): [4096,1024]@[1024,3072]+b_in
    gemm_f16<<<dim3(E3 / 128, MTOT / 128), 256, GEMM_SMEM>>>(
        E3, EMB, (const __half*)xh_p, (const __half*)wti_p, b_in,
        (__half*)qkv_p, nullptr);

    // 2) Attention (fp16 flash)
    flash_f16<<<dim3(SEQ / FB_M, NH, BATCH), 256, FLASH_SMEM>>>();

    // 3) Output projection (fp16 mma, fp32 out): [4096,1024]@[1024,1024]+b_out
    gemm_f16<<<dim3(EMB / 128, MTOT / 128), 256, GEMM_SMEM>>>(
        EMB, EMB, (const __half*)attn_p, (const __half*)wto_p, b_out,
        nullptr, out);
}

// round 10
// speedup vs baseline: 4.4040x; 1.0182x over previous
#include <cuda_runtime.h>
#include <cuda_fp16.h>
#include <math_constants.h>
#include <cstdint>

// Problem constants
#define BATCH 2
#define SEQ   2048
#define EMB   1024
#define E3    3072
#define NH    16
#define HD    64
#define MTOT  (BATCH*SEQ)   // 4096

// Scratch (static device globals — no cudaMalloc allowed)
__device__ __half g_xh   [(size_t)MTOT * EMB];   // x as fp16
__device__ __half g_qkvh [(size_t)MTOT * E3];    // qkv fp16
__device__ __half g_attnh[(size_t)MTOT * EMB];   // attn fp16
__device__ __half g_wti  [(size_t)E3 * EMB];     // w_in^T  fp16 [3072][1024]
__device__ __half g_wto  [(size_t)EMB * EMB];    // w_out^T fp16 [1024][1024]

#define LOG2E 1.4426950408889634f

// ---------------------------------------------------------------------------
__device__ __forceinline__ void mma_f16(float c[4], uint32_t a0, uint32_t a1,
                                        uint32_t a2, uint32_t a3,
                                        uint32_t b0, uint32_t b1) {
    asm volatile(
        "mma.sync.aligned.m16n8k16.row.col.f32.f16.f16.f32 "
        "{%0,%1,%2,%3}, {%4,%5,%6,%7}, {%8,%9}, {%0,%1,%2,%3};"
        : "+f"(c[0]), "+f"(c[1]), "+f"(c[2]), "+f"(c[3])
        : "r"(a0), "r"(a1), "r"(a2), "r"(a3), "r"(b0), "r"(b1));
}

__device__ __forceinline__ uint32_t smem_u32(const void* p) {
    uint32_t a;
    asm("{ .reg .u64 t; cvta.to.shared.u64 t, %1; cvt.u32.u64 %0, t; }" : "=r"(a) : "l"(p));
    return a;
}
__device__ __forceinline__ void cp16(uint32_t saddr, const void* gaddr) {
    asm volatile("cp.async.cg.shared.global [%0], [%1], 16;" :: "r"(saddr), "l"(gaddr));
}
#define CP_COMMIT() asm volatile("cp.async.commit_group;" ::: "memory")
#define CP_WAIT(n)  asm volatile("cp.async.wait_group %0;" :: "n"(n) : "memory")

__device__ __forceinline__ void ldsm_x4_trans(uint32_t& r0, uint32_t& r1,
                                              uint32_t& r2, uint32_t& r3,
                                              uint32_t addr) {
    asm volatile("ldmatrix.sync.aligned.m8n8.x4.trans.shared.b16 "
                 "{%0,%1,%2,%3}, [%4];"
                 : "=r"(r0), "=r"(r1), "=r"(r2), "=r"(r3) : "r"(addr));
}

// ---------------------------------------------------------------------------
// x fp32 -> fp16 (8 elems/thread)
// ---------------------------------------------------------------------------
__global__ void __launch_bounds__(256) cvt_x_half(
    const float* __restrict__ in, __half* __restrict__ out)
{
    const size_t i = ((size_t)blockIdx.x * 256 + threadIdx.x) * 8;
    const float4 f0 = *(const float4*)(in + i);
    const float4 f1 = *(const float4*)(in + i + 4);
    __half2 h[4];
    h[0] = __floats2half2_rn(f0.x, f0.y);
    h[1] = __floats2half2_rn(f0.z, f0.w);
    h[2] = __floats2half2_rn(f1.x, f1.y);
    h[3] = __floats2half2_rn(f1.z, f1.w);
    *(uint4*)(out + i) = *(uint4*)h;
}

// ---------------------------------------------------------------------------
// Transpose fp32 -> fp16: out[C][R] = half(in[R][C]^T)
// ---------------------------------------------------------------------------
__global__ void __launch_bounds__(256) transpose_h(
    const float* __restrict__ in, __half* __restrict__ out, int R, int C)
{
    __shared__ float t[32][33];
    const int bx = blockIdx.x * 32;
    const int by = blockIdx.y * 32;
    const int x = bx + threadIdx.x;
    #pragma unroll
    for (int j = 0; j < 4; j++) {
        const int y = by + threadIdx.y + j * 8;
        t[threadIdx.y + j * 8][threadIdx.x] = in[(size_t)y * C + x];
    }
    __syncthreads();
    const int x2 = by + threadIdx.x;
    #pragma unroll
    for (int j = 0; j < 4; j++) {
        const int y2 = bx + threadIdx.y + j * 8;
        out[(size_t)y2 * R + x2] = __float2half_rn(t[threadIdx.x][threadIdx.y + j * 8]);
    }
}

// ---------------------------------------------------------------------------
// fp16 mma GEMM v4: C = A[M,K] @ Bt[N,K]^T + bias. CTA 128x128, 8 warps
// (4x2), warp 32x64, BK=32, 4-stage cp.async ring, ONE barrier per iter.
// ---------------------------------------------------------------------------
#define GSH    40
#define GTILEH (128 * GSH)                 // fp16 units per stage per matrix
#define GSTG   4
#define GEMM_SMEM (2 * GSTG * GTILEH * 2)  // 81920 bytes

__global__ void __launch_bounds__(256, 2) gemm_f16(
    int N, int K,
    const __half* __restrict__ A,
    const __half* __restrict__ Bt,
    const float* __restrict__ bias,
    __half* __restrict__ Ch,
    float* __restrict__ Cf)
{
    extern __shared__ __half gsm[];
    __half* sA = gsm;                      // [GSTG][GTILEH]
    __half* sB = gsm + GSTG * GTILEH;
    const uint32_t sbA = smem_u32(sA);
    const uint32_t sbB = smem_u32(sB);

    const int tid  = threadIdx.x;
    const int wid  = tid >> 5;
    const int lane = tid & 31;
    const int wm   = wid >> 1;
    const int wn   = wid & 1;
    const int qr   = lane >> 2;
    const int qc   = lane & 3;

    const int row = tid & 127;
    const int hc  = tid >> 7;
    const uint32_t soff = (uint32_t)(row * GSH + hc * 16) * 2;
    const __half* Ag = A  + (size_t)(blockIdx.y * 128 + row) * K + hc * 16;
    const __half* Bg = Bt + (size_t)(blockIdx.x * 128 + row) * K + hc * 16;

    float acc[2][8][4];
    #pragma unroll
    for (int i = 0; i < 2; i++)
        #pragma unroll
        for (int j = 0; j < 8; j++)
            #pragma unroll
            for (int c = 0; c < 4; c++) acc[i][j][c] = 0.0f;

    const int KT = K / 32;

    // prologue: stages 0..2
    #pragma unroll
    for (int s = 0; s < GSTG - 1; s++) {
        const uint32_t dA = sbA + (uint32_t)s * GTILEH * 2 + soff;
        const uint32_t dB = sbB + (uint32_t)s * GTILEH * 2 + soff;
        const __half* ap = Ag + s * 32;
        const __half* bp = Bg + s * 32;
        cp16(dA, ap);      cp16(dA + 16, ap + 8);
        cp16(dB, bp);      cp16(dB + 16, bp + 8);
        CP_COMMIT();
    }

    const int aBase = (wm * 32 + qr) * GSH + 2 * qc;
    const int bBase = (wn * 64 + qr) * GSH + 2 * qc;

    for (int t = 0; t < KT; t++) {
        const int buf = t & (GSTG - 1);
        CP_WAIT(2);
        __syncthreads();

        // issue stage t+3 (empty commit keeps the wait-group invariant)
        if (t + GSTG - 1 < KT) {
            const int nb = (t + GSTG - 1) & (GSTG - 1);
            const uint32_t dA = sbA + (uint32_t)nb * GTILEH * 2 + soff;
            const uint32_t dB = sbB + (uint32_t)nb * GTILEH * 2 + soff;
            const __half* ap = Ag + (t + GSTG - 1) * 32;
            const __half* bp = Bg + (t + GSTG - 1) * 32;
            cp16(dA, ap);      cp16(dA + 16, ap + 8);
            cp16(dB, bp);      cp16(dB + 16, bp + 8);
        }
        CP_COMMIT();

        const __half* pa = sA + buf * GTILEH + aBase;
        const __half* pb = sB + buf * GTILEH + bBase;

        #pragma unroll
        for (int g = 0; g < 2; g++) {
            uint32_t af[2][4];
            #pragma unroll
            for (int mt = 0; mt < 2; mt++) {
                const __half* p = pa + mt * 16 * GSH + g * 16;
                af[mt][0] = *(const uint32_t*)(p);
                af[mt][1] = *(const uint32_t*)(p + 8 * GSH);
                af[mt][2] = *(const uint32_t*)(p + 8);
                af[mt][3] = *(const uint32_t*)(p + 8 * GSH + 8);
            }
            #pragma unroll
            for (int j = 0; j < 8; j++) {
                const __half* p = pb + j * 8 * GSH + g * 16;
                const uint32_t b0 = *(const uint32_t*)(p);
                const uint32_t b1 = *(const uint32_t*)(p + 8);
                mma_f16(acc[0][j], af[0][0], af[0][1], af[0][2], af[0][3], b0, b1);
                mma_f16(acc[1][j], af[1][0], af[1][1], af[1][2], af[1][3], b0, b1);
            }
        }
    }

    const int mBase = blockIdx.y * 128 + wm * 32;
    const int nBase = blockIdx.x * 128 + wn * 64;
    #pragma unroll
    for (int mi = 0; mi < 2; mi++) {
        #pragma unroll
        for (int nj = 0; nj < 8; nj++) {
            const int col = nBase + nj * 8 + qc * 2;
            const float bx0 = bias[col], bx1 = bias[col + 1];
            const int r0 = mBase + mi * 16 + qr;
            if (Ch) {
                *(__half2*)(Ch + (size_t)r0 * N + col) =
                    __floats2half2_rn(acc[mi][nj][0] + bx0, acc[mi][nj][1] + bx1);
                *(__half2*)(Ch + (size_t)(r0 + 8) * N + col) =
                    __floats2half2_rn(acc[mi][nj][2] + bx0, acc[mi][nj][3] + bx1);
            } else {
                *(float2*)(Cf + (size_t)r0 * N + col) =
                    make_float2(acc[mi][nj][0] + bx0, acc[mi][nj][1] + bx1);
                *(float2*)(Cf + (size_t)(r0 + 8) * N + col) =
                    make_float2(acc[mi][nj][2] + bx0, acc[mi][nj][3] + bx1);
            }
        }
    }
}

// ---------------------------------------------------------------------------
// Flash attention v6: fp16 mma, FB_M=128, 8 warps x m16, 256 thr, 2 CTA/SM,
// 4-stage cp.async K/V ring, ONE barrier per iter.
// SMEM fp16: Q 128*72 | K[4] | V[4] (64*72 each) = 92160 bytes.
// ---------------------------------------------------------------------------
#define FB_M   128
#define FSH    72
#define QSZH   (FB_M * FSH)
#define KVSZH  (64 * FSH)
#define FSTG   4
#define FLASH_SMEM ((QSZH + 2 * FSTG * KVSZH) * 2)   // 92160 bytes
#define NT     (SEQ / 64)

__global__ void __launch_bounds__(256, 2) flash_f16()
{
    extern __shared__ __half fsm[];
    const uint32_t sb = smem_u32(fsm);

    const int qt = blockIdx.x, h = blockIdx.y, bz = blockIdx.z;
    const int tid  = threadIdx.x;
    const int wid  = tid >> 5;
    const int lane = tid & 31;
    const int qr   = lane >> 2;
    const int qc   = lane & 3;
    const int rb   = wid * 16;

    const __half* qg = g_qkvh + (size_t)(bz * SEQ + qt * FB_M) * E3 + h * HD;
    const __half* kg = g_qkvh + (size_t)(bz * SEQ) * E3 + EMB     + h * HD;
    const __half* vg = g_qkvh + (size_t)(bz * SEQ) * E3 + 2 * EMB + h * HD;

    // cp.async: threads 0-127 -> K, 128-255 -> V; 64B of one row each
    const int isV  = tid >> 7;
    const int krow = tid & 63;
    const int khc  = (tid >> 6) & 1;
    const uint32_t soffKV = (uint32_t)(krow * FSH + khc * 32) * 2;
    const uint32_t sK0 = sb + QSZH * 2;
    const uint32_t sV0 = sb + (QSZH + FSTG * KVSZH) * 2;
    const __half* kvg   = isV ? vg : kg;
    const uint32_t kvs0 = isV ? sV0 : sK0;

    // prologue: stages 0..2
    #pragma unroll
    for (int s = 0; s < FSTG - 1; s++) {
        const __half* src = kvg + (size_t)(s * 64 + krow) * E3 + khc * 32;
        const uint32_t d = kvs0 + (uint32_t)s * (KVSZH * 2) + soffKV;
        #pragma unroll
        for (int c = 0; c < 4; c++) cp16(d + c * 16, src + c * 8);
        CP_COMMIT();
    }

    // load Q scaled by (1/8)*log2e
    {
        const float qscale = 0.125f * LOG2E;
        const int qrow = tid >> 1;
        const int qh   = tid & 1;
        const __half* src = qg + (size_t)qrow * E3 + qh * 32;
        __half* dst = fsm + qrow * FSH + qh * 32;
        #pragma unroll
        for (int p = 0; p < 4; p++) {
            uint4 raw = *(const uint4*)(src + p * 8);
            const __half2* hp = (const __half2*)&raw;
            __half2 o[4];
            #pragma unroll
            for (int e = 0; e < 4; e++) {
                float2 f = __half22float2(hp[e]);
                o[e] = __floats2half2_rn(f.x * qscale, f.y * qscale);
            }
            *(uint4*)(dst + p * 8) = *(uint4*)o;
        }
    }

    float o[8][4];
    float m_i[2], l_i[2];
    #pragma unroll
    for (int j = 0; j < 8; j++)
        #pragma unroll
        for (int c = 0; c < 4; c++) o[j][c] = 0.0f;
    m_i[0] = m_i[1] = -CUDART_INF_F;
    l_i[0] = l_i[1] = 0.0f;

    const int qb = (rb + qr) * FSH + 2 * qc;
    const uint32_t lmo = (uint32_t)(((lane >> 3) & 1) * 8 + (lane & 7)) * FSH * 2
                       + (uint32_t)((lane >> 4) * 8) * 2;

    for (int t = 0; t < NT; t++) {
        const int buf = t & (FSTG - 1);
        CP_WAIT(2);
        __syncthreads();

        if (t + FSTG - 1 < NT) {
            const int nb = (t + FSTG - 1) & (FSTG - 1);
            const __half* src = kvg + (size_t)((t + FSTG - 1) * 64 + krow) * E3 + khc * 32;
            const uint32_t d = kvs0 + (uint32_t)nb * (KVSZH * 2) + soffKV;
            #pragma unroll
            for (int c = 0; c < 4; c++) cp16(d + c * 16, src + c * 8);
        }
        CP_COMMIT();

        const __half* kb = fsm + QSZH + buf * KVSZH;
        const uint32_t vbase = sV0 + buf * (KVSZH * 2) + lmo;

        // ---- S = Q K^T ----
        float s[8][4];
        #pragma unroll
        for (int j = 0; j < 8; j++)
            #pragma unroll
            for (int c = 0; c < 4; c++) s[j][c] = 0.0f;

        #pragma unroll
        for (int g = 0; g < 4; g++) {
            const __half* qp = fsm + qb + g * 16;
            const uint32_t a0 = *(const uint32_t*)(qp);
            const uint32_t a1 = *(const uint32_t*)(qp + 8 * FSH);
            const uint32_t a2 = *(const uint32_t*)(qp + 8);
            const uint32_t a3 = *(const uint32_t*)(qp + 8 * FSH + 8);
            #pragma unroll
            for (int j = 0; j < 8; j++) {
                const __half* kp = kb + (j * 8 + qr) * FSH + g * 16 + 2 * qc;
                mma_f16(s[j], a0, a1, a2, a3,
                        *(const uint32_t*)(kp), *(const uint32_t*)(kp + 8));
            }
        }

        // ---- online softmax (exp2 domain) ----
        #pragma unroll
        for (int hf = 0; hf < 2; hf++) {
            float tm = -CUDART_INF_F;
            #pragma unroll
            for (int j = 0; j < 8; j++)
                tm = fmaxf(tm, fmaxf(s[j][hf * 2], s[j][hf * 2 + 1]));
            tm = fmaxf(tm, __shfl_xor_sync(0xffffffffu, tm, 1));
            tm = fmaxf(tm, __shfl_xor_sync(0xffffffffu, tm, 2));
            const float mnew  = fmaxf(m_i[hf], tm);
            const float alpha = exp2f(m_i[hf] - mnew);
            float ps = 0.0f;
            #pragma unroll
            for (int j = 0; j < 8; j++) {
                const float p0 = exp2f(s[j][hf * 2]     - mnew);
                const float p1 = exp2f(s[j][hf * 2 + 1] - mnew);
                s[j][hf * 2]     = p0;
                s[j][hf * 2 + 1] = p1;
                ps += p0 + p1;
            }
            ps += __shfl_xor_sync(0xffffffffu, ps, 1);
            ps += __shfl_xor_sync(0xffffffffu, ps, 2);
            l_i[hf] = l_i[hf] * alpha + ps;
            m_i[hf] = mnew;
            #pragma unroll
            for (int j = 0; j < 8; j++) {
                o[j][hf * 2]     *= alpha;
                o[j][hf * 2 + 1] *= alpha;
            }
        }

        // ---- O += P V ----
        #pragma unroll
        for (int g = 0; g < 4; g++) {
            uint32_t pa0, pa1, pa2, pa3;
            {
                __half2 t0 = __floats2half2_rn(s[2 * g][0],     s[2 * g][1]);
                __half2 t1 = __floats2half2_rn(s[2 * g][2],     s[2 * g][3]);
                __half2 t2 = __floats2half2_rn(s[2 * g + 1][0], s[2 * g + 1][1]);
                __half2 t3 = __floats2half2_rn(s[2 * g + 1][2], s[2 * g + 1][3]);
                pa0 = *(uint32_t*)&t0; pa1 = *(uint32_t*)&t1;
                pa2 = *(uint32_t*)&t2; pa3 = *(uint32_t*)&t3;
            }
            #pragma unroll
            for (int jp = 0; jp < 4; jp++) {
                uint32_t b0, b1, b2, b3;
                ldsm_x4_trans(b0, b1, b2, b3,
                              vbase + (uint32_t)(g * 16) * FSH * 2
                                    + (uint32_t)(jp * 16) * 2);
                mma_f16(o[2 * jp],     pa0, pa1, pa2, pa3, b0, b1);
                mma_f16(o[2 * jp + 1], pa0, pa1, pa2, pa3, b2, b3);
            }
        }
    }

    // ---- epilogue ----
    const float inv0 = 1.0f / l_i[0];
    const float inv1 = 1.0f / l_i[1];
    const size_t row0 = (size_t)(bz * SEQ + qt * FB_M + rb + qr);
    #pragma unroll
    for (int j = 0; j < 8; j++) {
        const int col = h * HD + j * 8 + 2 * qc;
        *(__half2*)(g_attnh + row0 * EMB + col) =
            __floats2half2_rn(o[j][0] * inv0, o[j][1] * inv0);
        *(__half2*)(g_attnh + (row0 + 8) * EMB + col) =
            __floats2half2_rn(o[j][2] * inv1, o[j][3] * inv1);
    }
}

// ---------------------------------------------------------------------------
extern "C" void kernel_launch(void* const* d_in, const int* in_sizes, int n_in,
                              void* d_out, int out_size)
{
    (void)in_sizes; (void)n_in; (void)out_size;
    const float* x     = (const float*)d_in[0];
    const float* w_in  = (const float*)d_in[1];
    const float* b_in  = (const float*)d_in[2];
    const float* w_out = (const float*)d_in[3];
    const float* b_out = (const float*)d_in[4];
    float* out = (float*)d_out;

    void *xh_p, *qkv_p, *attn_p, *wti_p, *wto_p;
    cudaGetSymbolAddress(&xh_p,   g_xh);
    cudaGetSymbolAddress(&qkv_p,  g_qkvh);
    cudaGetSymbolAddress(&attn_p, g_attnh);
    cudaGetSymbolAddress(&wti_p,  g_wti);
    cudaGetSymbolAddress(&wto_p,  g_wto);

    cudaFuncSetAttribute(flash_f16, cudaFuncAttributeMaxDynamicSharedMemorySize,
                         FLASH_SMEM);
    cudaFuncSetAttribute(gemm_f16, cudaFuncAttributeMaxDynamicSharedMemorySize,
                         GEMM_SMEM);

    // 0) conversions: x -> fp16, weights -> fp16 transposed [N][K]
    cvt_x_half<<<(MTOT * EMB) / (256 * 8), 256>>>(x, (__half*)xh_p);
    transpose_h<<<dim3(E3 / 32, EMB / 32), dim3(32, 8)>>>(w_in,  (__half*)wti_p, EMB, E3);
    transpose_h<<<dim3(EMB / 32, EMB / 32), dim3(32, 8)>>>(w_out, (__half*)wto_p, EMB, EMB);

    // 1) QKV projection (fp16 mma, fp16 out)
    gemm_f16<<<dim3(E3 / 128, MTOT / 128), 256, GEMM_SMEM>>>(
        E3, EMB, (const __half*)xh_p, (const __half*)wti_p, b_in,
        (__half*)qkv_p, nullptr);

    // 2) Attention (fp16 flash, 4-stage ring)
    flash_f16<<<dim3(SEQ / FB_M, NH, BATCH), 256, FLASH_SMEM>>>();

    // 3) Output projection (fp16 mma, fp32 out)
    gemm_f16<<<dim3(EMB / 128, MTOT / 128), 256, GEMM_SMEM>>>(
        EMB, EMB, (const __half*)attn_p, (const __half*)wto_p, b_out,
        nullptr, out);
}

// round 11
// speedup vs baseline: 6.6903x; 1.5191x over previous
#include <cuda_runtime.h>
#include <cuda_fp16.h>
#include <math_constants.h>
#include <cstdint>

// Problem constants
#define BATCH 2
#define SEQ   2048
#define EMB   1024
#define E3    3072
#define NH    16
#define HD    64
#define MTOT  (BATCH*SEQ)   // 4096

// Scratch (static device globals — no cudaMalloc allowed)
__device__ __half g_xh   [(size_t)MTOT * EMB];   // x as fp16
__device__ __half g_qkvh [(size_t)MTOT * E3];    // qkv fp16
__device__ __half g_attnh[(size_t)MTOT * EMB];   // attn fp16
__device__ __half g_wti  [(size_t)E3 * EMB];     // w_in^T  fp16 [3072][1024]
__device__ __half g_wto  [(size_t)EMB * EMB];    // w_out^T fp16 [1024][1024]

#define LOG2E 1.4426950408889634f

// ---------------------------------------------------------------------------
__device__ __forceinline__ void mma_f16(float c[4], uint32_t a0, uint32_t a1,
                                        uint32_t a2, uint32_t a3,
                                        uint32_t b0, uint32_t b1) {
    asm volatile(
        "mma.sync.aligned.m16n8k16.row.col.f32.f16.f16.f32 "
        "{%0,%1,%2,%3}, {%4,%5,%6,%7}, {%8,%9}, {%0,%1,%2,%3};"
        : "+f"(c[0]), "+f"(c[1]), "+f"(c[2]), "+f"(c[3])
        : "r"(a0), "r"(a1), "r"(a2), "r"(a3), "r"(b0), "r"(b1));
}

__device__ __forceinline__ uint32_t smem_u32(const void* p) {
    uint32_t a;
    asm("{ .reg .u64 t; cvta.to.shared.u64 t, %1; cvt.u32.u64 %0, t; }" : "=r"(a) : "l"(p));
    return a;
}
__device__ __forceinline__ void cp16(uint32_t saddr, const void* gaddr) {
    asm volatile("cp.async.cg.shared.global [%0], [%1], 16;" :: "r"(saddr), "l"(gaddr));
}
#define CP_COMMIT() asm volatile("cp.async.commit_group;" ::: "memory")
#define CP_WAIT(n)  asm volatile("cp.async.wait_group %0;" :: "n"(n) : "memory")

__device__ __forceinline__ void ldsm_x4_trans(uint32_t& r0, uint32_t& r1,
                                              uint32_t& r2, uint32_t& r3,
                                              uint32_t addr) {
    asm volatile("ldmatrix.sync.aligned.m8n8.x4.trans.shared.b16 "
                 "{%0,%1,%2,%3}, [%4];"
                 : "=r"(r0), "=r"(r1), "=r"(r2), "=r"(r3) : "r"(addr));
}

// ---------------------------------------------------------------------------
// x fp32 -> fp16 (8 elems/thread)
// ---------------------------------------------------------------------------
__global__ void __launch_bounds__(256) cvt_x_half(
    const float* __restrict__ in, __half* __restrict__ out)
{
    const size_t i = ((size_t)blockIdx.x * 256 + threadIdx.x) * 8;
    const float4 f0 = *(const float4*)(in + i);
    const float4 f1 = *(const float4*)(in + i + 4);
    __half2 h[4];
    h[0] = __floats2half2_rn(f0.x, f0.y);
    h[1] = __floats2half2_rn(f0.z, f0.w);
    h[2] = __floats2half2_rn(f1.x, f1.y);
    h[3] = __floats2half2_rn(f1.z, f1.w);
    *(uint4*)(out + i) = *(uint4*)h;
}

// ---------------------------------------------------------------------------
// Transpose fp32 -> fp16: out[C][R] = half(in[R][C]^T)
// ---------------------------------------------------------------------------
__global__ void __launch_bounds__(256) transpose_h(
    const float* __restrict__ in, __half* __restrict__ out, int R, int C)
{
    __shared__ float t[32][33];
    const int bx = blockIdx.x * 32;
    const int by = blockIdx.y * 32;
    const int x = bx + threadIdx.x;
    #pragma unroll
    for (int j = 0; j < 4; j++) {
        const int y = by + threadIdx.y + j * 8;
        t[threadIdx.y + j * 8][threadIdx.x] = in[(size_t)y * C + x];
    }
    __syncthreads();
    const int x2 = by + threadIdx.x;
    #pragma unroll
    for (int j = 0; j < 4; j++) {
        const int y2 = bx + threadIdx.y + j * 8;
        out[(size_t)y2 * R + x2] = __float2half_rn(t[threadIdx.x][threadIdx.y + j * 8]);
    }
}

// ---------------------------------------------------------------------------
// fp16 mma GEMM v5: C = A[M,K] @ Bt[N,K]^T + bias.
// CTA 128x128, 8 warps (4x2), warp 32x64, BK=64, 3-stage cp.async ring.
// SMEM rows = 64 halves (128B, full lines), chunk-XOR swizzle:
//   addr(row, chunk, off) = row*64 + ((chunk ^ (row&7))<<3) + off   [halves]
// Coalesced cp.async: warp-instr covers 4 full 128B lines (4 wavefronts).
// Verified conflict-free: cp.async stores, a-frag & b-frag LDS.32 phases.
// ---------------------------------------------------------------------------
#define GSTGH  8192                        // halves per stage per matrix (128*64)
#define GSTG   3
#define GEMM_SMEM (2 * GSTG * GSTGH * 2)   // 98304 bytes

__global__ void __launch_bounds__(256, 2) gemm_f16(
    int N, int K,
    const __half* __restrict__ A,
    const __half* __restrict__ Bt,
    const float* __restrict__ bias,
    __half* __restrict__ Ch,
    float* __restrict__ Cf)
{
    extern __shared__ __half gsm[];
    __half* sA = gsm;                      // [GSTG][GSTGH]
    __half* sB = gsm + GSTG * GSTGH;
    const uint32_t sbA = smem_u32(sA);
    const uint32_t sbB = smem_u32(sB);

    const int tid  = threadIdx.x;
    const int wid  = tid >> 5;
    const int lane = tid & 31;
    const int wm   = wid >> 1;             // 0..3 : 32-row slice
    const int wn   = wid & 1;              // 0..1 : 64-col slice
    const int qr   = lane >> 2;
    const int qc   = lane & 3;

    // coalesced cp.async mapping: chunk = tid&7 (16B), base row = tid>>3
    const int cch = tid & 7;
    const int cr0 = tid >> 3;              // 0..31
    const uint32_t cx = (uint32_t)((cch ^ (cr0 & 7)) << 3);  // halves
    const __half* Ag = A  + (size_t)blockIdx.y * 128 * K + cch * 8;
    const __half* Bg = Bt + (size_t)blockIdx.x * 128 * K + cch * 8;

    float acc[2][8][4];
    #pragma unroll
    for (int i = 0; i < 2; i++)
        #pragma unroll
        for (int j = 0; j < 8; j++)
            #pragma unroll
            for (int c = 0; c < 4; c++) acc[i][j][c] = 0.0f;

    const int KT = K / 64;

    // prologue: stages 0,1
    #pragma unroll
    for (int s = 0; s < GSTG - 1; s++) {
        #pragma unroll
        for (int i = 0; i < 4; i++) {
            const int row = cr0 + 32 * i;
            const uint32_t d = (uint32_t)(row * 64) + cx;
            cp16(sbA + ((uint32_t)s * GSTGH + d) * 2, Ag + (size_t)row * K + s * 64);
            cp16(sbB + ((uint32_t)s * GSTGH + d) * 2, Bg + (size_t)row * K + s * 64);
        }
        CP_COMMIT();
    }

    // fragment bases (halves within a stage)
    const int aBase = (wm * 32 + qr) * 64 + 2 * qc;
    const int bBase = (wn * 64 + qr) * 64 + 2 * qc;

    for (int t = 0; t < KT; t++) {
        const int buf = (t < GSTG) ? t : (t % GSTG);
        CP_WAIT(1);
        __syncthreads();

        if (t + GSTG - 1 < KT) {
            const int nb = (t + GSTG - 1) % GSTG;
            const int k0 = (t + GSTG - 1) * 64;
            #pragma unroll
            for (int i = 0; i < 4; i++) {
                const int row = cr0 + 32 * i;
                const uint32_t d = (uint32_t)(row * 64) + cx;
                cp16(sbA + ((uint32_t)nb * GSTGH + d) * 2, Ag + (size_t)row * K + k0);
                cp16(sbB + ((uint32_t)nb * GSTGH + d) * 2, Bg + (size_t)row * K + k0);
            }
        }
        CP_COMMIT();

        const __half* pa = sA + buf * GSTGH + aBase;
        const __half* pb = sB + buf * GSTGH + bBase;

        #pragma unroll
        for (int g = 0; g < 4; g++) {
            const int x0 = ((2 * g)     ^ qr) << 3;
            const int x1 = ((2 * g + 1) ^ qr) << 3;
            uint32_t af[2][4];
            #pragma unroll
            for (int mt = 0; mt < 2; mt++) {
                const __half* p = pa + mt * 16 * 64;
                af[mt][0] = *(const uint32_t*)(p + x0);
                af[mt][1] = *(const uint32_t*)(p + x0 + 512);
                af[mt][2] = *(const uint32_t*)(p + x1);
                af[mt][3] = *(const uint32_t*)(p + x1 + 512);
            }
            #pragma unroll
            for (int j = 0; j < 8; j++) {
                const __half* p = pb + j * 512;
                const uint32_t b0 = *(const uint32_t*)(p + x0);
                const uint32_t b1 = *(const uint32_t*)(p + x1);
                mma_f16(acc[0][j], af[0][0], af[0][1], af[0][2], af[0][3], b0, b1);
                mma_f16(acc[1][j], af[1][0], af[1][1], af[1][2], af[1][3], b0, b1);
            }
        }
    }

    const int mBase = blockIdx.y * 128 + wm * 32;
    const int nBase = blockIdx.x * 128 + wn * 64;
    #pragma unroll
    for (int mi = 0; mi < 2; mi++) {
        #pragma unroll
        for (int nj = 0; nj < 8; nj++) {
            const int col = nBase + nj * 8 + qc * 2;
            const float bx0 = bias[col], bx1 = bias[col + 1];
            const int r0 = mBase + mi * 16 + qr;
            if (Ch) {
                *(__half2*)(Ch + (size_t)r0 * N + col) =
                    __floats2half2_rn(acc[mi][nj][0] + bx0, acc[mi][nj][1] + bx1);
                *(__half2*)(Ch + (size_t)(r0 + 8) * N + col) =
                    __floats2half2_rn(acc[mi][nj][2] + bx0, acc[mi][nj][3] + bx1);
            } else {
                *(float2*)(Cf + (size_t)r0 * N + col) =
                    make_float2(acc[mi][nj][0] + bx0, acc[mi][nj][1] + bx1);
                *(float2*)(Cf + (size_t)(r0 + 8) * N + col) =
                    make_float2(acc[mi][nj][2] + bx0, acc[mi][nj][3] + bx1);
            }
        }
    }
}

// ---------------------------------------------------------------------------
// Flash attention v7: fp16 mma, FB_M=128, 8 warps x m16, 256 thr, 2 CTA/SM.
// 4-stage coalesced cp.async K/V ring (128B rows, chunk-XOR swizzle),
// Q fragments held in registers, h2exp2 softmax (P born as half2 A-frags),
// skip o-rescale when warp max unchanged.
// SMEM halves: Q 8192 | K[4]*4096 | V[4]*4096 = 40960 halves = 80KB.
// ---------------------------------------------------------------------------
#define FB_M   128
#define QSZH2  8192
#define KVH    4096
#define FSTG   4
#define FLASH_SMEM ((QSZH2 + 2 * FSTG * KVH) * 2)   // 81920 bytes
#define NT     (SEQ / 64)

__global__ void __launch_bounds__(256, 2) flash_f16()
{
    extern __shared__ __half fsm[];
    const uint32_t sb = smem_u32(fsm);

    const int qt = blockIdx.x, h = blockIdx.y, bz = blockIdx.z;
    const int tid  = threadIdx.x;
    const int lane = tid & 31;
    const int wid  = tid >> 5;
    const int qr   = lane >> 2;
    const int qc   = lane & 3;
    const int rb   = wid * 16;

    const __half* qg = g_qkvh + (size_t)(bz * SEQ + qt * FB_M) * E3 + h * HD;
    const __half* kg = g_qkvh + (size_t)(bz * SEQ) * E3 + EMB     + h * HD;
    const __half* vg = g_qkvh + (size_t)(bz * SEQ) * E3 + 2 * EMB + h * HD;

    // coalesced cp.async: threads 0-127 -> K, 128-255 -> V
    const int isV = tid >> 7;
    const int tt  = tid & 127;
    const int cch = tt & 7;                // 16B chunk
    const int cr0 = tt >> 3;               // 0..15
    const uint32_t cx = (uint32_t)((cch ^ (cr0 & 7)) << 3);
    const uint32_t sK0 = sb + QSZH2 * 2;
    const uint32_t sV0 = sK0 + FSTG * KVH * 2;
    const __half* kvg   = isV ? vg : kg;
    const uint32_t kvs0 = isV ? sV0 : sK0;

    // prologue: K/V stages 0..2
    #pragma unroll
    for (int s = 0; s < FSTG - 1; s++) {
        #pragma unroll
        for (int i = 0; i < 4; i++) {
            const int row = cr0 + 16 * i;
            cp16(kvs0 + ((uint32_t)s * KVH + row * 64 + cx) * 2,
                 kvg + (size_t)(s * 64 + row) * E3 + cch * 8);
        }
        CP_COMMIT();
    }

    // stage Q into swizzled smem (scaled by (1/8)*log2e)
    {
        const float qs = 0.125f * LOG2E;
        const int row = tid >> 1;
        const int hh  = tid & 1;
        const __half* src = qg + (size_t)row * E3 + hh * 32;
        #pragma unroll
        for (int i = 0; i < 4; i++) {
            const int c = hh * 4 + i;
            uint4 raw = *(const uint4*)(src + i * 8);
            const __half2* hp = (const __half2*)&raw;
            __half2 o4[4];
            #pragma unroll
            for (int e = 0; e < 4; e++) {
                float2 f = __half22float2(hp[e]);
                o4[e] = __floats2half2_rn(f.x * qs, f.y * qs);
            }
            *(uint4*)(fsm + row * 64 + ((c ^ (row & 7)) << 3)) = *(uint4*)o4;
        }
    }
    __syncthreads();

    // load Q fragments into registers (held across the whole loop)
    uint32_t qf[4][4];
    {
        const __half* pq = fsm + (rb + qr) * 64 + 2 * qc;
        #pragma unroll
        for (int g = 0; g < 4; g++) {
            const int x0 = ((2 * g)     ^ qr) << 3;
            const int x1 = ((2 * g + 1) ^ qr) << 3;
            qf[g][0] = *(const uint32_t*)(pq + x0);
            qf[g][1] = *(const uint32_t*)(pq + x0 + 512);
            qf[g][2] = *(const uint32_t*)(pq + x1);
            qf[g][3] = *(const uint32_t*)(pq + x1 + 512);
        }
    }

    float o[8][4];
    float m_i[2], l_i[2];
    #pragma unroll
    for (int j = 0; j < 8; j++)
        #pragma unroll
        for (int c = 0; c < 4; c++) o[j][c] = 0.0f;
    m_i[0] = m_i[1] = -CUDART_INF_F;
    l_i[0] = l_i[1] = 0.0f;

    // ldmatrix(trans) lane geometry for V
    const int vrow_l = (lane & 7) + ((lane >> 3) & 1) * 8;  // 0..15
    const int vcb    = (lane >> 4);                          // chunk base 0/1
    const int vx     = lane & 7;

    for (int t = 0; t < NT; t++) {
        const int buf = t & (FSTG - 1);
        CP_WAIT(2);
        __syncthreads();

        if (t + FSTG - 1 < NT) {
            const int nb = (t + FSTG - 1) & (FSTG - 1);
            #pragma unroll
            for (int i = 0; i < 4; i++) {
                const int row = cr0 + 16 * i;
                cp16(kvs0 + ((uint32_t)nb * KVH + row * 64 + cx) * 2,
                     kvg + (size_t)((t + FSTG - 1) * 64 + row) * E3 + cch * 8);
            }
        }
        CP_COMMIT();

        const __half* kb = fsm + QSZH2 + buf * KVH;
        const uint32_t vst = sV0 + (uint32_t)buf * KVH * 2;

        // ---- S = Q K^T ----
        float s[8][4];
        #pragma unroll
        for (int j = 0; j < 8; j++)
            #pragma unroll
            for (int c = 0; c < 4; c++) s[j][c] = 0.0f;

        #pragma unroll
        for (int g = 0; g < 4; g++) {
            const int x0 = ((2 * g)     ^ qr) << 3;
            const int x1 = ((2 * g + 1) ^ qr) << 3;
            #pragma unroll
            for (int j = 0; j < 8; j++) {
                const __half* kp = kb + (j * 8 + qr) * 64 + 2 * qc;
                mma_f16(s[j], qf[g][0], qf[g][1], qf[g][2], qf[g][3],
                        *(const uint32_t*)(kp + x0), *(const uint32_t*)(kp + x1));
            }
        }

        // ---- online softmax (exp2 domain, fp16 P) ----
        __half2 ph[8][2];
        #pragma unroll
        for (int hf = 0; hf < 2; hf++) {
            float tm = -CUDART_INF_F;
            #pragma unroll
            for (int j = 0; j < 8; j++)
                tm = fmaxf(tm, fmaxf(s[j][hf * 2], s[j][hf * 2 + 1]));
            tm = fmaxf(tm, __shfl_xor_sync(0xffffffffu, tm, 1));
            tm = fmaxf(tm, __shfl_xor_sync(0xffffffffu, tm, 2));
            const float mnew = fmaxf(m_i[hf], tm);
            const bool chg = __any_sync(0xffffffffu, mnew != m_i[hf]);
            float ps = 0.0f;
            #pragma unroll
            for (int j = 0; j < 8; j++) {
                __half2 e = h2exp2(__floats2half2_rn(s[j][hf * 2]     - mnew,
                                                     s[j][hf * 2 + 1] - mnew));
                ph[j][hf] = e;
                const float2 f = __half22float2(e);
                ps += f.x + f.y;
            }
            ps += __shfl_xor_sync(0xffffffffu, ps, 1);
            ps += __shfl_xor_sync(0xffffffffu, ps, 2);
            if (chg) {
                const float alpha = exp2f(m_i[hf] - mnew);
                l_i[hf] = l_i[hf] * alpha + ps;
                m_i[hf] = mnew;
                #pragma unroll
                for (int j = 0; j < 8; j++) {
                    o[j][hf * 2]     *= alpha;
                    o[j][hf * 2 + 1] *= alpha;
                }
            } else {
                l_i[hf] += ps;
            }
        }

        // ---- O += P V : A frags = ph directly; B via ldmatrix.x4.trans ----
        #pragma unroll
        for (int g = 0; g < 4; g++) {
            const uint32_t pa0 = *(const uint32_t*)&ph[2 * g][0];
            const uint32_t pa1 = *(const uint32_t*)&ph[2 * g][1];
            const uint32_t pa2 = *(const uint32_t*)&ph[2 * g + 1][0];
            const uint32_t pa3 = *(const uint32_t*)&ph[2 * g + 1][1];
            #pragma unroll
            for (int jp = 0; jp < 4; jp++) {
                uint32_t b0, b1, b2, b3;
                const uint32_t off =
                    (uint32_t)((g * 16 + vrow_l) * 64 +
                               (((jp * 2 + vcb) ^ vx) << 3)) * 2;
                ldsm_x4_trans(b0, b1, b2, b3, vst + off);
                mma_f16(o[2 * jp],     pa0, pa1, pa2, pa3, b0, b1);
                mma_f16(o[2 * jp + 1], pa0, pa1, pa2, pa3, b2, b3);
            }
        }
    }

    // ---- epilogue ----
    const float inv0 = 1.0f / l_i[0];
    const float inv1 = 1.0f / l_i[1];
    const size_t row0 = (size_t)(bz * SEQ + qt * FB_M + rb + qr);
    #pragma unroll
    for (int j = 0; j < 8; j++) {
        const int col = h * HD + j * 8 + 2 * qc;
        *(__half2*)(g_attnh + row0 * EMB + col) =
            __floats2half2_rn(o[j][0] * inv0, o[j][1] * inv0);
        *(__half2*)(g_attnh + (row0 + 8) * EMB + col) =
            __floats2half2_rn(o[j][2] * inv1, o[j][3] * inv1);
    }
}

// ---------------------------------------------------------------------------
extern "C" void kernel_launch(void* const* d_in, const int* in_sizes, int n_in,
                              void* d_out, int out_size)
{
    (void)in_sizes; (void)n_in; (void)out_size;
    const float* x     = (const float*)d_in[0];
    const float* w_in  = (const float*)d_in[1];
    const float* b_in  = (const float*)d_in[2];
    const float* w_out = (const float*)d_in[3];
    const float* b_out = (const float*)d_in[4];
    float* out = (float*)d_out;

    void *xh_p, *qkv_p, *attn_p, *wti_p, *wto_p;
    cudaGetSymbolAddress(&xh_p,   g_xh);
    cudaGetSymbolAddress(&qkv_p,  g_qkvh);
    cudaGetSymbolAddress(&attn_p, g_attnh);
    cudaGetSymbolAddress(&wti_p,  g_wti);
    cudaGetSymbolAddress(&wto_p,  g_wto);

    cudaFuncSetAttribute(flash_f16, cudaFuncAttributeMaxDynamicSharedMemorySize,
                         FLASH_SMEM);
    cudaFuncSetAttribute(gemm_f16, cudaFuncAttributeMaxDynamicSharedMemorySize,
                         GEMM_SMEM);

    // 0) conversions: x -> fp16, weights -> fp16 transposed [N][K]
    cvt_x_half<<<(MTOT * EMB) / (256 * 8), 256>>>(x, (__half*)xh_p);
    transpose_h<<<dim3(E3 / 32, EMB / 32), dim3(32, 8)>>>(w_in,  (__half*)wti_p, EMB, E3);
    transpose_h<<<dim3(EMB / 32, EMB / 32), dim3(32, 8)>>>(w_out, (__half*)wto_p, EMB, EMB);

    // 1) QKV projection (fp16 mma, fp16 out)
    gemm_f16<<<dim3(E3 / 128, MTOT / 128), 256, GEMM_SMEM>>>(
        E3, EMB, (const __half*)xh_p, (const __half*)wti_p, b_in,
        (__half*)qkv_p, nullptr);

    // 2) Attention (fp16 flash v7)
    flash_f16<<<dim3(SEQ / FB_M, NH, BATCH), 256, FLASH_SMEM>>>();

    // 3) Output projection (fp16 mma, fp32 out)
    gemm_f16<<<dim3(EMB / 128, MTOT / 128), 256, GEMM_SMEM>>>(
        EMB, EMB, (const __half*)attn_p, (const __half*)wto_p, b_out,
        nullptr, out);
}

// round 12
// speedup vs baseline: 7.0517x; 1.0540x over previous
#include <cuda_runtime.h>
#include <cuda_fp16.h>
#include <math_constants.h>
#include <cstdint>

// Problem constants
#define BATCH 2
#define SEQ   2048
#define EMB   1024
#define E3    3072
#define NH    16
#define HD    64
#define MTOT  (BATCH*SEQ)   // 4096

// Scratch (static device globals — no cudaMalloc allowed)
__device__ __half g_xh   [(size_t)MTOT * EMB];   // x as fp16
__device__ __half g_qkvh [(size_t)MTOT * E3];    // qkv fp16
__device__ __half g_attnh[(size_t)MTOT * EMB];   // attn fp16
__device__ __half g_wti  [(size_t)E3 * EMB];     // w_in^T  fp16 [3072][1024]
__device__ __half g_wto  [(size_t)EMB * EMB];    // w_out^T fp16 [1024][1024]

#define LOG2E 1.4426950408889634f

// ---------------------------------------------------------------------------
__device__ __forceinline__ void mma_f16(float c[4], uint32_t a0, uint32_t a1,
                                        uint32_t a2, uint32_t a3,
                                        uint32_t b0, uint32_t b1) {
    asm volatile(
        "mma.sync.aligned.m16n8k16.row.col.f32.f16.f16.f32 "
        "{%0,%1,%2,%3}, {%4,%5,%6,%7}, {%8,%9}, {%0,%1,%2,%3};"
        : "+f"(c[0]), "+f"(c[1]), "+f"(c[2]), "+f"(c[3])
        : "r"(a0), "r"(a1), "r"(a2), "r"(a3), "r"(b0), "r"(b1));
}

__device__ __forceinline__ uint32_t smem_u32(const void* p) {
    uint32_t a;
    asm("{ .reg .u64 t; cvta.to.shared.u64 t, %1; cvt.u32.u64 %0, t; }" : "=r"(a) : "l"(p));
    return a;
}
__device__ __forceinline__ void cp16(uint32_t saddr, const void* gaddr) {
    asm volatile("cp.async.cg.shared.global [%0], [%1], 16;" :: "r"(saddr), "l"(gaddr));
}
#define CP_COMMIT() asm volatile("cp.async.commit_group;" ::: "memory")
#define CP_WAIT(n)  asm volatile("cp.async.wait_group %0;" :: "n"(n) : "memory")

__device__ __forceinline__ void ldsm_x4(uint32_t& r0, uint32_t& r1,
                                        uint32_t& r2, uint32_t& r3,
                                        uint32_t addr) {
    asm volatile("ldmatrix.sync.aligned.m8n8.x4.shared.b16 "
                 "{%0,%1,%2,%3}, [%4];"
                 : "=r"(r0), "=r"(r1), "=r"(r2), "=r"(r3) : "r"(addr));
}
__device__ __forceinline__ void ldsm_x4_trans(uint32_t& r0, uint32_t& r1,
                                              uint32_t& r2, uint32_t& r3,
                                              uint32_t addr) {
    asm volatile("ldmatrix.sync.aligned.m8n8.x4.trans.shared.b16 "
                 "{%0,%1,%2,%3}, [%4];"
                 : "=r"(r0), "=r"(r1), "=r"(r2), "=r"(r3) : "r"(addr));
}

// ---------------------------------------------------------------------------
// x fp32 -> fp16 (8 elems/thread)
// ---------------------------------------------------------------------------
__global__ void __launch_bounds__(256) cvt_x_half(
    const float* __restrict__ in, __half* __restrict__ out)
{
    const size_t i = ((size_t)blockIdx.x * 256 + threadIdx.x) * 8;
    const float4 f0 = *(const float4*)(in + i);
    const float4 f1 = *(const float4*)(in + i + 4);
    __half2 h[4];
    h[0] = __floats2half2_rn(f0.x, f0.y);
    h[1] = __floats2half2_rn(f0.z, f0.w);
    h[2] = __floats2half2_rn(f1.x, f1.y);
    h[3] = __floats2half2_rn(f1.z, f1.w);
    *(uint4*)(out + i) = *(uint4*)h;
}

// ---------------------------------------------------------------------------
// Transpose fp32 -> fp16: out[C][R] = half(in[R][C]^T)
// ---------------------------------------------------------------------------
__global__ void __launch_bounds__(256) transpose_h(
    const float* __restrict__ in, __half* __restrict__ out, int R, int C)
{
    __shared__ float t[32][33];
    const int bx = blockIdx.x * 32;
    const int by = blockIdx.y * 32;
    const int x = bx + threadIdx.x;
    #pragma unroll
    for (int j = 0; j < 4; j++) {
        const int y = by + threadIdx.y + j * 8;
        t[threadIdx.y + j * 8][threadIdx.x] = in[(size_t)y * C + x];
    }
    __syncthreads();
    const int x2 = by + threadIdx.x;
    #pragma unroll
    for (int j = 0; j < 4; j++) {
        const int y2 = bx + threadIdx.y + j * 8;
        out[(size_t)y2 * R + x2] = __float2half_rn(t[threadIdx.x][threadIdx.y + j * 8]);
    }
}

// ---------------------------------------------------------------------------
// fp16 mma GEMM v6: C = A[M,K] @ Bt[N,K]^T + bias.
// CTA 128x128, 8 warps (4x2), warp 32x64, BK=64, 3-stage cp.async ring.
// SMEM rows = 64 halves (128B lines), chunk-XOR swizzle
//   addr(row, chunk) = row*64 + ((chunk ^ (row&7))<<3)   [halves]
// All fragments via ldmatrix.x4 (24 LDSM vs 96 LDS.32 per warp-iter).
// ---------------------------------------------------------------------------
#define GSTGH  8192
#define GSTG   3
#define GEMM_SMEM (2 * GSTG * GSTGH * 2)   // 98304 bytes

__global__ void __launch_bounds__(256, 2) gemm_f16(
    int N, int K,
    const __half* __restrict__ A,
    const __half* __restrict__ Bt,
    const float* __restrict__ bias,
    __half* __restrict__ Ch,
    float* __restrict__ Cf)
{
    extern __shared__ __half gsm[];
    const uint32_t sbA = smem_u32(gsm);
    const uint32_t sbB = sbA + GSTG * GSTGH * 2;

    const int tid  = threadIdx.x;
    const int wid  = tid >> 5;
    const int lane = tid & 31;
    const int wm   = wid >> 1;
    const int wn   = wid & 1;
    const int qr   = lane >> 2;
    const int qc   = lane & 3;

    // ldmatrix lane geometry
    const int arow = ((lane >> 3) & 1) * 8 + (lane & 7);   // A-frag row offset
    const int achk = lane >> 4;                            // A-frag chunk bit
    const int brow = ((lane >> 4) & 1) * 8 + (lane & 7);   // B-frag row offset
    const int bchk = (lane >> 3) & 1;                      // B-frag chunk bit

    // coalesced cp.async mapping
    const int cch = tid & 7;
    const int cr0 = tid >> 3;
    const uint32_t cx = (uint32_t)((cch ^ (cr0 & 7)) << 3);
    const __half* Ag = A  + (size_t)blockIdx.y * 128 * K + cch * 8;
    const __half* Bg = Bt + (size_t)blockIdx.x * 128 * K + cch * 8;

    float acc[2][8][4];
    #pragma unroll
    for (int i = 0; i < 2; i++)
        #pragma unroll
        for (int j = 0; j < 8; j++)
            #pragma unroll
            for (int c = 0; c < 4; c++) acc[i][j][c] = 0.0f;

    const int KT = K / 64;

    #pragma unroll
    for (int s = 0; s < GSTG - 1; s++) {
        #pragma unroll
        for (int i = 0; i < 4; i++) {
            const int row = cr0 + 32 * i;
            const uint32_t d = (uint32_t)(row * 64) + cx;
            cp16(sbA + ((uint32_t)s * GSTGH + d) * 2, Ag + (size_t)row * K + s * 64);
            cp16(sbB + ((uint32_t)s * GSTGH + d) * 2, Bg + (size_t)row * K + s * 64);
        }
        CP_COMMIT();
    }

    for (int t = 0; t < KT; t++) {
        const int buf = (t < GSTG) ? t : (t % GSTG);
        CP_WAIT(1);
        __syncthreads();

        if (t + GSTG - 1 < KT) {
            const int nb = (t + GSTG - 1) % GSTG;
            const int k0 = (t + GSTG - 1) * 64;
            #pragma unroll
            for (int i = 0; i < 4; i++) {
                const int row = cr0 + 32 * i;
                const uint32_t d = (uint32_t)(row * 64) + cx;
                cp16(sbA + ((uint32_t)nb * GSTGH + d) * 2, Ag + (size_t)row * K + k0);
                cp16(sbB + ((uint32_t)nb * GSTGH + d) * 2, Bg + (size_t)row * K + k0);
            }
        }
        CP_COMMIT();

        const uint32_t pA = sbA + (uint32_t)buf * GSTGH * 2;
        const uint32_t pB = sbB + (uint32_t)buf * GSTGH * 2;

        #pragma unroll
        for (int g = 0; g < 4; g++) {
            // A fragments: 2 ldmatrix.x4 (one per 16-row m-tile)
            uint32_t af[2][4];
            #pragma unroll
            for (int mt = 0; mt < 2; mt++) {
                const int row = wm * 32 + mt * 16 + arow;
                const int ch  = 2 * g + achk;
                ldsm_x4(af[mt][0], af[mt][1], af[mt][2], af[mt][3],
                        pA + (uint32_t)(row * 64 + ((ch ^ (row & 7)) << 3)) * 2);
            }
            // B fragments + mma: 4 ldmatrix.x4 (each covers 2 n8 tiles)
            #pragma unroll
            for (int jp = 0; jp < 4; jp++) {
                const int row = wn * 64 + jp * 16 + brow;
                const int ch  = 2 * g + bchk;
                uint32_t b0, b1, b2, b3;
                ldsm_x4(b0, b1, b2, b3,
                        pB + (uint32_t)(row * 64 + ((ch ^ (row & 7)) << 3)) * 2);
                mma_f16(acc[0][2 * jp],     af[0][0], af[0][1], af[0][2], af[0][3], b0, b1);
                mma_f16(acc[1][2 * jp],     af[1][0], af[1][1], af[1][2], af[1][3], b0, b1);
                mma_f16(acc[0][2 * jp + 1], af[0][0], af[0][1], af[0][2], af[0][3], b2, b3);
                mma_f16(acc[1][2 * jp + 1], af[1][0], af[1][1], af[1][2], af[1][3], b2, b3);
            }
        }
    }

    const int mBase = blockIdx.y * 128 + wm * 32;
    const int nBase = blockIdx.x * 128 + wn * 64;
    #pragma unroll
    for (int mi = 0; mi < 2; mi++) {
        #pragma unroll
        for (int nj = 0; nj < 8; nj++) {
            const int col = nBase + nj * 8 + qc * 2;
            const float bx0 = bias[col], bx1 = bias[col + 1];
            const int r0 = mBase + mi * 16 + qr;
            if (Ch) {
                *(__half2*)(Ch + (size_t)r0 * N + col) =
                    __floats2half2_rn(acc[mi][nj][0] + bx0, acc[mi][nj][1] + bx1);
                *(__half2*)(Ch + (size_t)(r0 + 8) * N + col) =
                    __floats2half2_rn(acc[mi][nj][2] + bx0, acc[mi][nj][3] + bx1);
            } else {
                *(float2*)(Cf + (size_t)r0 * N + col) =
                    make_float2(acc[mi][nj][0] + bx0, acc[mi][nj][1] + bx1);
                *(float2*)(Cf + (size_t)(r0 + 8) * N + col) =
                    make_float2(acc[mi][nj][2] + bx0, acc[mi][nj][3] + bx1);
            }
        }
    }
}

// ---------------------------------------------------------------------------
// Flash attention v8: fp16 mma, FB_M=128, 8 warps x m16, 256 thr, 2 CTA/SM.
// 4-stage coalesced cp.async K/V ring, Q frags in registers, K frags via
// ldmatrix.x4 (16 vs 64 LDS.32 per iter), V via ldmatrix.x4.trans, h2exp2
// softmax with P born as half2 A-frags, conditional o-rescale.
// ---------------------------------------------------------------------------
#define FB_M   128
#define QSZH2  8192
#define KVH    4096
#define FSTG   4
#define FLASH_SMEM ((QSZH2 + 2 * FSTG * KVH) * 2)   // 81920 bytes
#define NT     (SEQ / 64)

__global__ void __launch_bounds__(256, 2) flash_f16()
{
    extern __shared__ __half fsm[];
    const uint32_t sb = smem_u32(fsm);

    const int qt = blockIdx.x, h = blockIdx.y, bz = blockIdx.z;
    const int tid  = threadIdx.x;
    const int lane = tid & 31;
    const int wid  = tid >> 5;
    const int qr   = lane >> 2;
    const int qc   = lane & 3;
    const int rb   = wid * 16;

    const __half* qg = g_qkvh + (size_t)(bz * SEQ + qt * FB_M) * E3 + h * HD;
    const __half* kg = g_qkvh + (size_t)(bz * SEQ) * E3 + EMB     + h * HD;
    const __half* vg = g_qkvh + (size_t)(bz * SEQ) * E3 + 2 * EMB + h * HD;

    // coalesced cp.async: threads 0-127 -> K, 128-255 -> V
    const int isV = tid >> 7;
    const int tt  = tid & 127;
    const int cch = tt & 7;
    const int cr0 = tt >> 3;
    const uint32_t cx = (uint32_t)((cch ^ (cr0 & 7)) << 3);
    const uint32_t sK0 = sb + QSZH2 * 2;
    const uint32_t sV0 = sK0 + FSTG * KVH * 2;
    const __half* kvg   = isV ? vg : kg;
    const uint32_t kvs0 = isV ? sV0 : sK0;

    #pragma unroll
    for (int s = 0; s < FSTG - 1; s++) {
        #pragma unroll
        for (int i = 0; i < 4; i++) {
            const int row = cr0 + 16 * i;
            cp16(kvs0 + ((uint32_t)s * KVH + row * 64 + cx) * 2,
                 kvg + (size_t)(s * 64 + row) * E3 + cch * 8);
        }
        CP_COMMIT();
    }

    // stage Q into swizzled smem (scaled by (1/8)*log2e)
    {
        const float qs = 0.125f * LOG2E;
        const int row = tid >> 1;
        const int hh  = tid & 1;
        const __half* src = qg + (size_t)row * E3 + hh * 32;
        #pragma unroll
        for (int i = 0; i < 4; i++) {
            const int c = hh * 4 + i;
            uint4 raw = *(const uint4*)(src + i * 8);
            const __half2* hp = (const __half2*)&raw;
            __half2 o4[4];
            #pragma unroll
            for (int e = 0; e < 4; e++) {
                float2 f = __half22float2(hp[e]);
                o4[e] = __floats2half2_rn(f.x * qs, f.y * qs);
            }
            *(uint4*)(fsm + row * 64 + ((c ^ (row & 7)) << 3)) = *(uint4*)o4;
        }
    }
    __syncthreads();

    // Q fragments -> registers via ldmatrix.x4 (A-frag geometry)
    uint32_t qf[4][4];
    {
        const int arow = ((lane >> 3) & 1) * 8 + (lane & 7);
        const int achk = lane >> 4;
        const int row  = rb + arow;
        #pragma unroll
        for (int g = 0; g < 4; g++) {
            const int ch = 2 * g + achk;
            ldsm_x4(qf[g][0], qf[g][1], qf[g][2], qf[g][3],
                    sb + (uint32_t)(row * 64 + ((ch ^ (row & 7)) << 3)) * 2);
        }
    }

    float o[8][4];
    float m_i[2], l_i[2];
    #pragma unroll
    for (int j = 0; j < 8; j++)
        #pragma unroll
        for (int c = 0; c < 4; c++) o[j][c] = 0.0f;
    m_i[0] = m_i[1] = -CUDART_INF_F;
    l_i[0] = l_i[1] = 0.0f;

    // K-frag (B, non-trans) lane geometry
    const int brow = ((lane >> 4) & 1) * 8 + (lane & 7);
    const int bchk = (lane >> 3) & 1;
    // V-frag (trans) lane geometry
    const int vrow_l = (lane & 7) + ((lane >> 3) & 1) * 8;
    const int vcb    = (lane >> 4);
    const int vx     = lane & 7;

    for (int t = 0; t < NT; t++) {
        const int buf = t & (FSTG - 1);
        CP_WAIT(2);
        __syncthreads();

        if (t + FSTG - 1 < NT) {
            const int nb = (t + FSTG - 1) & (FSTG - 1);
            #pragma unroll
            for (int i = 0; i < 4; i++) {
                const int row = cr0 + 16 * i;
                cp16(kvs0 + ((uint32_t)nb * KVH + row * 64 + cx) * 2,
                     kvg + (size_t)((t + FSTG - 1) * 64 + row) * E3 + cch * 8);
            }
        }
        CP_COMMIT();

        const uint32_t kst = sK0 + (uint32_t)buf * KVH * 2;
        const uint32_t vst = sV0 + (uint32_t)buf * KVH * 2;

        // ---- S = Q K^T (K frags via ldmatrix.x4) ----
        float s[8][4];
        #pragma unroll
        for (int j = 0; j < 8; j++)
            #pragma unroll
            for (int c = 0; c < 4; c++) s[j][c] = 0.0f;

        #pragma unroll
        for (int g = 0; g < 4; g++) {
            #pragma unroll
            for (int jp = 0; jp < 4; jp++) {
                const int row = jp * 16 + brow;
                const int ch  = 2 * g + bchk;
                uint32_t b0, b1, b2, b3;
                ldsm_x4(b0, b1, b2, b3,
                        kst + (uint32_t)(row * 64 + ((ch ^ (row & 7)) << 3)) * 2);
                mma_f16(s[2 * jp],     qf[g][0], qf[g][1], qf[g][2], qf[g][3], b0, b1);
                mma_f16(s[2 * jp + 1], qf[g][0], qf[g][1], qf[g][2], qf[g][3], b2, b3);
            }
        }

        // ---- online softmax (exp2 domain, fp16 P) ----
        __half2 ph[8][2];
        #pragma unroll
        for (int hf = 0; hf < 2; hf++) {
            float tm = -CUDART_INF_F;
            #pragma unroll
            for (int j = 0; j < 8; j++)
                tm = fmaxf(tm, fmaxf(s[j][hf * 2], s[j][hf * 2 + 1]));
            tm = fmaxf(tm, __shfl_xor_sync(0xffffffffu, tm, 1));
            tm = fmaxf(tm, __shfl_xor_sync(0xffffffffu, tm, 2));
            const float mnew = fmaxf(m_i[hf], tm);
            const bool chg = __any_sync(0xffffffffu, mnew != m_i[hf]);
            float ps = 0.0f;
            #pragma unroll
            for (int j = 0; j < 8; j++) {
                __half2 e = h2exp2(__floats2half2_rn(s[j][hf * 2]     - mnew,
                                                     s[j][hf * 2 + 1] - mnew));
                ph[j][hf] = e;
                const float2 f = __half22float2(e);
                ps += f.x + f.y;
            }
            ps += __shfl_xor_sync(0xffffffffu, ps, 1);
            ps += __shfl_xor_sync(0xffffffffu, ps, 2);
            if (chg) {
                const float alpha = exp2f(m_i[hf] - mnew);
                l_i[hf] = l_i[hf] * alpha + ps;
                m_i[hf] = mnew;
                #pragma unroll
                for (int j = 0; j < 8; j++) {
                    o[j][hf * 2]     *= alpha;
                    o[j][hf * 2 + 1] *= alpha;
                }
            } else {
                l_i[hf] += ps;
            }
        }

        // ---- O += P V ----
        #pragma unroll
        for (int g = 0; g < 4; g++) {
            const uint32_t pa0 = *(const uint32_t*)&ph[2 * g][0];
            const uint32_t pa1 = *(const uint32_t*)&ph[2 * g][1];
            const uint32_t pa2 = *(const uint32_t*)&ph[2 * g + 1][0];
            const uint32_t pa3 = *(const uint32_t*)&ph[2 * g + 1][1];
            #pragma unroll
            for (int jp = 0; jp < 4; jp++) {
                uint32_t b0, b1, b2, b3;
                const uint32_t off =
                    (uint32_t)((g * 16 + vrow_l) * 64 +
                               (((jp * 2 + vcb) ^ vx) << 3)) * 2;
                ldsm_x4_trans(b0, b1, b2, b3, vst + off);
                mma_f16(o[2 * jp],     pa0, pa1, pa2, pa3, b0, b1);
                mma_f16(o[2 * jp + 1], pa0, pa1, pa2, pa3, b2, b3);
            }
        }
    }

    // ---- epilogue ----
    const float inv0 = 1.0f / l_i[0];
    const float inv1 = 1.0f / l_i[1];
    const size_t row0 = (size_t)(bz * SEQ + qt * FB_M + rb + qr);
    #pragma unroll
    for (int j = 0; j < 8; j++) {
        const int col = h * HD + j * 8 + 2 * qc;
        *(__half2*)(g_attnh + row0 * EMB + col) =
            __floats2half2_rn(o[j][0] * inv0, o[j][1] * inv0);
        *(__half2*)(g_attnh + (row0 + 8) * EMB + col) =
            __floats2half2_rn(o[j][2] * inv1, o[j][3] * inv1);
    }
}

// ---------------------------------------------------------------------------
extern "C" void kernel_launch(void* const* d_in, const int* in_sizes, int n_in,
                              void* d_out, int out_size)
{
    (void)in_sizes; (void)n_in; (void)out_size;
    const float* x     = (const float*)d_in[0];
    const float* w_in  = (const float*)d_in[1];
    const float* b_in  = (const float*)d_in[2];
    const float* w_out = (const float*)d_in[3];
    const float* b_out = (const float*)d_in[4];
    float* out = (float*)d_out;

    void *xh_p, *qkv_p, *attn_p, *wti_p, *wto_p;
    cudaGetSymbolAddress(&xh_p,   g_xh);
    cudaGetSymbolAddress(&qkv_p,  g_qkvh);
    cudaGetSymbolAddress(&attn_p, g_attnh);
    cudaGetSymbolAddress(&wti_p,  g_wti);
    cudaGetSymbolAddress(&wto_p,  g_wto);

    cudaFuncSetAttribute(flash_f16, cudaFuncAttributeMaxDynamicSharedMemorySize,
                         FLASH_SMEM);
    cudaFuncSetAttribute(gemm_f16, cudaFuncAttributeMaxDynamicSharedMemorySize,
                         GEMM_SMEM);

    // 0) conversions: x -> fp16, weights -> fp16 transposed [N][K]
    cvt_x_half<<<(MTOT * EMB) / (256 * 8), 256>>>(x, (__half*)xh_p);
    transpose_h<<<dim3(E3 / 32, EMB / 32), dim3(32, 8)>>>(w_in,  (__half*)wti_p, EMB, E3);
    transpose_h<<<dim3(EMB / 32, EMB / 32), dim3(32, 8)>>>(w_out, (__half*)wto_p, EMB, EMB);

    // 1) QKV projection (fp16 mma, fp16 out)
    gemm_f16<<<dim3(E3 / 128, MTOT / 128), 256, GEMM_SMEM>>>(
        E3, EMB, (const __half*)xh_p, (const __half*)wti_p, b_in,
        (__half*)qkv_p, nullptr);

    // 2) Attention (fp16 flash v8)
    flash_f16<<<dim3(SEQ / FB_M, NH, BATCH), 256, FLASH_SMEM>>>();

    // 3) Output projection (fp16 mma, fp32 out)
    gemm_f16<<<dim3(EMB / 128, MTOT / 128), 256, GEMM_SMEM>>>(
        EMB, EMB, (const __half*)attn_p, (const __half*)wto_p, b_out,
        nullptr, out);
}